// round 5
// baseline (speedup 1.0000x reference)
#include <cuda_runtime.h>
#include <cuda_bf16.h>
#include <math.h>
#include <stdint.h>

// Problem constants
#define BB   64
#define TT   366
#define INF  24
#define H1   1024
#define H2   2048
#define HM   2048
#define PEN  1024
#define BT   23424      // BB*TT
#define G3   6144       // 3*HM
#define NBLK 96         // persistent GRU blocks (co-resident on 148 SMs)

// ---------------------------------------------------------------------------
// Scratch (allocation-free: __device__ globals)
// ---------------------------------------------------------------------------
__device__ float g_act1[(size_t)BT * H1];            //  96 MB
__device__ float g_act2[(size_t)BT * H2];            // 192 MB
__device__ float g_xg  [(size_t)BT * G3];            // 576 MB
__device__ float g_hs  [(size_t)(TT + 1) * BB * HM]; // 192 MB (slot 0 = h0 = 0)
__device__ float g_outs[(size_t)BT * PEN];           //  96 MB
__device__ float g_hg  [(size_t)BB * G3];            // 1.5 MB  gate pre-activations
__device__ __nv_bfloat16 g_hhi[(size_t)BB * HM];     // h split hi (bf16)
__device__ __nv_bfloat16 g_hlo[(size_t)BB * HM];     // h split lo (bf16)
__device__ __nv_bfloat16 g_Whi[(size_t)G3 * HM];     // W_hh split hi (25 MB)
__device__ __nv_bfloat16 g_Wlo[(size_t)G3 * HM];     // W_hh split lo (25 MB)
__device__ int      g_labels[BB];
__device__ unsigned g_bar_cnt = 0;
__device__ volatile unsigned g_bar_gen = 0;

// ---------------------------------------------------------------------------
// mma helpers
// ---------------------------------------------------------------------------
__device__ __forceinline__ unsigned f2tf32(float x) {
    unsigned u;
    asm("cvt.rna.tf32.f32 %0, %1;" : "=r"(u) : "f"(x));
    return u;
}

__device__ __forceinline__ void mma_tf32(float* d, const unsigned* a, const unsigned* b) {
    asm volatile(
        "mma.sync.aligned.m16n8k8.row.col.f32.tf32.tf32.f32 "
        "{%0,%1,%2,%3}, {%4,%5,%6,%7}, {%8,%9}, {%0,%1,%2,%3};"
        : "+f"(d[0]), "+f"(d[1]), "+f"(d[2]), "+f"(d[3])
        : "r"(a[0]), "r"(a[1]), "r"(a[2]), "r"(a[3]), "r"(b[0]), "r"(b[1]));
}

__device__ __forceinline__ void mma_bf16(float* d, const unsigned* a, const unsigned* b) {
    asm volatile(
        "mma.sync.aligned.m16n8k16.row.col.f32.bf16.bf16.f32 "
        "{%0,%1,%2,%3}, {%4,%5,%6,%7}, {%8,%9}, {%0,%1,%2,%3};"
        : "+f"(d[0]), "+f"(d[1]), "+f"(d[2]), "+f"(d[3])
        : "r"(a[0]), "r"(a[1]), "r"(a[2]), "r"(a[3]), "r"(b[0]), "r"(b[1]));
}

#define TKP 36   // padded k-stride (32-bit words): bank = 4*row + kword -> conflict-free

// ---------------------------------------------------------------------------
// Software grid barrier (all NBLK blocks co-resident).
// __threadfence (gpu scope) emits CCTL.IVALL -> L1 coherence across SMs.
// ---------------------------------------------------------------------------
__device__ __forceinline__ void gridbar()
{
    __syncthreads();
    if (threadIdx.x == 0) {
        __threadfence();
        unsigned mygen = g_bar_gen;
        if (atomicAdd(&g_bar_cnt, 1u) == NBLK - 1) {
            g_bar_cnt = 0;
            __threadfence();
            g_bar_gen = mygen + 1;
        } else {
            while (g_bar_gen == mygen) { __nanosleep(32); }
        }
        __threadfence();
    }
    __syncthreads();
}

// ---------------------------------------------------------------------------
// Label decode: dtype-robust (int32 vs int64 little-endian).
// ---------------------------------------------------------------------------
__global__ void decode_labels_kernel(const int* __restrict__ raw)
{
    __shared__ int any_odd_nonzero;
    if (threadIdx.x == 0) any_odd_nonzero = 0;
    __syncthreads();
    if (threadIdx.x < 32) {
        if (raw[2 * threadIdx.x + 1] != 0) atomicOr(&any_odd_nonzero, 1);
    }
    __syncthreads();
    const bool is64 = (any_odd_nonzero == 0);
    if (threadIdx.x < BB) {
        g_labels[threadIdx.x] = is64 ? raw[2 * threadIdx.x] : raw[threadIdx.x];
    }
}

// ---------------------------------------------------------------------------
// W_hh split prep: W -> Whi(bf16) + Wlo(bf16)
// ---------------------------------------------------------------------------
__global__ __launch_bounds__(256) void prep_w_kernel(
    const float* __restrict__ W,
    __nv_bfloat16* __restrict__ Whi, __nv_bfloat16* __restrict__ Wlo, int n)
{
    int i = blockIdx.x * 256 + threadIdx.x;
    if (i < n) {
        float w = W[i];
        __nv_bfloat16 hi = __float2bfloat16(w);
        Whi[i] = hi;
        Wlo[i] = __float2bfloat16(w - __bfloat162float(hi));
    }
}

// ---------------------------------------------------------------------------
// Persistent GRU: all 366 steps in one kernel. 96 blocks x 256 threads.
// Per step: block computes HG[64, 64 cols] = (hhi+hlo) @ (Whi+Wlo)^T slice via
// 3-term split-bf16 mma; gridbar; fused gate update (writes hs[t+1], hhi, hlo);
// gridbar.
// ---------------------------------------------------------------------------
__global__ __launch_bounds__(256) void gru_persist(
    const float* __restrict__ xg,
    const __nv_bfloat16* __restrict__ Whi,
    const __nv_bfloat16* __restrict__ Wlo,
    const float* __restrict__ b_hh,
    float* __restrict__ hs,
    __nv_bfloat16* __restrict__ hhi,
    __nv_bfloat16* __restrict__ hlo,
    float* __restrict__ HG)
{
    __shared__ unsigned sAh[64 * TKP];
    __shared__ unsigned sAl[64 * TKP];
    __shared__ unsigned sBh[64 * TKP];
    __shared__ unsigned sBl[64 * TKP];

    const int tid  = threadIdx.x;
    const int bid  = blockIdx.x;
    const int lane = tid & 31;
    const int warp = tid >> 5;
    const int wm   = warp >> 2;   // 0..1 (32 rows)
    const int wn   = warp & 3;    // 0..3 (16 cols)
    const int g    = lane >> 2;
    const int tg   = lane & 3;
    const int n0   = bid * 64;    // this block's G3 column base

    // init h state = 0
    for (int i = bid * 256 + tid; i < BB * HM; i += NBLK * 256) {
        hs[i]  = 0.0f;
        hhi[i] = __float2bfloat16(0.0f);
        hlo[i] = __float2bfloat16(0.0f);
    }
    gridbar();

    for (int t = 0; t < TT; t++) {
        // ---- recurrent GEMM slice ----
        float acc[2][2][4];
#pragma unroll
        for (int i = 0; i < 2; i++)
#pragma unroll
            for (int j = 0; j < 2; j++)
#pragma unroll
                for (int q = 0; q < 4; q++) acc[i][j][q] = 0.0f;

        uint4 pAh[2], pAl[2], pBh[2], pBl[2];

        // prefetch tile 0
        {
            const int kb = 0;
#pragma unroll
            for (int q = 0; q < 2; q++) {
                const int u4  = tid * 2 + q;      // 0..511
                const int row = u4 >> 3;          // 0..63
                const int off = (u4 & 7) * 8;     // bf16 offset
                pAh[q] = *(const uint4*)(hhi + (size_t)row * HM + kb + off);
                pAl[q] = *(const uint4*)(hlo + (size_t)row * HM + kb + off);
                pBh[q] = *(const uint4*)(Whi + (size_t)(n0 + row) * HM + kb + off);
                pBl[q] = *(const uint4*)(Wlo + (size_t)(n0 + row) * HM + kb + off);
            }
        }

        for (int kt = 0; kt < HM / 64; kt++) {
            __syncthreads();
#pragma unroll
            for (int q = 0; q < 2; q++) {
                const int u4   = tid * 2 + q;
                const int row  = u4 >> 3;
                const int woff = (u4 & 7) * 4;
                *(uint4*)&sAh[row * TKP + woff] = pAh[q];
                *(uint4*)&sAl[row * TKP + woff] = pAl[q];
                *(uint4*)&sBh[row * TKP + woff] = pBh[q];
                *(uint4*)&sBl[row * TKP + woff] = pBl[q];
            }
            __syncthreads();

            if (kt + 1 < HM / 64) {
                const int kb = (kt + 1) * 64;
#pragma unroll
                for (int q = 0; q < 2; q++) {
                    const int u4  = tid * 2 + q;
                    const int row = u4 >> 3;
                    const int off = (u4 & 7) * 8;
                    pAh[q] = *(const uint4*)(hhi + (size_t)row * HM + kb + off);
                    pAl[q] = *(const uint4*)(hlo + (size_t)row * HM + kb + off);
                    pBh[q] = *(const uint4*)(Whi + (size_t)(n0 + row) * HM + kb + off);
                    pBl[q] = *(const uint4*)(Wlo + (size_t)(n0 + row) * HM + kb + off);
                }
            }

#pragma unroll
            for (int kc = 0; kc < 4; kc++) {
                unsigned ah[2][4], al[2][4];
#pragma unroll
                for (int i = 0; i < 2; i++) {
                    const int r0 = (wm * 32 + i * 16 + g) * TKP + kc * 8 + tg;
                    const int r1 = r0 + 8 * TKP;
                    ah[i][0] = sAh[r0]; ah[i][1] = sAh[r1];
                    ah[i][2] = sAh[r0 + 4]; ah[i][3] = sAh[r1 + 4];
                    al[i][0] = sAl[r0]; al[i][1] = sAl[r1];
                    al[i][2] = sAl[r0 + 4]; al[i][3] = sAl[r1 + 4];
                }
                unsigned bh[2][2], bl[2][2];
#pragma unroll
                for (int j = 0; j < 2; j++) {
                    const int r = (wn * 16 + j * 8 + g) * TKP + kc * 8 + tg;
                    bh[j][0] = sBh[r]; bh[j][1] = sBh[r + 4];
                    bl[j][0] = sBl[r]; bl[j][1] = sBl[r + 4];
                }
#pragma unroll
                for (int i = 0; i < 2; i++)
#pragma unroll
                    for (int j = 0; j < 2; j++) {
                        mma_bf16(acc[i][j], ah[i], bh[j]);
                        mma_bf16(acc[i][j], ah[i], bl[j]);
                        mma_bf16(acc[i][j], al[i], bh[j]);
                    }
            }
        }

        // epilogue -> HG
#pragma unroll
        for (int i = 0; i < 2; i++) {
            const int row = wm * 32 + i * 16 + g;
#pragma unroll
            for (int j = 0; j < 2; j++) {
                const int col = n0 + wn * 16 + j * 8 + tg * 2;
                HG[(size_t)row * G3 + col]           = acc[i][j][0];
                HG[(size_t)row * G3 + col + 1]       = acc[i][j][1];
                HG[(size_t)(row + 8) * G3 + col]     = acc[i][j][2];
                HG[(size_t)(row + 8) * G3 + col + 1] = acc[i][j][3];
            }
        }
        gridbar();

        // ---- fused gates ----
        {
            const float* hsp = hs + (size_t)t * (BB * HM);
            float*       hsn = hs + (size_t)(t + 1) * (BB * HM);
            for (int idx = bid * 256 + tid; idx < BB * HM; idx += NBLK * 256) {
                const int b = idx >> 11;
                const int u = idx & 2047;
                const float ar = HG[(size_t)b * G3 + u]          + b_hh[u];
                const float az = HG[(size_t)b * G3 + HM + u]     + b_hh[HM + u];
                const float an = HG[(size_t)b * G3 + 2 * HM + u] + b_hh[2 * HM + u];
                const float* xrow = xg + (size_t)(b * TT + t) * G3;
                const float r  = 1.0f / (1.0f + expf(-(xrow[u] + ar)));
                const float z  = 1.0f / (1.0f + expf(-(xrow[HM + u] + az)));
                const float nn = tanhf(xrow[2 * HM + u] + r * an);
                const float hp = hsp[idx];
                const float h  = (1.0f - z) * nn + z * hp;
                hsn[idx] = h;
                const __nv_bfloat16 hb = __float2bfloat16(h);
                hhi[idx] = hb;
                hlo[idx] = __float2bfloat16(h - __bfloat162float(hb));
            }
        }
        gridbar();
    }
}

// ---------------------------------------------------------------------------
// TF32 tensor-core NT GEMM (unchanged from R3): C = act(A @ B^T + bias)
// ---------------------------------------------------------------------------
template<bool RELU>
__global__ __launch_bounds__(256, 2) void gemm_tf32_nt(
    const float* __restrict__ A, const float* __restrict__ Bm,
    const float* __restrict__ bias, float* __restrict__ C,
    int M, int N, int K)
{
    __shared__ unsigned As[128 * TKP];
    __shared__ unsigned Bs[128 * TKP];

    const int tid  = threadIdx.x;
    const int lane = tid & 31;
    const int warp = tid >> 5;
    const int wm   = warp >> 2;
    const int wn   = warp & 3;
    const int g    = lane >> 2;
    const int tg   = lane & 3;

    const int mBase = blockIdx.y * 128;
    const int nBase = blockIdx.x * 128;
    const int lrow  = tid >> 1;
    const int lcol  = (tid & 1) << 2;

    float acc[4][4][4];
#pragma unroll
    for (int i = 0; i < 4; i++)
#pragma unroll
        for (int j = 0; j < 4; j++)
#pragma unroll
            for (int q = 0; q < 4; q++) acc[i][j][q] = 0.0f;

    const float* Ap = A  + (size_t)(mBase + lrow) * K + lcol;
    const float* Bp = Bm + (size_t)(nBase + lrow) * K + lcol;

    for (int k0 = 0; k0 < K; k0 += 32) {
        __syncthreads();
#pragma unroll
        for (int p = 0; p < 4; p++) {
            float4 av = *(const float4*)(Ap + k0 + p * 8);
            float4 bv = *(const float4*)(Bp + k0 + p * 8);
            uint4 at = make_uint4(f2tf32(av.x), f2tf32(av.y), f2tf32(av.z), f2tf32(av.w));
            uint4 bt = make_uint4(f2tf32(bv.x), f2tf32(bv.y), f2tf32(bv.z), f2tf32(bv.w));
            *(uint4*)&As[lrow * TKP + p * 8 + lcol] = at;
            *(uint4*)&Bs[lrow * TKP + p * 8 + lcol] = bt;
        }
        __syncthreads();
#pragma unroll
        for (int kk = 0; kk < 32; kk += 8) {
            unsigned af[4][4], bf[4][2];
#pragma unroll
            for (int f = 0; f < 4; f++) {
                const int r = (wm * 64 + f * 16 + g) * TKP + kk + tg;
                af[f][0] = As[r];
                af[f][1] = As[r + 8 * TKP];
                af[f][2] = As[r + 4];
                af[f][3] = As[r + 8 * TKP + 4];
            }
#pragma unroll
            for (int f = 0; f < 4; f++) {
                const int r = (wn * 32 + f * 8 + g) * TKP + kk + tg;
                bf[f][0] = Bs[r];
                bf[f][1] = Bs[r + 4];
            }
#pragma unroll
            for (int i = 0; i < 4; i++)
#pragma unroll
                for (int j = 0; j < 4; j++)
                    mma_tf32(acc[i][j], af[i], bf[j]);
        }
    }

#pragma unroll
    for (int i = 0; i < 4; i++) {
        const int row = mBase + wm * 64 + i * 16 + g;
#pragma unroll
        for (int j = 0; j < 4; j++) {
            const int col = nBase + wn * 32 + j * 8 + tg * 2;
            const float b0 = bias[col], b1 = bias[col + 1];
            float v00 = acc[i][j][0] + b0, v01 = acc[i][j][1] + b1;
            float v10 = acc[i][j][2] + b0, v11 = acc[i][j][3] + b1;
            if (RELU) {
                v00 = fmaxf(v00, 0.0f); v01 = fmaxf(v01, 0.0f);
                v10 = fmaxf(v10, 0.0f); v11 = fmaxf(v11, 0.0f);
            }
            C[(size_t)row * N + col]           = v00;
            C[(size_t)row * N + col + 1]       = v01;
            C[(size_t)(row + 8) * N + col]     = v10;
            C[(size_t)(row + 8) * N + col + 1] = v11;
        }
    }
}

// ---------------------------------------------------------------------------
// FFMA GEMM (act1 only, K=24)
// ---------------------------------------------------------------------------
__global__ __launch_bounds__(256) void gemm_ffma_nt(
    const float* __restrict__ A, const float* __restrict__ Bm,
    const float* __restrict__ bias, float* __restrict__ C,
    int M, int N, int K)
{
    __shared__ float As[8][128];
    __shared__ float Bs[8][128];

    const int tid  = threadIdx.x;
    const int tx   = tid & 15;
    const int ty   = tid >> 4;
    const int arow = tid >> 1;
    const int acol = (tid & 1) << 2;

    const float* Ap = A  + (size_t)(blockIdx.y * 128 + arow) * K + acol;
    const float* Bp = Bm + (size_t)(blockIdx.x * 128 + arow) * K + acol;

    float acc[8][8];
#pragma unroll
    for (int i = 0; i < 8; i++)
#pragma unroll
        for (int j = 0; j < 8; j++) acc[i][j] = 0.0f;

    for (int k0 = 0; k0 < K; k0 += 8) {
        float4 a = *(const float4*)(Ap + k0);
        float4 b = *(const float4*)(Bp + k0);
        __syncthreads();
        As[acol + 0][arow] = a.x; As[acol + 1][arow] = a.y;
        As[acol + 2][arow] = a.z; As[acol + 3][arow] = a.w;
        Bs[acol + 0][arow] = b.x; Bs[acol + 1][arow] = b.y;
        Bs[acol + 2][arow] = b.z; Bs[acol + 3][arow] = b.w;
        __syncthreads();
#pragma unroll
        for (int k = 0; k < 8; k++) {
            float av[8], bv[8];
            *(float4*)(av)     = *(const float4*)&As[k][ty * 8];
            *(float4*)(av + 4) = *(const float4*)&As[k][ty * 8 + 4];
            *(float4*)(bv)     = *(const float4*)&Bs[k][tx * 8];
            *(float4*)(bv + 4) = *(const float4*)&Bs[k][tx * 8 + 4];
#pragma unroll
            for (int i = 0; i < 8; i++)
#pragma unroll
                for (int j = 0; j < 8; j++)
                    acc[i][j] += av[i] * bv[j];
        }
    }

    const int crow = blockIdx.y * 128 + ty * 8;
    const int ccol = blockIdx.x * 128 + tx * 8;
#pragma unroll
    for (int i = 0; i < 8; i++) {
#pragma unroll
        for (int j = 0; j < 8; j++) {
            float v = acc[i][j] + bias[ccol + j];
            v = fmaxf(v, 0.0f);
            C[(size_t)(crow + i) * N + ccol + j] = v;
        }
    }
}

// ---------------------------------------------------------------------------
// Per-(b,t) heads
// ---------------------------------------------------------------------------
__global__ __launch_bounds__(128) void heads_kernel(
    const float* __restrict__ outs,
    const float* __restrict__ W4, const float* __restrict__ b4,
    const float* __restrict__ W5, const float* __restrict__ b5,
    const float* __restrict__ W6, const float* __restrict__ b6,
    float* __restrict__ out)
{
    const int r  = blockIdx.x;     // t*BB + b
    const int t  = r >> 6;
    const int b  = r & 63;
    const int lab = g_labels[b];
    const float* s  = outs + (size_t)r * PEN;
    const float* w4 = W4 + (size_t)lab * PEN;
    const float* w5 = W5 + (size_t)lab * PEN;
    const float* w6 = W6 + (size_t)lab * PEN;

    float a4 = 0.f, a5 = 0.f, a6 = 0.f;
    for (int p = threadIdx.x; p < PEN; p += 128) {
        const float v = s[p];
        a4 += v * w4[p];
        a5 += v * w5[p];
        a6 += v * w6[p];
    }
    __shared__ float red[3][128];
    red[0][threadIdx.x] = a4;
    red[1][threadIdx.x] = a5;
    red[2][threadIdx.x] = a6;
    __syncthreads();
    for (int s2 = 64; s2 > 0; s2 >>= 1) {
        if (threadIdx.x < s2) {
            red[0][threadIdx.x] += red[0][threadIdx.x + s2];
            red[1][threadIdx.x] += red[1][threadIdx.x + s2];
            red[2][threadIdx.x] += red[2][threadIdx.x + s2];
        }
        __syncthreads();
    }
    if (threadIdx.x == 0) {
        const int o = b * TT + t;
        out[o]          = red[0][0] + b4[lab];
        out[BT + o]     = red[1][0] + b5[lab];
        out[2 * BT + o] = red[2][0] + b6[lab];
    }
}

__global__ void zero_kernel(float* p, int n)
{
    int i = blockIdx.x * blockDim.x + threadIdx.x;
    if (i < n) p[i] = 0.0f;
}

// ---------------------------------------------------------------------------
// Launch
// ---------------------------------------------------------------------------
extern "C" void kernel_launch(void* const* d_in, const int* in_sizes, int n_in,
                              void* d_out, int out_size)
{
    const float* x    = (const float*)d_in[0];
    const int*   labr = (const int*)d_in[1];
    const float* W1   = (const float*)d_in[2];
    const float* b1   = (const float*)d_in[3];
    const float* W2   = (const float*)d_in[4];
    const float* b2   = (const float*)d_in[5];
    const float* W_ih = (const float*)d_in[6];
    const float* W_hh = (const float*)d_in[7];
    const float* b_ih = (const float*)d_in[8];
    const float* b_hh = (const float*)d_in[9];
    const float* W3   = (const float*)d_in[10];
    const float* b3   = (const float*)d_in[11];
    const float* W4   = (const float*)d_in[12];
    const float* b4   = (const float*)d_in[13];
    const float* W5   = (const float*)d_in[14];
    const float* b5   = (const float*)d_in[15];
    const float* W6   = (const float*)d_in[16];
    const float* b6   = (const float*)d_in[17];
    float* out = (float*)d_out;

    float *act1, *act2, *xg, *hs, *outs, *hg;
    __nv_bfloat16 *hhi, *hlo, *whi, *wlo;
    cudaGetSymbolAddress((void**)&act1, g_act1);
    cudaGetSymbolAddress((void**)&act2, g_act2);
    cudaGetSymbolAddress((void**)&xg,   g_xg);
    cudaGetSymbolAddress((void**)&hs,   g_hs);
    cudaGetSymbolAddress((void**)&outs, g_outs);
    cudaGetSymbolAddress((void**)&hg,   g_hg);
    cudaGetSymbolAddress((void**)&hhi,  g_hhi);
    cudaGetSymbolAddress((void**)&hlo,  g_hlo);
    cudaGetSymbolAddress((void**)&whi,  g_Whi);
    cudaGetSymbolAddress((void**)&wlo,  g_Wlo);

    // 1) act1 = relu(x @ W1^T + b1)   [BT, H1], K=24  (FFMA)
    {
        dim3 g(H1 / 128, BT / 128);
        gemm_ffma_nt<<<g, 256>>>(x, W1, b1, act1, BT, H1, INF);
    }
    // 2) act2 = relu(act1 @ W2^T + b2)  [BT, H2]
    {
        dim3 g(H2 / 128, BT / 128);
        gemm_tf32_nt<true><<<g, 256>>>(act1, W2, b2, act2, BT, H2, H1);
    }
    // 3) xg = act2 @ W_ih^T + b_ih    [BT, 6144]
    {
        dim3 g(G3 / 128, BT / 128);
        gemm_tf32_nt<false><<<g, 256>>>(act2, W_ih, b_ih, xg, BT, G3, H2);
    }
    // 4) W_hh split prep
    prep_w_kernel<<<(G3 * HM + 255) / 256, 256>>>(W_hh, whi, wlo, G3 * HM);
    // 5) labels
    decode_labels_kernel<<<1, 64>>>(labr);
    // 6) persistent GRU (ncu -s 5 captures this launch)
    gru_persist<<<NBLK, 256>>>(xg, whi, wlo, b_hh, hs, hhi, hlo, hg);
    // 7) out_s = relu(hs[1..T] @ W3^T + b3)  [BT, PEN]
    {
        dim3 g(PEN / 128, BT / 128);
        gemm_tf32_nt<true><<<g, 256>>>(hs + (size_t)BB * HM, W3, b3, outs, BT, PEN, H2);
    }
    // 8) heads
    heads_kernel<<<BT, 128>>>(outs, W4, b4, W5, b5, W6, b6, out);
    // 9) zero tail of d_out (the two scalar 0 outputs, if present)
    const int tail = out_size - 3 * BT;
    if (tail > 0)
        zero_kernel<<<(tail + 255) / 256, 256>>>(out + 3 * BT, tail);
}

// round 7
// speedup vs baseline: 1.8012x; 1.8012x over previous
#include <cuda_runtime.h>
#include <cuda_bf16.h>
#include <math.h>
#include <stdint.h>

#define BB 64
#define TT 366
#define INF 24
#define H1 1024
#define H2 2048
#define HM 2048
#define PEN 1024
#define BT 23424
#define G3 6144
#define NBLK 96
typedef __nv_bfloat16 bf16;

// ---------------- scratch ---------------------------------------------------
__device__ bf16  g_a1hi[(size_t)BT * H1];
__device__ bf16  g_a1lo[(size_t)BT * H1];
__device__ bf16  g_a2hi[(size_t)BT * H2];
__device__ bf16  g_a2lo[(size_t)BT * H2];
__device__ float g_xg  [(size_t)BT * G3];
__device__ bf16  g_hshi[(size_t)(TT + 1) * BB * HM];
__device__ bf16  g_hslo[(size_t)(TT + 1) * BB * HM];
__device__ float g_outs[(size_t)BT * PEN];
__device__ float g_hg  [(size_t)BB * G3];
__device__ bf16  g_W2hi [(size_t)H2 * H1];
__device__ bf16  g_W2lo [(size_t)H2 * H1];
__device__ bf16  g_Wihhi[(size_t)G3 * H2];
__device__ bf16  g_Wihlo[(size_t)G3 * H2];
__device__ bf16  g_Whhhi[(size_t)G3 * HM];
__device__ bf16  g_Whhlo[(size_t)G3 * HM];
__device__ bf16  g_W3hi [(size_t)PEN * HM];
__device__ bf16  g_W3lo [(size_t)PEN * HM];
__device__ int      g_labels[BB];
__device__ unsigned g_bar_cnt = 0;
__device__ volatile unsigned g_bar_gen = 0;

// ---------------- asm helpers ----------------------------------------------
__device__ __forceinline__ uint32_t su32(const void* p) {
    uint32_t a;
    asm("{ .reg .u64 t; cvta.to.shared.u64 t, %1; cvt.u32.u64 %0, t; }" : "=r"(a) : "l"(p));
    return a;
}
__device__ __forceinline__ void mma16816(float* d, const uint32_t* a, const uint32_t* b) {
    asm volatile(
        "mma.sync.aligned.m16n8k16.row.col.f32.bf16.bf16.f32 "
        "{%0,%1,%2,%3},{%4,%5,%6,%7},{%8,%9},{%0,%1,%2,%3};"
        : "+f"(d[0]), "+f"(d[1]), "+f"(d[2]), "+f"(d[3])
        : "r"(a[0]), "r"(a[1]), "r"(a[2]), "r"(a[3]), "r"(b[0]), "r"(b[1]));
}
__device__ __forceinline__ void ldsm4(uint32_t* r, uint32_t a) {
    asm volatile("ldmatrix.sync.aligned.m8n8.x4.shared.b16 {%0,%1,%2,%3},[%4];"
                 : "=r"(r[0]), "=r"(r[1]), "=r"(r[2]), "=r"(r[3]) : "r"(a));
}
__device__ __forceinline__ void cpa16(uint32_t d, const void* s) {
    asm volatile("cp.async.cg.shared.global [%0],[%1],16;" :: "r"(d), "l"(s));
}
__device__ __forceinline__ void cp_commit() { asm volatile("cp.async.commit_group;"); }
__device__ __forceinline__ void cp_wait1()  { asm volatile("cp.async.wait_group 1;"); }
__device__ __forceinline__ void cp_wait0()  { asm volatile("cp.async.wait_group 0;"); }

__device__ __forceinline__ void split1(float v, unsigned short& h, unsigned short& l) {
    bf16 hb = __float2bfloat16(v);
    h = *reinterpret_cast<unsigned short*>(&hb);
    bf16 lb = __float2bfloat16(v - __bfloat162float(hb));
    l = *reinterpret_cast<unsigned short*>(&lb);
}
__device__ __forceinline__ void split8(const float* s, bf16* hi, bf16* lo) {
    float4 a = *(const float4*)s, b = *(const float4*)(s + 4);
    float v[8] = {a.x, a.y, a.z, a.w, b.x, b.y, b.z, b.w};
    __align__(16) unsigned short h[8], l[8];
#pragma unroll
    for (int i = 0; i < 8; i++) split1(v[i], h[i], l[i]);
    *(uint4*)hi = *(const uint4*)h;
    *(uint4*)lo = *(const uint4*)l;
}

__device__ __forceinline__ void gridbar()
{
    __syncthreads();
    if (threadIdx.x == 0) {
        __threadfence();
        unsigned g = g_bar_gen;
        if (atomicAdd(&g_bar_cnt, 1u) == NBLK - 1) {
            g_bar_cnt = 0;
            __threadfence();
            g_bar_gen = g + 1;
        } else {
            while (g_bar_gen == g) { __nanosleep(32); }
        }
        __threadfence();
    }
    __syncthreads();
}

// ---------------- split all weights -----------------------------------------
__global__ __launch_bounds__(256) void split_all(
    const float* __restrict__ W2, const float* __restrict__ Wih,
    const float* __restrict__ Whh, const float* __restrict__ W3r)
{
    const size_t n1 = (size_t)H2 * H1 / 8, n2 = (size_t)G3 * H2 / 8;
    const size_t n3 = (size_t)G3 * HM / 8, n4 = (size_t)PEN * HM / 8;
    size_t c = (size_t)blockIdx.x * 256 + threadIdx.x;
    if (c < n1) split8(W2 + c * 8, g_W2hi + c * 8, g_W2lo + c * 8);
    else if (c < n1 + n2) { size_t j = c - n1; split8(Wih + j * 8, g_Wihhi + j * 8, g_Wihlo + j * 8); }
    else if (c < n1 + n2 + n3) { size_t j = c - n1 - n2; split8(Whh + j * 8, g_Whhhi + j * 8, g_Whhlo + j * 8); }
    else if (c < n1 + n2 + n3 + n4) { size_t j = c - n1 - n2 - n3; split8(W3r + j * 8, g_W3hi + j * 8, g_W3lo + j * 8); }
}

// ---------------- act1 FFMA (K=24) -> bf16 hi/lo ----------------------------
__global__ __launch_bounds__(256) void gemm_ffma_split(
    const float* __restrict__ A, const float* __restrict__ Bm,
    const float* __restrict__ bias)
{
    __shared__ float As[8][128], Bs[8][128];
    const int tid = threadIdx.x, tx = tid & 15, ty = tid >> 4;
    const int arow = tid >> 1, acol = (tid & 1) << 2;
    const float* Ap = A  + (size_t)(blockIdx.y * 128 + arow) * INF + acol;
    const float* Bp = Bm + (size_t)(blockIdx.x * 128 + arow) * INF + acol;
    float acc[8][8];
#pragma unroll
    for (int i = 0; i < 8; i++)
#pragma unroll
        for (int j = 0; j < 8; j++) acc[i][j] = 0.0f;
    for (int k0 = 0; k0 < INF; k0 += 8) {
        float4 a = *(const float4*)(Ap + k0);
        float4 b = *(const float4*)(Bp + k0);
        __syncthreads();
        As[acol][arow] = a.x; As[acol + 1][arow] = a.y; As[acol + 2][arow] = a.z; As[acol + 3][arow] = a.w;
        Bs[acol][arow] = b.x; Bs[acol + 1][arow] = b.y; Bs[acol + 2][arow] = b.z; Bs[acol + 3][arow] = b.w;
        __syncthreads();
#pragma unroll
        for (int k = 0; k < 8; k++) {
            float av[8], bv[8];
            *(float4*)av       = *(const float4*)&As[k][ty * 8];
            *(float4*)(av + 4) = *(const float4*)&As[k][ty * 8 + 4];
            *(float4*)bv       = *(const float4*)&Bs[k][tx * 8];
            *(float4*)(bv + 4) = *(const float4*)&Bs[k][tx * 8 + 4];
#pragma unroll
            for (int i = 0; i < 8; i++)
#pragma unroll
                for (int j = 0; j < 8; j++) acc[i][j] += av[i] * bv[j];
        }
    }
    const int crow = blockIdx.y * 128 + ty * 8, ccol = blockIdx.x * 128 + tx * 8;
#pragma unroll
    for (int i = 0; i < 8; i++) {
        __align__(16) unsigned short h8[8], l8[8];
#pragma unroll
        for (int j = 0; j < 8; j++)
            split1(fmaxf(acc[i][j] + bias[ccol + j], 0.0f), h8[j], l8[j]);
        *(uint4*)(g_a1hi + (size_t)(crow + i) * H1 + ccol) = *(const uint4*)h8;
        *(uint4*)(g_a1lo + (size_t)(crow + i) * H1 + ccol) = *(const uint4*)l8;
    }
}

// ---------------- bf16-split NT GEMM (128x128, K-tile 64, cp.async+ldsm) ----
// smem stage: Ah@0 Al@18432 Bh@36864 Bl@55296 ; rows 144B (conflict-free)
#define RB   144
#define ASZ  18432
#define STG  73728
template<int OUTM, int RELU>
__global__ __launch_bounds__(256) void gemm_tc(
    const bf16* __restrict__ Ahi, const bf16* __restrict__ Alo,
    const bf16* __restrict__ Bhi, const bf16* __restrict__ Blo,
    const float* __restrict__ bias,
    float* __restrict__ Cf, bf16* __restrict__ Chi, bf16* __restrict__ Clo,
    int N, int K)
{
    extern __shared__ char smraw[];
    const uint32_t sb = su32(smraw);
    const int tid = threadIdx.x, warp = tid >> 5, lane = tid & 31;
    const int wm = warp >> 2, wn = warp & 3, g = lane >> 2, tg = lane & 3;
    const int mBase = blockIdx.y * 128, nBase = blockIdx.x * 128;
    const int NTI = K / 64;
    const int arow = (lane & 7) + ((lane >> 3) & 1) * 8, ach = lane >> 4;
    const int brow = (lane & 7) + ((lane >> 4) & 1) * 8, bch = (lane >> 3) & 1;

    float acc[4][4][4];
#pragma unroll
    for (int i = 0; i < 4; i++)
#pragma unroll
        for (int j = 0; j < 4; j++)
#pragma unroll
            for (int q = 0; q < 4; q++) acc[i][j][q] = 0.0f;

    auto load_stage = [&](int st, int k0) {
        uint32_t d0 = sb + st * STG;
#pragma unroll
        for (int q = 0; q < 4; q++) {
            int c = q * 256 + tid, row = c >> 3, ch = c & 7;
            size_t ka = (size_t)(mBase + row) * K + k0 + ch * 8;
            size_t kb = (size_t)(nBase + row) * K + k0 + ch * 8;
            uint32_t o = row * RB + ch * 16;
            cpa16(d0 + o,             Ahi + ka);
            cpa16(d0 + ASZ + o,       Alo + ka);
            cpa16(d0 + 2 * ASZ + o,   Bhi + kb);
            cpa16(d0 + 3 * ASZ + o,   Blo + kb);
        }
        cp_commit();
    };

    load_stage(0, 0);
    for (int kt = 0; kt < NTI; kt++) {
        if (kt + 1 < NTI) { load_stage((kt + 1) & 1, (kt + 1) * 64); cp_wait1(); }
        else cp_wait0();
        __syncthreads();
        const uint32_t s0 = sb + (kt & 1) * STG;
#pragma unroll
        for (int kk = 0; kk < 4; kk++) {
            uint32_t ah[4][4], al[4][4];
#pragma unroll
            for (int i = 0; i < 4; i++) {
                uint32_t ad = s0 + (wm * 64 + i * 16 + arow) * RB + (kk * 2 + ach) * 16;
                ldsm4(ah[i], ad);
                ldsm4(al[i], ad + ASZ);
            }
#pragma unroll
            for (int j = 0; j < 2; j++) {
                uint32_t bh[4], bl[4];
                uint32_t bd = s0 + 2 * ASZ + (wn * 32 + j * 16 + brow) * RB + (kk * 2 + bch) * 16;
                ldsm4(bh, bd);
                ldsm4(bl, bd + ASZ);
#pragma unroll
                for (int i = 0; i < 4; i++) {
                    mma16816(acc[i][2 * j],     ah[i], bh);
                    mma16816(acc[i][2 * j],     ah[i], bl);
                    mma16816(acc[i][2 * j],     al[i], bh);
                    mma16816(acc[i][2 * j + 1], ah[i], bh + 2);
                    mma16816(acc[i][2 * j + 1], ah[i], bl + 2);
                    mma16816(acc[i][2 * j + 1], al[i], bh + 2);
                }
            }
        }
        __syncthreads();
    }

#pragma unroll
    for (int i = 0; i < 4; i++) {
        const int row = mBase + wm * 64 + i * 16 + g;
#pragma unroll
        for (int j = 0; j < 4; j++) {
            const int col = nBase + wn * 32 + j * 8 + 2 * tg;
            const float b0 = bias[col], b1 = bias[col + 1];
            float v00 = acc[i][j][0] + b0, v01 = acc[i][j][1] + b1;
            float v10 = acc[i][j][2] + b0, v11 = acc[i][j][3] + b1;
            if (RELU) { v00 = fmaxf(v00, 0.f); v01 = fmaxf(v01, 0.f);
                        v10 = fmaxf(v10, 0.f); v11 = fmaxf(v11, 0.f); }
            if (OUTM == 0) {
                *(float2*)(Cf + (size_t)row * N + col)       = make_float2(v00, v01);
                *(float2*)(Cf + (size_t)(row + 8) * N + col) = make_float2(v10, v11);
            } else {
                unsigned short h0, l0, h1, l1;
                split1(v00, h0, l0); split1(v01, h1, l1);
                *(uint32_t*)(Chi + (size_t)row * N + col) = (uint32_t)h0 | ((uint32_t)h1 << 16);
                *(uint32_t*)(Clo + (size_t)row * N + col) = (uint32_t)l0 | ((uint32_t)l1 << 16);
                split1(v10, h0, l0); split1(v11, h1, l1);
                *(uint32_t*)(Chi + (size_t)(row + 8) * N + col) = (uint32_t)h0 | ((uint32_t)h1 << 16);
                *(uint32_t*)(Clo + (size_t)(row + 8) * N + col) = (uint32_t)l0 | ((uint32_t)l1 << 16);
            }
        }
    }
}

// ---------------- persistent GRU (M64 x N64/block, K-tile 64) ---------------
// smem stage: Ah@0 Al@9216 Bh@18432 Bl@27648 ; stage=36864
#define GASZ 9216
#define GSTG 36864
__global__ __launch_bounds__(128) void gru_persist(
    const float* __restrict__ b_hh, const int* __restrict__ labraw)
{
    extern __shared__ char smraw[];
    const uint32_t sb = su32(smraw);
    const int tid = threadIdx.x, bid = blockIdx.x, warp = tid >> 5, lane = tid & 31;
    const int wm = warp >> 1, wn = warp & 1, g = lane >> 2, tg = lane & 3;
    const int n0 = bid * 64;
    const int arow = (lane & 7) + ((lane >> 3) & 1) * 8, ach = lane >> 4;
    const int brow = (lane & 7) + ((lane >> 4) & 1) * 8, bch = (lane >> 3) & 1;
    const int gsz = NBLK * 128, gtid = bid * 128 + tid;

    // init: h0 = 0, labels
    for (int i = gtid; i < BB * HM; i += gsz) {
        g_hshi[i] = __float2bfloat16(0.0f);
        g_hslo[i] = __float2bfloat16(0.0f);
    }
    if (bid == 0 && warp == 0) {
        unsigned oddmask = __ballot_sync(0xffffffff, labraw[2 * lane + 1] != 0);
        if (oddmask == 0) { g_labels[lane] = labraw[2 * lane]; g_labels[lane + 32] = labraw[2 * (lane + 32)]; }
        else              { g_labels[lane] = labraw[lane];     g_labels[lane + 32] = labraw[lane + 32]; }
    }
    gridbar();

    for (int t = 0; t < TT; t++) {
        const bf16* Ah_t = g_hshi + (size_t)t * BB * HM;
        const bf16* Al_t = g_hslo + (size_t)t * BB * HM;

        float acc[2][4][4];
#pragma unroll
        for (int i = 0; i < 2; i++)
#pragma unroll
            for (int j = 0; j < 4; j++)
#pragma unroll
                for (int q = 0; q < 4; q++) acc[i][j][q] = 0.0f;

        auto load_stage = [&](int st, int k0) {
            uint32_t d0 = sb + st * GSTG;
#pragma unroll
            for (int q = 0; q < 4; q++) {
                int c = q * 128 + tid, row = c >> 3, ch = c & 7;
                size_t ka = (size_t)row * HM + k0 + ch * 8;
                size_t kb = (size_t)(n0 + row) * HM + k0 + ch * 8;
                uint32_t o = row * RB + ch * 16;
                cpa16(d0 + o,            Ah_t + ka);
                cpa16(d0 + GASZ + o,     Al_t + ka);
                cpa16(d0 + 2 * GASZ + o, g_Whhhi + kb);
                cpa16(d0 + 3 * GASZ + o, g_Whhlo + kb);
            }
            cp_commit();
        };

        load_stage(0, 0);
        for (int kt = 0; kt < HM / 64; kt++) {
            if (kt + 1 < HM / 64) { load_stage((kt + 1) & 1, (kt + 1) * 64); cp_wait1(); }
            else cp_wait0();
            __syncthreads();
            const uint32_t s0 = sb + (kt & 1) * GSTG;
#pragma unroll
            for (int kk = 0; kk < 4; kk++) {
                uint32_t ah[2][4], al[2][4];
#pragma unroll
                for (int i = 0; i < 2; i++) {
                    uint32_t ad = s0 + (wm * 32 + i * 16 + arow) * RB + (kk * 2 + ach) * 16;
                    ldsm4(ah[i], ad);
                    ldsm4(al[i], ad + GASZ);
                }
#pragma unroll
                for (int j = 0; j < 2; j++) {
                    uint32_t bh[4], bl[4];
                    uint32_t bd = s0 + 2 * GASZ + (wn * 32 + j * 16 + brow) * RB + (kk * 2 + bch) * 16;
                    ldsm4(bh, bd);
                    ldsm4(bl, bd + GASZ);
#pragma unroll
                    for (int i = 0; i < 2; i++) {
                        mma16816(acc[i][2 * j],     ah[i], bh);
                        mma16816(acc[i][2 * j],     ah[i], bl);
                        mma16816(acc[i][2 * j],     al[i], bh);
                        mma16816(acc[i][2 * j + 1], ah[i], bh + 2);
                        mma16816(acc[i][2 * j + 1], ah[i], bl + 2);
                        mma16816(acc[i][2 * j + 1], al[i], bh + 2);
                    }
                }
            }
            __syncthreads();
        }

        // epilogue -> g_hg
#pragma unroll
        for (int i = 0; i < 2; i++) {
            const int row = wm * 32 + i * 16 + g;
#pragma unroll
            for (int j = 0; j < 4; j++) {
                const int col = n0 + wn * 32 + j * 8 + 2 * tg;
                *(float2*)(g_hg + (size_t)row * G3 + col)       = make_float2(acc[i][j][0], acc[i][j][1]);
                *(float2*)(g_hg + (size_t)(row + 8) * G3 + col) = make_float2(acc[i][j][2], acc[i][j][3]);
            }
        }
        gridbar();

        // fused gates
        {
            bf16* hhn = g_hshi + (size_t)(t + 1) * BB * HM;
            bf16* hln = g_hslo + (size_t)(t + 1) * BB * HM;
            for (int idx = gtid; idx < BB * HM; idx += gsz) {
                const int b = idx >> 11, u = idx & 2047;
                const float ar = g_hg[(size_t)b * G3 + u]          + b_hh[u];
                const float az = g_hg[(size_t)b * G3 + HM + u]     + b_hh[HM + u];
                const float an = g_hg[(size_t)b * G3 + 2 * HM + u] + b_hh[2 * HM + u];
                const float* xrow = g_xg + (size_t)(b * TT + t) * G3;
                const float r  = 1.0f / (1.0f + expf(-(xrow[u] + ar)));
                const float z  = 1.0f / (1.0f + expf(-(xrow[HM + u] + az)));
                const float nn = tanhf(xrow[2 * HM + u] + r * an);
                const float hp = __bfloat162float(Ah_t[idx]) + __bfloat162float(Al_t[idx]);
                const float h  = (1.0f - z) * nn + z * hp;
                unsigned short hh, hl;
                split1(h, hh, hl);
                hhn[idx] = *reinterpret_cast<bf16*>(&hh);
                hln[idx] = *reinterpret_cast<bf16*>(&hl);
            }
        }
        gridbar();
    }
}

// ---------------- heads + zero ----------------------------------------------
__global__ __launch_bounds__(128) void heads_kernel(
    const float* __restrict__ W4, const float* __restrict__ b4,
    const float* __restrict__ W5, const float* __restrict__ b5,
    const float* __restrict__ W6, const float* __restrict__ b6,
    float* __restrict__ out)
{
    const int r = blockIdx.x, t = r >> 6, b = r & 63;
    const int lab = g_labels[b];
    const float* s  = g_outs + (size_t)r * PEN;
    const float* w4 = W4 + (size_t)lab * PEN;
    const float* w5 = W5 + (size_t)lab * PEN;
    const float* w6 = W6 + (size_t)lab * PEN;
    float a4 = 0.f, a5 = 0.f, a6 = 0.f;
    for (int p = threadIdx.x; p < PEN; p += 128) {
        const float v = s[p];
        a4 += v * w4[p]; a5 += v * w5[p]; a6 += v * w6[p];
    }
    __shared__ float red[3][128];
    red[0][threadIdx.x] = a4; red[1][threadIdx.x] = a5; red[2][threadIdx.x] = a6;
    __syncthreads();
    for (int s2 = 64; s2 > 0; s2 >>= 1) {
        if (threadIdx.x < s2) {
            red[0][threadIdx.x] += red[0][threadIdx.x + s2];
            red[1][threadIdx.x] += red[1][threadIdx.x + s2];
            red[2][threadIdx.x] += red[2][threadIdx.x + s2];
        }
        __syncthreads();
    }
    if (threadIdx.x == 0) {
        const int o = b * TT + t;
        out[o]          = red[0][0] + b4[lab];
        out[BT + o]     = red[1][0] + b5[lab];
        out[2 * BT + o] = red[2][0] + b6[lab];
    }
}

__global__ void zero_kernel(float* p, int n)
{
    int i = blockIdx.x * blockDim.x + threadIdx.x;
    if (i < n) p[i] = 0.0f;
}

// ---------------- launch ----------------------------------------------------
extern "C" void kernel_launch(void* const* d_in, const int* in_sizes, int n_in,
                              void* d_out, int out_size)
{
    const float* x    = (const float*)d_in[0];
    const int*   labr = (const int*)d_in[1];
    const float* W1   = (const float*)d_in[2];
    const float* b1   = (const float*)d_in[3];
    const float* W2   = (const float*)d_in[4];
    const float* b2   = (const float*)d_in[5];
    const float* W_ih = (const float*)d_in[6];
    const float* W_hh = (const float*)d_in[7];
    const float* b_ih = (const float*)d_in[8];
    const float* b_hh = (const float*)d_in[9];
    const float* W3   = (const float*)d_in[10];
    const float* b3   = (const float*)d_in[11];
    const float* W4   = (const float*)d_in[12];
    const float* b4   = (const float*)d_in[13];
    const float* W5   = (const float*)d_in[14];
    const float* b5   = (const float*)d_in[15];
    const float* W6   = (const float*)d_in[16];
    const float* b6   = (const float*)d_in[17];
    float* out = (float*)d_out;

    bf16 *a1hi, *a1lo, *a2hi, *a2lo, *hshi, *hslo, *w2hi, *w2lo, *wihhi, *wihlo, *w3hi, *w3lo;
    float *xg, *outs;
    cudaGetSymbolAddress((void**)&a1hi, g_a1hi);
    cudaGetSymbolAddress((void**)&a1lo, g_a1lo);
    cudaGetSymbolAddress((void**)&a2hi, g_a2hi);
    cudaGetSymbolAddress((void**)&a2lo, g_a2lo);
    cudaGetSymbolAddress((void**)&hshi, g_hshi);
    cudaGetSymbolAddress((void**)&hslo, g_hslo);
    cudaGetSymbolAddress((void**)&w2hi, g_W2hi);
    cudaGetSymbolAddress((void**)&w2lo, g_W2lo);
    cudaGetSymbolAddress((void**)&wihhi, g_Wihhi);
    cudaGetSymbolAddress((void**)&wihlo, g_Wihlo);
    cudaGetSymbolAddress((void**)&w3hi, g_W3hi);
    cudaGetSymbolAddress((void**)&w3lo, g_W3lo);
    cudaGetSymbolAddress((void**)&xg, g_xg);
    cudaGetSymbolAddress((void**)&outs, g_outs);

    const int GEMM_SMEM = 2 * STG;    // 147456
    const int GRU_SMEM  = 2 * GSTG;   //  73728
    cudaFuncSetAttribute(gemm_tc<0, 0>, cudaFuncAttributeMaxDynamicSharedMemorySize, GEMM_SMEM);
    cudaFuncSetAttribute(gemm_tc<0, 1>, cudaFuncAttributeMaxDynamicSharedMemorySize, GEMM_SMEM);
    cudaFuncSetAttribute(gemm_tc<1, 1>, cudaFuncAttributeMaxDynamicSharedMemorySize, GEMM_SMEM);
    cudaFuncSetAttribute(gru_persist, cudaFuncAttributeMaxDynamicSharedMemorySize, GRU_SMEM);

    // 0) zero output tail
    const int tail = out_size - 3 * BT;
    zero_kernel<<<(((tail > 0 ? tail : 1) + 255) / 256), 256>>>(out + 3 * BT, tail > 0 ? tail : 0);
    // 1) act1
    {
        dim3 g(H1 / 128, BT / 128);
        gemm_ffma_split<<<g, 256>>>(x, W1, b1);
    }
    // 2) split all weights
    {
        size_t chunks = (size_t)H2 * H1 / 8 + (size_t)G3 * H2 / 8 + (size_t)G3 * HM / 8 + (size_t)PEN * HM / 8;
        split_all<<<(unsigned)((chunks + 255) / 256), 256>>>(W2, W_ih, W_hh, W3);
    }
    // 3) act2 -> bf16 hi/lo
    {
        dim3 g(H2 / 128, BT / 128);
        gemm_tc<1, 1><<<g, 256, GEMM_SMEM>>>(a1hi, a1lo, w2hi, w2lo, b2,
                                             nullptr, a2hi, a2lo, H2, H1);
    }
    // 4) xg -> f32
    {
        dim3 g(G3 / 128, BT / 128);
        gemm_tc<0, 0><<<g, 256, GEMM_SMEM>>>(a2hi, a2lo, wihhi, wihlo, b_ih,
                                             xg, nullptr, nullptr, G3, H2);
    }
    // 5) persistent GRU (profiled)
    gru_persist<<<NBLK, 128, GRU_SMEM>>>(b_hh, labr);
    // 6) out_s = relu(h @ W3^T + b3)
    {
        dim3 g(PEN / 128, BT / 128);
        gemm_tc<0, 1><<<g, 256, GEMM_SMEM>>>(hshi + (size_t)BB * HM, hslo + (size_t)BB * HM,
                                             w3hi, w3lo, b3, outs, nullptr, nullptr, PEN, HM);
    }
    // 7) heads
    heads_kernel<<<BT, 128>>>(W4, b4, W5, b5, W6, b6, out);
}

// round 8
// speedup vs baseline: 1.9470x; 1.0809x over previous
#include <cuda_runtime.h>
#include <cuda_bf16.h>
#include <math.h>
#include <stdint.h>

#define BB 64
#define TT 366
#define INF 24
#define H1 1024
#define H2 2048
#define HM 2048
#define PEN 1024
#define BT 23424
#define G3 6144
#define NBLK 96
typedef __nv_bfloat16 bf16;

// ---------------- scratch ---------------------------------------------------
__device__ bf16  g_a1hi[(size_t)BT * H1];
__device__ bf16  g_a1lo[(size_t)BT * H1];
__device__ bf16  g_a2hi[(size_t)BT * H2];
__device__ bf16  g_a2lo[(size_t)BT * H2];
__device__ float g_xg  [(size_t)BT * G3];
__device__ bf16  g_hshi[(size_t)(TT + 1) * BB * HM];
__device__ bf16  g_hslo[(size_t)(TT + 1) * BB * HM];
__device__ float g_outs[(size_t)BT * PEN];
__device__ float g_hg  [(size_t)BB * G3];
__device__ bf16  g_W2hi [(size_t)H2 * H1];
__device__ bf16  g_W2lo [(size_t)H2 * H1];
__device__ bf16  g_Wihhi[(size_t)G3 * H2];
__device__ bf16  g_Wihlo[(size_t)G3 * H2];
__device__ bf16  g_Whhhi[(size_t)G3 * HM];
__device__ bf16  g_Whhlo[(size_t)G3 * HM];
__device__ bf16  g_W3hi [(size_t)PEN * HM];
__device__ bf16  g_W3lo [(size_t)PEN * HM];
__device__ int      g_labels[BB];
__device__ unsigned g_bar_cnt = 0;
__device__ volatile unsigned g_bar_gen = 0;

// ---------------- asm helpers ----------------------------------------------
__device__ __forceinline__ uint32_t su32(const void* p) {
    uint32_t a;
    asm("{ .reg .u64 t; cvta.to.shared.u64 t, %1; cvt.u32.u64 %0, t; }" : "=r"(a) : "l"(p));
    return a;
}
__device__ __forceinline__ void mma16816(float* d, const uint32_t* a, const uint32_t* b) {
    asm volatile(
        "mma.sync.aligned.m16n8k16.row.col.f32.bf16.bf16.f32 "
        "{%0,%1,%2,%3},{%4,%5,%6,%7},{%8,%9},{%0,%1,%2,%3};"
        : "+f"(d[0]), "+f"(d[1]), "+f"(d[2]), "+f"(d[3])
        : "r"(a[0]), "r"(a[1]), "r"(a[2]), "r"(a[3]), "r"(b[0]), "r"(b[1]));
}
__device__ __forceinline__ void ldsm4(uint32_t* r, uint32_t a) {
    asm volatile("ldmatrix.sync.aligned.m8n8.x4.shared.b16 {%0,%1,%2,%3},[%4];"
                 : "=r"(r[0]), "=r"(r[1]), "=r"(r[2]), "=r"(r[3]) : "r"(a));
}
__device__ __forceinline__ void cpa16(uint32_t d, const void* s) {
    asm volatile("cp.async.cg.shared.global [%0],[%1],16;" :: "r"(d), "l"(s));
}
__device__ __forceinline__ void cp_commit() { asm volatile("cp.async.commit_group;"); }
__device__ __forceinline__ void cp_wait1()  { asm volatile("cp.async.wait_group 1;"); }
__device__ __forceinline__ void cp_wait0()  { asm volatile("cp.async.wait_group 0;"); }

__device__ __forceinline__ void split1(float v, unsigned short& h, unsigned short& l) {
    bf16 hb = __float2bfloat16(v);
    h = *reinterpret_cast<unsigned short*>(&hb);
    bf16 lb = __float2bfloat16(v - __bfloat162float(hb));
    l = *reinterpret_cast<unsigned short*>(&lb);
}
__device__ __forceinline__ void split8(const float* s, bf16* hi, bf16* lo) {
    float4 a = *(const float4*)s, b = *(const float4*)(s + 4);
    float v[8] = {a.x, a.y, a.z, a.w, b.x, b.y, b.z, b.w};
    __align__(16) unsigned short h[8], l[8];
#pragma unroll
    for (int i = 0; i < 8; i++) split1(v[i], h[i], l[i]);
    *(uint4*)hi = *(const uint4*)h;
    *(uint4*)lo = *(const uint4*)l;
}

__device__ __forceinline__ void gridbar()
{
    __syncthreads();
    if (threadIdx.x == 0) {
        __threadfence();
        unsigned g = g_bar_gen;
        if (atomicAdd(&g_bar_cnt, 1u) == NBLK - 1) {
            g_bar_cnt = 0;
            __threadfence();
            g_bar_gen = g + 1;
        } else {
            while (g_bar_gen == g) { __nanosleep(32); }
        }
        __threadfence();
    }
    __syncthreads();
}

// ---------------- split all weights -----------------------------------------
__global__ __launch_bounds__(256) void split_all(
    const float* __restrict__ W2, const float* __restrict__ Wih,
    const float* __restrict__ Whh, const float* __restrict__ W3r)
{
    const size_t n1 = (size_t)H2 * H1 / 8, n2 = (size_t)G3 * H2 / 8;
    const size_t n3 = (size_t)G3 * HM / 8, n4 = (size_t)PEN * HM / 8;
    size_t c = (size_t)blockIdx.x * 256 + threadIdx.x;
    if (c < n1) split8(W2 + c * 8, g_W2hi + c * 8, g_W2lo + c * 8);
    else if (c < n1 + n2) { size_t j = c - n1; split8(Wih + j * 8, g_Wihhi + j * 8, g_Wihlo + j * 8); }
    else if (c < n1 + n2 + n3) { size_t j = c - n1 - n2; split8(Whh + j * 8, g_Whhhi + j * 8, g_Whhlo + j * 8); }
    else if (c < n1 + n2 + n3 + n4) { size_t j = c - n1 - n2 - n3; split8(W3r + j * 8, g_W3hi + j * 8, g_W3lo + j * 8); }
}

// ---------------- act1 FFMA (K=24) -> bf16 hi/lo ----------------------------
__global__ __launch_bounds__(256) void gemm_ffma_split(
    const float* __restrict__ A, const float* __restrict__ Bm,
    const float* __restrict__ bias)
{
    __shared__ float As[8][128], Bs[8][128];
    const int tid = threadIdx.x, tx = tid & 15, ty = tid >> 4;
    const int arow = tid >> 1, acol = (tid & 1) << 2;
    const float* Ap = A  + (size_t)(blockIdx.y * 128 + arow) * INF + acol;
    const float* Bp = Bm + (size_t)(blockIdx.x * 128 + arow) * INF + acol;
    float acc[8][8];
#pragma unroll
    for (int i = 0; i < 8; i++)
#pragma unroll
        for (int j = 0; j < 8; j++) acc[i][j] = 0.0f;
    for (int k0 = 0; k0 < INF; k0 += 8) {
        float4 a = *(const float4*)(Ap + k0);
        float4 b = *(const float4*)(Bp + k0);
        __syncthreads();
        As[acol][arow] = a.x; As[acol + 1][arow] = a.y; As[acol + 2][arow] = a.z; As[acol + 3][arow] = a.w;
        Bs[acol][arow] = b.x; Bs[acol + 1][arow] = b.y; Bs[acol + 2][arow] = b.z; Bs[acol + 3][arow] = b.w;
        __syncthreads();
#pragma unroll
        for (int k = 0; k < 8; k++) {
            float av[8], bv[8];
            *(float4*)av       = *(const float4*)&As[k][ty * 8];
            *(float4*)(av + 4) = *(const float4*)&As[k][ty * 8 + 4];
            *(float4*)bv       = *(const float4*)&Bs[k][tx * 8];
            *(float4*)(bv + 4) = *(const float4*)&Bs[k][tx * 8 + 4];
#pragma unroll
            for (int i = 0; i < 8; i++)
#pragma unroll
                for (int j = 0; j < 8; j++) acc[i][j] += av[i] * bv[j];
        }
    }
    const int crow = blockIdx.y * 128 + ty * 8, ccol = blockIdx.x * 128 + tx * 8;
#pragma unroll
    for (int i = 0; i < 8; i++) {
        __align__(16) unsigned short h8[8], l8[8];
#pragma unroll
        for (int j = 0; j < 8; j++)
            split1(fmaxf(acc[i][j] + bias[ccol + j], 0.0f), h8[j], l8[j]);
        *(uint4*)(g_a1hi + (size_t)(crow + i) * H1 + ccol) = *(const uint4*)h8;
        *(uint4*)(g_a1lo + (size_t)(crow + i) * H1 + ccol) = *(const uint4*)l8;
    }
}

// ---------------- bf16-split NT GEMM (128x128, K-tile 64, 3-stage) ----------
#define RB   144
#define ASZ  18432
#define STG  73728
template<int OUTM, int RELU>
__global__ __launch_bounds__(256) void gemm_tc(
    const bf16* __restrict__ Ahi, const bf16* __restrict__ Alo,
    const bf16* __restrict__ Bhi, const bf16* __restrict__ Blo,
    const float* __restrict__ bias,
    float* __restrict__ Cf, bf16* __restrict__ Chi, bf16* __restrict__ Clo,
    int N, int K)
{
    extern __shared__ char smraw[];
    const uint32_t sb = su32(smraw);
    const int tid = threadIdx.x, warp = tid >> 5, lane = tid & 31;
    const int wm = warp >> 2, wn = warp & 3, g = lane >> 2, tg = lane & 3;
    const int mBase = blockIdx.y * 128, nBase = blockIdx.x * 128;
    const int NT = K / 64;
    const int arow = (lane & 7) + ((lane >> 3) & 1) * 8, ach = lane >> 4;
    const int brow = (lane & 7) + ((lane >> 4) & 1) * 8, bch = (lane >> 3) & 1;

    float acc[4][4][4];
#pragma unroll
    for (int i = 0; i < 4; i++)
#pragma unroll
        for (int j = 0; j < 4; j++)
#pragma unroll
            for (int q = 0; q < 4; q++) acc[i][j][q] = 0.0f;

    auto load_stage = [&](int st, int k0) {
        uint32_t d0 = sb + st * STG;
#pragma unroll
        for (int q = 0; q < 4; q++) {
            int c = q * 256 + tid, row = c >> 3, ch = c & 7;
            size_t ka = (size_t)(mBase + row) * K + k0 + ch * 8;
            size_t kb = (size_t)(nBase + row) * K + k0 + ch * 8;
            uint32_t o = row * RB + ch * 16;
            cpa16(d0 + o,           Ahi + ka);
            cpa16(d0 + ASZ + o,     Alo + ka);
            cpa16(d0 + 2 * ASZ + o, Bhi + kb);
            cpa16(d0 + 3 * ASZ + o, Blo + kb);
        }
        cp_commit();
    };

    load_stage(0, 0);
    load_stage(1, 64);
    for (int kt = 0; kt < NT; kt++) {
        if (kt < NT - 1) cp_wait1(); else cp_wait0();
        __syncthreads();
        if (kt + 2 < NT) load_stage((kt + 2) % 3, (kt + 2) * 64);
        const uint32_t s0 = sb + (kt % 3) * STG;
#pragma unroll
        for (int kk = 0; kk < 4; kk++) {
            uint32_t ah[4][4], al[4][4];
#pragma unroll
            for (int i = 0; i < 4; i++) {
                uint32_t ad = s0 + (wm * 64 + i * 16 + arow) * RB + (kk * 2 + ach) * 16;
                ldsm4(ah[i], ad);
                ldsm4(al[i], ad + ASZ);
            }
#pragma unroll
            for (int j = 0; j < 2; j++) {
                uint32_t bh[4], bl[4];
                uint32_t bd = s0 + 2 * ASZ + (wn * 32 + j * 16 + brow) * RB + (kk * 2 + bch) * 16;
                ldsm4(bh, bd);
                ldsm4(bl, bd + ASZ);
#pragma unroll
                for (int i = 0; i < 4; i++) {
                    mma16816(acc[i][2 * j],     ah[i], bh);
                    mma16816(acc[i][2 * j],     ah[i], bl);
                    mma16816(acc[i][2 * j],     al[i], bh);
                    mma16816(acc[i][2 * j + 1], ah[i], bh + 2);
                    mma16816(acc[i][2 * j + 1], ah[i], bl + 2);
                    mma16816(acc[i][2 * j + 1], al[i], bh + 2);
                }
            }
        }
    }

#pragma unroll
    for (int i = 0; i < 4; i++) {
        const int row = mBase + wm * 64 + i * 16 + g;
#pragma unroll
        for (int j = 0; j < 4; j++) {
            const int col = nBase + wn * 32 + j * 8 + 2 * tg;
            const float b0 = bias[col], b1 = bias[col + 1];
            float v00 = acc[i][j][0] + b0, v01 = acc[i][j][1] + b1;
            float v10 = acc[i][j][2] + b0, v11 = acc[i][j][3] + b1;
            if (RELU) { v00 = fmaxf(v00, 0.f); v01 = fmaxf(v01, 0.f);
                        v10 = fmaxf(v10, 0.f); v11 = fmaxf(v11, 0.f); }
            if (OUTM == 0) {
                *(float2*)(Cf + (size_t)row * N + col)       = make_float2(v00, v01);
                *(float2*)(Cf + (size_t)(row + 8) * N + col) = make_float2(v10, v11);
            } else {
                unsigned short h0, l0, h1, l1;
                split1(v00, h0, l0); split1(v01, h1, l1);
                *(uint32_t*)(Chi + (size_t)row * N + col) = (uint32_t)h0 | ((uint32_t)h1 << 16);
                *(uint32_t*)(Clo + (size_t)row * N + col) = (uint32_t)l0 | ((uint32_t)l1 << 16);
                split1(v10, h0, l0); split1(v11, h1, l1);
                *(uint32_t*)(Chi + (size_t)(row + 8) * N + col) = (uint32_t)h0 | ((uint32_t)h1 << 16);
                *(uint32_t*)(Clo + (size_t)(row + 8) * N + col) = (uint32_t)l0 | ((uint32_t)l1 << 16);
            }
        }
    }
}

// ---------------- persistent GRU (256 thr, M64 x N64/block, 3-stage) --------
#define GASZ 9216
#define GSTG 36864
__global__ __launch_bounds__(256) void gru_persist(
    const float* __restrict__ b_hh, const int* __restrict__ labraw)
{
    extern __shared__ char smraw[];
    const uint32_t sb = su32(smraw);
    const int tid = threadIdx.x, bid = blockIdx.x, warp = tid >> 5, lane = tid & 31;
    const int wm = warp >> 2, wn = warp & 3, g = lane >> 2, tg = lane & 3;
    const int n0 = bid * 64;
    const int arow = (lane & 7) + ((lane >> 3) & 1) * 8, ach = lane >> 4;
    const int brow = (lane & 7) + ((lane >> 4) & 1) * 8, bch = (lane >> 3) & 1;
    const int gsz = NBLK * 256, gtid = bid * 256 + tid;

    for (int i = gtid; i < BB * HM; i += gsz) {
        g_hshi[i] = __float2bfloat16(0.0f);
        g_hslo[i] = __float2bfloat16(0.0f);
    }
    if (bid == 0 && warp == 0) {
        unsigned oddmask = __ballot_sync(0xffffffff, labraw[2 * lane + 1] != 0);
        if (oddmask == 0) { g_labels[lane] = labraw[2 * lane]; g_labels[lane + 32] = labraw[2 * (lane + 32)]; }
        else              { g_labels[lane] = labraw[lane];     g_labels[lane + 32] = labraw[lane + 32]; }
    }
    gridbar();

    const int NT = HM / 64;
    for (int t = 0; t < TT; t++) {
        const bf16* Ah_t = g_hshi + (size_t)t * BB * HM;
        const bf16* Al_t = g_hslo + (size_t)t * BB * HM;

        float acc[2][2][4];
#pragma unroll
        for (int i = 0; i < 2; i++)
#pragma unroll
            for (int j = 0; j < 2; j++)
#pragma unroll
                for (int q = 0; q < 4; q++) acc[i][j][q] = 0.0f;

        auto load_stage = [&](int st, int k0) {
            uint32_t d0 = sb + st * GSTG;
#pragma unroll
            for (int q = 0; q < 2; q++) {
                int c = q * 256 + tid, row = c >> 3, ch = c & 7;
                size_t ka = (size_t)row * HM + k0 + ch * 8;
                size_t kb = (size_t)(n0 + row) * HM + k0 + ch * 8;
                uint32_t o = row * RB + ch * 16;
                cpa16(d0 + o,            Ah_t + ka);
                cpa16(d0 + GASZ + o,     Al_t + ka);
                cpa16(d0 + 2 * GASZ + o, g_Whhhi + kb);
                cpa16(d0 + 3 * GASZ + o, g_Whhlo + kb);
            }
            cp_commit();
        };

        load_stage(0, 0);
        load_stage(1, 64);
        for (int kt = 0; kt < NT; kt++) {
            if (kt < NT - 1) cp_wait1(); else cp_wait0();
            __syncthreads();
            if (kt + 2 < NT) load_stage((kt + 2) % 3, (kt + 2) * 64);
            const uint32_t s0 = sb + (kt % 3) * GSTG;
#pragma unroll
            for (int kk = 0; kk < 4; kk++) {
                uint32_t ah[2][4], al[2][4];
#pragma unroll
                for (int i = 0; i < 2; i++) {
                    uint32_t ad = s0 + (wm * 32 + i * 16 + arow) * RB + (kk * 2 + ach) * 16;
                    ldsm4(ah[i], ad);
                    ldsm4(al[i], ad + GASZ);
                }
                uint32_t bh[4], bl[4];
                uint32_t bd = s0 + 2 * GASZ + (wn * 16 + brow) * RB + (kk * 2 + bch) * 16;
                ldsm4(bh, bd);
                ldsm4(bl, bd + GASZ);
#pragma unroll
                for (int i = 0; i < 2; i++) {
                    mma16816(acc[i][0], ah[i], bh);
                    mma16816(acc[i][0], ah[i], bl);
                    mma16816(acc[i][0], al[i], bh);
                    mma16816(acc[i][1], ah[i], bh + 2);
                    mma16816(acc[i][1], ah[i], bl + 2);
                    mma16816(acc[i][1], al[i], bh + 2);
                }
            }
        }

        // epilogue -> g_hg
#pragma unroll
        for (int i = 0; i < 2; i++) {
            const int row = wm * 32 + i * 16 + g;
#pragma unroll
            for (int j = 0; j < 2; j++) {
                const int col = n0 + wn * 16 + j * 8 + 2 * tg;
                *(float2*)(g_hg + (size_t)row * G3 + col)       = make_float2(acc[i][j][0], acc[i][j][1]);
                *(float2*)(g_hg + (size_t)(row + 8) * G3 + col) = make_float2(acc[i][j][2], acc[i][j][3]);
            }
        }
        gridbar();

        // fused gates
        {
            bf16* hhn = g_hshi + (size_t)(t + 1) * BB * HM;
            bf16* hln = g_hslo + (size_t)(t + 1) * BB * HM;
            for (int idx = gtid; idx < BB * HM; idx += gsz) {
                const int b = idx >> 11, u = idx & 2047;
                const float ar = g_hg[(size_t)b * G3 + u]          + b_hh[u];
                const float az = g_hg[(size_t)b * G3 + HM + u]     + b_hh[HM + u];
                const float an = g_hg[(size_t)b * G3 + 2 * HM + u] + b_hh[2 * HM + u];
                const float* xrow = g_xg + (size_t)(b * TT + t) * G3;
                const float r  = 1.0f / (1.0f + expf(-(xrow[u] + ar)));
                const float z  = 1.0f / (1.0f + expf(-(xrow[HM + u] + az)));
                const float nn = tanhf(xrow[2 * HM + u] + r * an);
                const float hp = __bfloat162float(Ah_t[idx]) + __bfloat162float(Al_t[idx]);
                const float h  = (1.0f - z) * nn + z * hp;
                unsigned short hh, hl;
                split1(h, hh, hl);
                hhn[idx] = *reinterpret_cast<bf16*>(&hh);
                hln[idx] = *reinterpret_cast<bf16*>(&hl);
            }
        }
        gridbar();
    }
}

// ---------------- heads + zero ----------------------------------------------
__global__ __launch_bounds__(128) void heads_kernel(
    const float* __restrict__ W4, const float* __restrict__ b4,
    const float* __restrict__ W5, const float* __restrict__ b5,
    const float* __restrict__ W6, const float* __restrict__ b6,
    float* __restrict__ out)
{
    const int r = blockIdx.x, t = r >> 6, b = r & 63;
    const int lab = g_labels[b];
    const float* s  = g_outs + (size_t)r * PEN;
    const float* w4 = W4 + (size_t)lab * PEN;
    const float* w5 = W5 + (size_t)lab * PEN;
    const float* w6 = W6 + (size_t)lab * PEN;
    float a4 = 0.f, a5 = 0.f, a6 = 0.f;
    for (int p = threadIdx.x; p < PEN; p += 128) {
        const float v = s[p];
        a4 += v * w4[p]; a5 += v * w5[p]; a6 += v * w6[p];
    }
    __shared__ float red[3][128];
    red[0][threadIdx.x] = a4; red[1][threadIdx.x] = a5; red[2][threadIdx.x] = a6;
    __syncthreads();
    for (int s2 = 64; s2 > 0; s2 >>= 1) {
        if (threadIdx.x < s2) {
            red[0][threadIdx.x] += red[0][threadIdx.x + s2];
            red[1][threadIdx.x] += red[1][threadIdx.x + s2];
            red[2][threadIdx.x] += red[2][threadIdx.x + s2];
        }
        __syncthreads();
    }
    if (threadIdx.x == 0) {
        const int o = b * TT + t;
        out[o]          = red[0][0] + b4[lab];
        out[BT + o]     = red[1][0] + b5[lab];
        out[2 * BT + o] = red[2][0] + b6[lab];
    }
}

__global__ void zero_kernel(float* p, int n)
{
    int i = blockIdx.x * blockDim.x + threadIdx.x;
    if (i < n) p[i] = 0.0f;
}

// ---------------- launch ----------------------------------------------------
extern "C" void kernel_launch(void* const* d_in, const int* in_sizes, int n_in,
                              void* d_out, int out_size)
{
    const float* x    = (const float*)d_in[0];
    const int*   labr = (const int*)d_in[1];
    const float* W1   = (const float*)d_in[2];
    const float* b1   = (const float*)d_in[3];
    const float* W2   = (const float*)d_in[4];
    const float* b2   = (const float*)d_in[5];
    const float* W_ih = (const float*)d_in[6];
    const float* W_hh = (const float*)d_in[7];
    const float* b_ih = (const float*)d_in[8];
    const float* b_hh = (const float*)d_in[9];
    const float* W3   = (const float*)d_in[10];
    const float* b3   = (const float*)d_in[11];
    const float* W4   = (const float*)d_in[12];
    const float* b4   = (const float*)d_in[13];
    const float* W5   = (const float*)d_in[14];
    const float* b5   = (const float*)d_in[15];
    const float* W6   = (const float*)d_in[16];
    const float* b6   = (const float*)d_in[17];
    float* out = (float*)d_out;

    bf16 *a1hi, *a1lo, *a2hi, *a2lo, *hshi, *hslo, *w2hi, *w2lo, *wihhi, *wihlo, *w3hi, *w3lo;
    float *xg, *outs;
    cudaGetSymbolAddress((void**)&a1hi, g_a1hi);
    cudaGetSymbolAddress((void**)&a1lo, g_a1lo);
    cudaGetSymbolAddress((void**)&a2hi, g_a2hi);
    cudaGetSymbolAddress((void**)&a2lo, g_a2lo);
    cudaGetSymbolAddress((void**)&hshi, g_hshi);
    cudaGetSymbolAddress((void**)&hslo, g_hslo);
    cudaGetSymbolAddress((void**)&w2hi, g_W2hi);
    cudaGetSymbolAddress((void**)&w2lo, g_W2lo);
    cudaGetSymbolAddress((void**)&wihhi, g_Wihhi);
    cudaGetSymbolAddress((void**)&wihlo, g_Wihlo);
    cudaGetSymbolAddress((void**)&w3hi, g_W3hi);
    cudaGetSymbolAddress((void**)&w3lo, g_W3lo);
    cudaGetSymbolAddress((void**)&xg, g_xg);
    cudaGetSymbolAddress((void**)&outs, g_outs);

    const int GEMM_SMEM = 3 * STG;    // 221184
    const int GRU_SMEM  = 3 * GSTG;   // 110592
    cudaFuncSetAttribute(gemm_tc<0, 0>, cudaFuncAttributeMaxDynamicSharedMemorySize, GEMM_SMEM);
    cudaFuncSetAttribute(gemm_tc<0, 1>, cudaFuncAttributeMaxDynamicSharedMemorySize, GEMM_SMEM);
    cudaFuncSetAttribute(gemm_tc<1, 1>, cudaFuncAttributeMaxDynamicSharedMemorySize, GEMM_SMEM);
    cudaFuncSetAttribute(gru_persist, cudaFuncAttributeMaxDynamicSharedMemorySize, GRU_SMEM);

    // 0) zero output tail
    const int tail = out_size - 3 * BT;
    zero_kernel<<<(((tail > 0 ? tail : 1) + 255) / 256), 256>>>(out + 3 * BT, tail > 0 ? tail : 0);
    // 1) act1
    {
        dim3 g(H1 / 128, BT / 128);
        gemm_ffma_split<<<g, 256>>>(x, W1, b1);
    }
    // 2) split all weights
    {
        size_t chunks = (size_t)H2 * H1 / 8 + (size_t)G3 * H2 / 8 + (size_t)G3 * HM / 8 + (size_t)PEN * HM / 8;
        split_all<<<(unsigned)((chunks + 255) / 256), 256>>>(W2, W_ih, W_hh, W3);
    }
    // 3) act2 -> bf16 hi/lo
    {
        dim3 g(H2 / 128, BT / 128);
        gemm_tc<1, 1><<<g, 256, GEMM_SMEM>>>(a1hi, a1lo, w2hi, w2lo, b2,
                                             nullptr, a2hi, a2lo, H2, H1);
    }
    // 4) xg -> f32
    {
        dim3 g(G3 / 128, BT / 128);
        gemm_tc<0, 0><<<g, 256, GEMM_SMEM>>>(a2hi, a2lo, wihhi, wihlo, b_ih,
                                             xg, nullptr, nullptr, G3, H2);
    }
    // 5) persistent GRU (profiled)
    gru_persist<<<NBLK, 256, GRU_SMEM>>>(b_hh, labr);
    // 6) out_s = relu(h @ W3^T + b3)
    {
        dim3 g(PEN / 128, BT / 128);
        gemm_tc<0, 1><<<g, 256, GEMM_SMEM>>>(hshi + (size_t)BB * HM, hslo + (size_t)BB * HM,
                                             w3hi, w3lo, b3, outs, nullptr, nullptr, PEN, HM);
    }
    // 7) heads
    heads_kernel<<<BT, 128>>>(W4, b4, W5, b5, W6, b6, out);
}

// round 9
// speedup vs baseline: 1.9823x; 1.0182x over previous
#include <cuda_runtime.h>
#include <cuda_bf16.h>
#include <math.h>
#include <stdint.h>

#define BB 64
#define TT 366
#define INF 24
#define H1 1024
#define H2 2048
#define HM 2048
#define PEN 1024
#define BT 23424
#define G3 6144
#define NBLK 128
typedef __nv_bfloat16 bf16;

// ---------------- scratch ---------------------------------------------------
__device__ bf16  g_a1hi[(size_t)BT * H1];
__device__ bf16  g_a1lo[(size_t)BT * H1];
__device__ bf16  g_a2hi[(size_t)BT * H2];
__device__ bf16  g_a2lo[(size_t)BT * H2];
__device__ float g_xg  [(size_t)BT * G3];
__device__ bf16  g_hshi[(size_t)(TT + 1) * BB * HM];
__device__ bf16  g_hslo[(size_t)(TT + 1) * BB * HM];
__device__ float g_outs[(size_t)BT * PEN];
__device__ float g_hg  [(size_t)BB * G3];
__device__ bf16  g_W2hi [(size_t)H2 * H1];
__device__ bf16  g_W2lo [(size_t)H2 * H1];
__device__ bf16  g_Wihhi[(size_t)G3 * H2];
__device__ bf16  g_Wihlo[(size_t)G3 * H2];
__device__ bf16  g_Whhhi[(size_t)G3 * HM];
__device__ bf16  g_Whhlo[(size_t)G3 * HM];
__device__ bf16  g_W3hi [(size_t)PEN * HM];
__device__ bf16  g_W3lo [(size_t)PEN * HM];
__device__ int      g_labels[BB];
__device__ unsigned g_bar_cnt = 0;
__device__ volatile unsigned g_bar_gen = 0;

// ---------------- asm helpers ----------------------------------------------
__device__ __forceinline__ uint32_t su32(const void* p) {
    uint32_t a;
    asm("{ .reg .u64 t; cvta.to.shared.u64 t, %1; cvt.u32.u64 %0, t; }" : "=r"(a) : "l"(p));
    return a;
}
__device__ __forceinline__ void mma16816(float* d, const uint32_t* a, const uint32_t* b) {
    asm volatile(
        "mma.sync.aligned.m16n8k16.row.col.f32.bf16.bf16.f32 "
        "{%0,%1,%2,%3},{%4,%5,%6,%7},{%8,%9},{%0,%1,%2,%3};"
        : "+f"(d[0]), "+f"(d[1]), "+f"(d[2]), "+f"(d[3])
        : "r"(a[0]), "r"(a[1]), "r"(a[2]), "r"(a[3]), "r"(b[0]), "r"(b[1]));
}
__device__ __forceinline__ void ldsm4(uint32_t* r, uint32_t a) {
    asm volatile("ldmatrix.sync.aligned.m8n8.x4.shared.b16 {%0,%1,%2,%3},[%4];"
                 : "=r"(r[0]), "=r"(r[1]), "=r"(r[2]), "=r"(r[3]) : "r"(a));
}
__device__ __forceinline__ void cpa16(uint32_t d, const void* s) {
    asm volatile("cp.async.cg.shared.global [%0],[%1],16;" :: "r"(d), "l"(s));
}
__device__ __forceinline__ void cp_commit() { asm volatile("cp.async.commit_group;"); }
__device__ __forceinline__ void cp_wait1()  { asm volatile("cp.async.wait_group 1;"); }
__device__ __forceinline__ void cp_wait0()  { asm volatile("cp.async.wait_group 0;"); }

__device__ __forceinline__ void split1(float v, unsigned short& h, unsigned short& l) {
    bf16 hb = __float2bfloat16(v);
    h = *reinterpret_cast<unsigned short*>(&hb);
    bf16 lb = __float2bfloat16(v - __bfloat162float(hb));
    l = *reinterpret_cast<unsigned short*>(&lb);
}
__device__ __forceinline__ void split8(const float* s, bf16* hi, bf16* lo) {
    float4 a = *(const float4*)s, b = *(const float4*)(s + 4);
    float v[8] = {a.x, a.y, a.z, a.w, b.x, b.y, b.z, b.w};
    __align__(16) unsigned short h[8], l[8];
#pragma unroll
    for (int i = 0; i < 8; i++) split1(v[i], h[i], l[i]);
    *(uint4*)hi = *(const uint4*)h;
    *(uint4*)lo = *(const uint4*)l;
}

__device__ __forceinline__ void gridbar()
{
    __syncthreads();
    if (threadIdx.x == 0) {
        __threadfence();
        unsigned g = g_bar_gen;
        if (atomicAdd(&g_bar_cnt, 1u) == NBLK - 1) {
            g_bar_cnt = 0;
            __threadfence();
            g_bar_gen = g + 1;
        } else {
            while (g_bar_gen == g) { __nanosleep(32); }
        }
        __threadfence();
    }
    __syncthreads();
}

// ---------------- split all weights -----------------------------------------
__global__ __launch_bounds__(256) void split_all(
    const float* __restrict__ W2, const float* __restrict__ Wih,
    const float* __restrict__ Whh, const float* __restrict__ W3r)
{
    const size_t n1 = (size_t)H2 * H1 / 8, n2 = (size_t)G3 * H2 / 8;
    const size_t n3 = (size_t)G3 * HM / 8, n4 = (size_t)PEN * HM / 8;
    size_t c = (size_t)blockIdx.x * 256 + threadIdx.x;
    if (c < n1) split8(W2 + c * 8, g_W2hi + c * 8, g_W2lo + c * 8);
    else if (c < n1 + n2) { size_t j = c - n1; split8(Wih + j * 8, g_Wihhi + j * 8, g_Wihlo + j * 8); }
    else if (c < n1 + n2 + n3) { size_t j = c - n1 - n2; split8(Whh + j * 8, g_Whhhi + j * 8, g_Whhlo + j * 8); }
    else if (c < n1 + n2 + n3 + n4) { size_t j = c - n1 - n2 - n3; split8(W3r + j * 8, g_W3hi + j * 8, g_W3lo + j * 8); }
}

// ---------------- act1 FFMA (K=24) -> bf16 hi/lo ----------------------------
__global__ __launch_bounds__(256) void gemm_ffma_split(
    const float* __restrict__ A, const float* __restrict__ Bm,
    const float* __restrict__ bias)
{
    __shared__ float As[8][128], Bs[8][128];
    const int tid = threadIdx.x, tx = tid & 15, ty = tid >> 4;
    const int arow = tid >> 1, acol = (tid & 1) << 2;
    const float* Ap = A  + (size_t)(blockIdx.y * 128 + arow) * INF + acol;
    const float* Bp = Bm + (size_t)(blockIdx.x * 128 + arow) * INF + acol;
    float acc[8][8];
#pragma unroll
    for (int i = 0; i < 8; i++)
#pragma unroll
        for (int j = 0; j < 8; j++) acc[i][j] = 0.0f;
    for (int k0 = 0; k0 < INF; k0 += 8) {
        float4 a = *(const float4*)(Ap + k0);
        float4 b = *(const float4*)(Bp + k0);
        __syncthreads();
        As[acol][arow] = a.x; As[acol + 1][arow] = a.y; As[acol + 2][arow] = a.z; As[acol + 3][arow] = a.w;
        Bs[acol][arow] = b.x; Bs[acol + 1][arow] = b.y; Bs[acol + 2][arow] = b.z; Bs[acol + 3][arow] = b.w;
        __syncthreads();
#pragma unroll
        for (int k = 0; k < 8; k++) {
            float av[8], bv[8];
            *(float4*)av       = *(const float4*)&As[k][ty * 8];
            *(float4*)(av + 4) = *(const float4*)&As[k][ty * 8 + 4];
            *(float4*)bv       = *(const float4*)&Bs[k][tx * 8];
            *(float4*)(bv + 4) = *(const float4*)&Bs[k][tx * 8 + 4];
#pragma unroll
            for (int i = 0; i < 8; i++)
#pragma unroll
                for (int j = 0; j < 8; j++) acc[i][j] += av[i] * bv[j];
        }
    }
    const int crow = blockIdx.y * 128 + ty * 8, ccol = blockIdx.x * 128 + tx * 8;
#pragma unroll
    for (int i = 0; i < 8; i++) {
        __align__(16) unsigned short h8[8], l8[8];
#pragma unroll
        for (int j = 0; j < 8; j++)
            split1(fmaxf(acc[i][j] + bias[ccol + j], 0.0f), h8[j], l8[j]);
        *(uint4*)(g_a1hi + (size_t)(crow + i) * H1 + ccol) = *(const uint4*)h8;
        *(uint4*)(g_a1lo + (size_t)(crow + i) * H1 + ccol) = *(const uint4*)l8;
    }
}

// ---------------- bf16-split NT GEMM (128x128, K-tile 64, 3-stage) ----------
#define RB   144
#define ASZ  18432
#define STG  73728
template<int OUTM, int RELU>
__global__ __launch_bounds__(256, 1) void gemm_tc(
    const bf16* __restrict__ Ahi, const bf16* __restrict__ Alo,
    const bf16* __restrict__ Bhi, const bf16* __restrict__ Blo,
    const float* __restrict__ bias,
    float* __restrict__ Cf, bf16* __restrict__ Chi, bf16* __restrict__ Clo,
    int N, int K)
{
    extern __shared__ char smraw[];
    const uint32_t sb = su32(smraw);
    const int tid = threadIdx.x, warp = tid >> 5, lane = tid & 31;
    const int wm = warp >> 2, wn = warp & 3, g = lane >> 2, tg = lane & 3;
    const int mBase = blockIdx.y * 128, nBase = blockIdx.x * 128;
    const int NT = K / 64;
    const int arow = (lane & 7) + ((lane >> 3) & 1) * 8, ach = lane >> 4;
    const int brow = (lane & 7) + ((lane >> 4) & 1) * 8, bch = (lane >> 3) & 1;

    float acc[4][4][4];
#pragma unroll
    for (int i = 0; i < 4; i++)
#pragma unroll
        for (int j = 0; j < 4; j++)
#pragma unroll
            for (int q = 0; q < 4; q++) acc[i][j][q] = 0.0f;

    auto load_stage = [&](int st, int k0) {
        uint32_t d0 = sb + st * STG;
#pragma unroll
        for (int q = 0; q < 4; q++) {
            int c = q * 256 + tid, row = c >> 3, ch = c & 7;
            size_t ka = (size_t)(mBase + row) * K + k0 + ch * 8;
            size_t kb = (size_t)(nBase + row) * K + k0 + ch * 8;
            uint32_t o = row * RB + ch * 16;
            cpa16(d0 + o,           Ahi + ka);
            cpa16(d0 + ASZ + o,     Alo + ka);
            cpa16(d0 + 2 * ASZ + o, Bhi + kb);
            cpa16(d0 + 3 * ASZ + o, Blo + kb);
        }
        cp_commit();
    };

    load_stage(0, 0);
    load_stage(1, 64);
    for (int kt = 0; kt < NT; kt++) {
        if (kt < NT - 1) cp_wait1(); else cp_wait0();
        __syncthreads();
        if (kt + 2 < NT) load_stage((kt + 2) % 3, (kt + 2) * 64);
        const uint32_t s0 = sb + (kt % 3) * STG;
#pragma unroll
        for (int kk = 0; kk < 4; kk++) {
            uint32_t ah[4][4], al[4][4];
#pragma unroll
            for (int i = 0; i < 4; i++) {
                uint32_t ad = s0 + (wm * 64 + i * 16 + arow) * RB + (kk * 2 + ach) * 16;
                ldsm4(ah[i], ad);
                ldsm4(al[i], ad + ASZ);
            }
#pragma unroll
            for (int j = 0; j < 2; j++) {
                uint32_t bh[4], bl[4];
                uint32_t bd = s0 + 2 * ASZ + (wn * 32 + j * 16 + brow) * RB + (kk * 2 + bch) * 16;
                ldsm4(bh, bd);
                ldsm4(bl, bd + ASZ);
#pragma unroll
                for (int i = 0; i < 4; i++) {
                    mma16816(acc[i][2 * j],     ah[i], bh);
                    mma16816(acc[i][2 * j],     ah[i], bl);
                    mma16816(acc[i][2 * j],     al[i], bh);
                    mma16816(acc[i][2 * j + 1], ah[i], bh + 2);
                    mma16816(acc[i][2 * j + 1], ah[i], bl + 2);
                    mma16816(acc[i][2 * j + 1], al[i], bh + 2);
                }
            }
        }
    }

#pragma unroll
    for (int i = 0; i < 4; i++) {
        const int row = mBase + wm * 64 + i * 16 + g;
#pragma unroll
        for (int j = 0; j < 4; j++) {
            const int col = nBase + wn * 32 + j * 8 + 2 * tg;
            const float b0 = bias[col], b1 = bias[col + 1];
            float v00 = acc[i][j][0] + b0, v01 = acc[i][j][1] + b1;
            float v10 = acc[i][j][2] + b0, v11 = acc[i][j][3] + b1;
            if (RELU) { v00 = fmaxf(v00, 0.f); v01 = fmaxf(v01, 0.f);
                        v10 = fmaxf(v10, 0.f); v11 = fmaxf(v11, 0.f); }
            if (OUTM == 0) {
                *(float2*)(Cf + (size_t)row * N + col)       = make_float2(v00, v01);
                *(float2*)(Cf + (size_t)(row + 8) * N + col) = make_float2(v10, v11);
            } else {
                unsigned short h0, l0, h1, l1;
                split1(v00, h0, l0); split1(v01, h1, l1);
                *(uint32_t*)(Chi + (size_t)row * N + col) = (uint32_t)h0 | ((uint32_t)h1 << 16);
                *(uint32_t*)(Clo + (size_t)row * N + col) = (uint32_t)l0 | ((uint32_t)l1 << 16);
                split1(v10, h0, l0); split1(v11, h1, l1);
                *(uint32_t*)(Chi + (size_t)(row + 8) * N + col) = (uint32_t)h0 | ((uint32_t)h1 << 16);
                *(uint32_t*)(Clo + (size_t)(row + 8) * N + col) = (uint32_t)l0 | ((uint32_t)l1 << 16);
            }
        }
    }
}

// ---------------- persistent GRU (128 blk x 192 thr, N-slice 48, 3-stage) ---
// stage: Ah@0(9216) Al@9216 Bh@18432(6912) Bl@25344 ; GSTG=32256
#define GA   9216
#define GBO  18432
#define GBLO 25344
#define GSTG 32256
__global__ __launch_bounds__(192, 1) void gru_persist(
    const float* __restrict__ b_hh, const int* __restrict__ labraw)
{
    extern __shared__ char smraw[];
    const uint32_t sb = su32(smraw);
    const int tid = threadIdx.x, bid = blockIdx.x, warp = tid >> 5, lane = tid & 31;
    const int wm = warp / 3, wn = warp % 3, g = lane >> 2, tg = lane & 3;
    const int n0 = bid * 48;
    const int arow = (lane & 7) + ((lane >> 3) & 1) * 8, ach = lane >> 4;
    const int brow = (lane & 7) + ((lane >> 4) & 1) * 8, bch = (lane >> 3) & 1;
    const int gsz = NBLK * 192, gtid = bid * 192 + tid;

    for (int i = gtid; i < BB * HM; i += gsz) {
        g_hshi[i] = __float2bfloat16(0.0f);
        g_hslo[i] = __float2bfloat16(0.0f);
    }
    if (bid == 0 && warp == 0) {
        unsigned oddmask = __ballot_sync(0xffffffff, labraw[2 * lane + 1] != 0);
        if (oddmask == 0) { g_labels[lane] = labraw[2 * lane]; g_labels[lane + 32] = labraw[2 * (lane + 32)]; }
        else              { g_labels[lane] = labraw[lane];     g_labels[lane + 32] = labraw[lane + 32]; }
    }
    gridbar();

    const int NT = HM / 64;
    for (int t = 0; t < TT; t++) {
        const bf16* Ah_t = g_hshi + (size_t)t * BB * HM;
        const bf16* Al_t = g_hslo + (size_t)t * BB * HM;

        float acc[2][2][4];
#pragma unroll
        for (int i = 0; i < 2; i++)
#pragma unroll
            for (int j = 0; j < 2; j++)
#pragma unroll
                for (int q = 0; q < 4; q++) acc[i][j][q] = 0.0f;

        auto load_stage = [&](int st, int k0) {
            uint32_t d0 = sb + st * GSTG;
            for (int c = tid; c < 1792; c += 192) {
                if (c < 1024) {
                    const bool hi = c < 512;
                    const int cc = c & 511, row = cc >> 3, ch = cc & 7;
                    size_t ka = (size_t)row * HM + k0 + ch * 8;
                    cpa16(d0 + (hi ? 0 : GA) + row * RB + ch * 16,
                          (hi ? Ah_t : Al_t) + ka);
                } else {
                    const bool hi = c < 1408;
                    const int cc = c - (hi ? 1024 : 1408), row = cc >> 3, ch = cc & 7;
                    size_t kb = (size_t)(n0 + row) * HM + k0 + ch * 8;
                    cpa16(d0 + (hi ? GBO : GBLO) + row * RB + ch * 16,
                          (hi ? g_Whhhi : g_Whhlo) + kb);
                }
            }
            cp_commit();
        };

        load_stage(0, 0);
        load_stage(1, 64);
        for (int kt = 0; kt < NT; kt++) {
            if (kt < NT - 1) cp_wait1(); else cp_wait0();
            __syncthreads();
            if (kt + 2 < NT) load_stage((kt + 2) % 3, (kt + 2) * 64);
            const uint32_t s0 = sb + (kt % 3) * GSTG;
#pragma unroll
            for (int kk = 0; kk < 4; kk++) {
                uint32_t ah[2][4], al[2][4];
#pragma unroll
                for (int i = 0; i < 2; i++) {
                    uint32_t ad = s0 + (wm * 32 + i * 16 + arow) * RB + (kk * 2 + ach) * 16;
                    ldsm4(ah[i], ad);
                    ldsm4(al[i], ad + GA);
                }
                uint32_t bh[4], bl[4];
                uint32_t bd = s0 + GBO + (wn * 16 + brow) * RB + (kk * 2 + bch) * 16;
                ldsm4(bh, bd);
                ldsm4(bl, bd + (GBLO - GBO));
#pragma unroll
                for (int i = 0; i < 2; i++) {
                    mma16816(acc[i][0], ah[i], bh);
                    mma16816(acc[i][0], ah[i], bl);
                    mma16816(acc[i][0], al[i], bh);
                    mma16816(acc[i][1], ah[i], bh + 2);
                    mma16816(acc[i][1], ah[i], bl + 2);
                    mma16816(acc[i][1], al[i], bh + 2);
                }
            }
        }

        // epilogue -> g_hg
#pragma unroll
        for (int i = 0; i < 2; i++) {
            const int row = wm * 32 + i * 16 + g;
#pragma unroll
            for (int j = 0; j < 2; j++) {
                const int col = n0 + wn * 16 + j * 8 + 2 * tg;
                *(float2*)(g_hg + (size_t)row * G3 + col)       = make_float2(acc[i][j][0], acc[i][j][1]);
                *(float2*)(g_hg + (size_t)(row + 8) * G3 + col) = make_float2(acc[i][j][2], acc[i][j][3]);
            }
        }
        gridbar();

        // fused gates
        {
            bf16* hhn = g_hshi + (size_t)(t + 1) * BB * HM;
            bf16* hln = g_hslo + (size_t)(t + 1) * BB * HM;
            for (int idx = gtid; idx < BB * HM; idx += gsz) {
                const int b = idx >> 11, u = idx & 2047;
                const float ar = g_hg[(size_t)b * G3 + u]          + b_hh[u];
                const float az = g_hg[(size_t)b * G3 + HM + u]     + b_hh[HM + u];
                const float an = g_hg[(size_t)b * G3 + 2 * HM + u] + b_hh[2 * HM + u];
                const float* xrow = g_xg + (size_t)(b * TT + t) * G3;
                const float r  = 1.0f / (1.0f + expf(-(xrow[u] + ar)));
                const float z  = 1.0f / (1.0f + expf(-(xrow[HM + u] + az)));
                const float nn = tanhf(xrow[2 * HM + u] + r * an);
                const float hp = __bfloat162float(Ah_t[idx]) + __bfloat162float(Al_t[idx]);
                const float h  = (1.0f - z) * nn + z * hp;
                unsigned short hh, hl;
                split1(h, hh, hl);
                hhn[idx] = *reinterpret_cast<bf16*>(&hh);
                hln[idx] = *reinterpret_cast<bf16*>(&hl);
            }
        }
        gridbar();
    }
}

// ---------------- heads + zero ----------------------------------------------
__global__ __launch_bounds__(128) void heads_kernel(
    const float* __restrict__ W4, const float* __restrict__ b4,
    const float* __restrict__ W5, const float* __restrict__ b5,
    const float* __restrict__ W6, const float* __restrict__ b6,
    float* __restrict__ out)
{
    const int r = blockIdx.x, t = r >> 6, b = r & 63;
    const int lab = g_labels[b];
    const float* s  = g_outs + (size_t)r * PEN;
    const float* w4 = W4 + (size_t)lab * PEN;
    const float* w5 = W5 + (size_t)lab * PEN;
    const float* w6 = W6 + (size_t)lab * PEN;
    float a4 = 0.f, a5 = 0.f, a6 = 0.f;
    for (int p = threadIdx.x; p < PEN; p += 128) {
        const float v = s[p];
        a4 += v * w4[p]; a5 += v * w5[p]; a6 += v * w6[p];
    }
    __shared__ float red[3][128];
    red[0][threadIdx.x] = a4; red[1][threadIdx.x] = a5; red[2][threadIdx.x] = a6;
    __syncthreads();
    for (int s2 = 64; s2 > 0; s2 >>= 1) {
        if (threadIdx.x < s2) {
            red[0][threadIdx.x] += red[0][threadIdx.x + s2];
            red[1][threadIdx.x] += red[1][threadIdx.x + s2];
            red[2][threadIdx.x] += red[2][threadIdx.x + s2];
        }
        __syncthreads();
    }
    if (threadIdx.x == 0) {
        const int o = b * TT + t;
        out[o]          = red[0][0] + b4[lab];
        out[BT + o]     = red[1][0] + b5[lab];
        out[2 * BT + o] = red[2][0] + b6[lab];
    }
}

__global__ void zero_kernel(float* p, int n)
{
    int i = blockIdx.x * blockDim.x + threadIdx.x;
    if (i < n) p[i] = 0.0f;
}

// ---------------- launch ----------------------------------------------------
extern "C" void kernel_launch(void* const* d_in, const int* in_sizes, int n_in,
                              void* d_out, int out_size)
{
    const float* x    = (const float*)d_in[0];
    const int*   labr = (const int*)d_in[1];
    const float* W1   = (const float*)d_in[2];
    const float* b1   = (const float*)d_in[3];
    const float* W2   = (const float*)d_in[4];
    const float* b2   = (const float*)d_in[5];
    const float* W_ih = (const float*)d_in[6];
    const float* W_hh = (const float*)d_in[7];
    const float* b_ih = (const float*)d_in[8];
    const float* b_hh = (const float*)d_in[9];
    const float* W3   = (const float*)d_in[10];
    const float* b3   = (const float*)d_in[11];
    const float* W4   = (const float*)d_in[12];
    const float* b4   = (const float*)d_in[13];
    const float* W5   = (const float*)d_in[14];
    const float* b5   = (const float*)d_in[15];
    const float* W6   = (const float*)d_in[16];
    const float* b6   = (const float*)d_in[17];
    float* out = (float*)d_out;

    bf16 *a1hi, *a1lo, *a2hi, *a2lo, *hshi, *hslo, *w2hi, *w2lo, *wihhi, *wihlo, *w3hi, *w3lo;
    float *xg, *outs;
    cudaGetSymbolAddress((void**)&a1hi, g_a1hi);
    cudaGetSymbolAddress((void**)&a1lo, g_a1lo);
    cudaGetSymbolAddress((void**)&a2hi, g_a2hi);
    cudaGetSymbolAddress((void**)&a2lo, g_a2lo);
    cudaGetSymbolAddress((void**)&hshi, g_hshi);
    cudaGetSymbolAddress((void**)&hslo, g_hslo);
    cudaGetSymbolAddress((void**)&w2hi, g_W2hi);
    cudaGetSymbolAddress((void**)&w2lo, g_W2lo);
    cudaGetSymbolAddress((void**)&wihhi, g_Wihhi);
    cudaGetSymbolAddress((void**)&wihlo, g_Wihlo);
    cudaGetSymbolAddress((void**)&w3hi, g_W3hi);
    cudaGetSymbolAddress((void**)&w3lo, g_W3lo);
    cudaGetSymbolAddress((void**)&xg, g_xg);
    cudaGetSymbolAddress((void**)&outs, g_outs);

    const int GEMM_SMEM = 3 * STG;    // 221184
    const int GRU_SMEM  = 3 * GSTG;   //  96768
    cudaFuncSetAttribute(gemm_tc<0, 0>, cudaFuncAttributeMaxDynamicSharedMemorySize, GEMM_SMEM);
    cudaFuncSetAttribute(gemm_tc<0, 1>, cudaFuncAttributeMaxDynamicSharedMemorySize, GEMM_SMEM);
    cudaFuncSetAttribute(gemm_tc<1, 1>, cudaFuncAttributeMaxDynamicSharedMemorySize, GEMM_SMEM);
    cudaFuncSetAttribute(gru_persist, cudaFuncAttributeMaxDynamicSharedMemorySize, GRU_SMEM);

    // 0) zero output tail
    const int tail = out_size - 3 * BT;
    zero_kernel<<<(((tail > 0 ? tail : 1) + 255) / 256), 256>>>(out + 3 * BT, tail > 0 ? tail : 0);
    // 1) act1
    {
        dim3 g(H1 / 128, BT / 128);
        gemm_ffma_split<<<g, 256>>>(x, W1, b1);
    }
    // 2) split all weights
    {
        size_t chunks = (size_t)H2 * H1 / 8 + (size_t)G3 * H2 / 8 + (size_t)G3 * HM / 8 + (size_t)PEN * HM / 8;
        split_all<<<(unsigned)((chunks + 255) / 256), 256>>>(W2, W_ih, W_hh, W3);
    }
    // 3) act2 -> bf16 hi/lo
    {
        dim3 g(H2 / 128, BT / 128);
        gemm_tc<1, 1><<<g, 256, GEMM_SMEM>>>(a1hi, a1lo, w2hi, w2lo, b2,
                                             nullptr, a2hi, a2lo, H2, H1);
    }
    // 4) xg -> f32
    {
        dim3 g(G3 / 128, BT / 128);
        gemm_tc<0, 0><<<g, 256, GEMM_SMEM>>>(a2hi, a2lo, wihhi, wihlo, b_ih,
                                             xg, nullptr, nullptr, G3, H2);
    }
    // 5) persistent GRU (profiled)
    gru_persist<<<NBLK, 192, GRU_SMEM>>>(b_hh, labr);
    // 6) out_s = relu(h @ W3^T + b3)
    {
        dim3 g(PEN / 128, BT / 128);
        gemm_tc<0, 1><<<g, 256, GEMM_SMEM>>>(hshi + (size_t)BB * HM, hslo + (size_t)BB * HM,
                                             w3hi, w3lo, b3, outs, nullptr, nullptr, PEN, HM);
    }
    // 7) heads
    heads_kernel<<<BT, 128>>>(W4, b4, W5, b5, W6, b6, out);
}

// round 10
// speedup vs baseline: 2.0320x; 1.0250x over previous
#include <cuda_runtime.h>
#include <cuda_bf16.h>
#include <math.h>
#include <stdint.h>

#define BB 64
#define TT 366
#define INF 24
#define H1 1024
#define H2 2048
#define HM 2048
#define PEN 1024
#define BT 23424
#define G3 6144
#define NBLK 128
typedef __nv_bfloat16 bf16;

// ---------------- scratch ---------------------------------------------------
__device__ bf16  g_a1hi[(size_t)BT * H1];
__device__ bf16  g_a1lo[(size_t)BT * H1];
__device__ bf16  g_a2hi[(size_t)BT * H2];
__device__ bf16  g_a2lo[(size_t)BT * H2];
__device__ float g_xg  [(size_t)BT * G3];
__device__ bf16  g_hshi[(size_t)(TT + 1) * BB * HM];
__device__ bf16  g_hslo[(size_t)(TT + 1) * BB * HM];
__device__ float g_outs[(size_t)BT * PEN];
__device__ bf16  g_W2hi [(size_t)H2 * H1];
__device__ bf16  g_W2lo [(size_t)H2 * H1];
__device__ bf16  g_Wihhi[(size_t)G3 * H2];
__device__ bf16  g_Wihlo[(size_t)G3 * H2];
__device__ bf16  g_Whhhi[(size_t)G3 * HM];   // gate-permuted layout
__device__ bf16  g_Whhlo[(size_t)G3 * HM];   // gate-permuted layout
__device__ bf16  g_W3hi [(size_t)PEN * HM];
__device__ bf16  g_W3lo [(size_t)PEN * HM];
__device__ int      g_labels[BB];
__device__ unsigned g_bar_cnt = 0;
__device__ volatile unsigned g_bar_gen = 0;

// ---------------- asm helpers ----------------------------------------------
__device__ __forceinline__ uint32_t su32(const void* p) {
    uint32_t a;
    asm("{ .reg .u64 t; cvta.to.shared.u64 t, %1; cvt.u32.u64 %0, t; }" : "=r"(a) : "l"(p));
    return a;
}
__device__ __forceinline__ void mma16816(float* d, const uint32_t* a, const uint32_t* b) {
    asm volatile(
        "mma.sync.aligned.m16n8k16.row.col.f32.bf16.bf16.f32 "
        "{%0,%1,%2,%3},{%4,%5,%6,%7},{%8,%9},{%0,%1,%2,%3};"
        : "+f"(d[0]), "+f"(d[1]), "+f"(d[2]), "+f"(d[3])
        : "r"(a[0]), "r"(a[1]), "r"(a[2]), "r"(a[3]), "r"(b[0]), "r"(b[1]));
}
__device__ __forceinline__ void ldsm4(uint32_t* r, uint32_t a) {
    asm volatile("ldmatrix.sync.aligned.m8n8.x4.shared.b16 {%0,%1,%2,%3},[%4];"
                 : "=r"(r[0]), "=r"(r[1]), "=r"(r[2]), "=r"(r[3]) : "r"(a));
}
__device__ __forceinline__ void cpa16(uint32_t d, const void* s) {
    asm volatile("cp.async.cg.shared.global [%0],[%1],16;" :: "r"(d), "l"(s));
}
__device__ __forceinline__ void cp_commit() { asm volatile("cp.async.commit_group;"); }
__device__ __forceinline__ void cp_wait1()  { asm volatile("cp.async.wait_group 1;"); }
__device__ __forceinline__ void cp_wait0()  { asm volatile("cp.async.wait_group 0;"); }

__device__ __forceinline__ void split1(float v, unsigned short& h, unsigned short& l) {
    bf16 hb = __float2bfloat16(v);
    h = *reinterpret_cast<unsigned short*>(&hb);
    bf16 lb = __float2bfloat16(v - __bfloat162float(hb));
    l = *reinterpret_cast<unsigned short*>(&lb);
}
__device__ __forceinline__ void split8(const float* s, bf16* hi, bf16* lo) {
    float4 a = *(const float4*)s, b = *(const float4*)(s + 4);
    float v[8] = {a.x, a.y, a.z, a.w, b.x, b.y, b.z, b.w};
    __align__(16) unsigned short h[8], l[8];
#pragma unroll
    for (int i = 0; i < 8; i++) split1(v[i], h[i], l[i]);
    *(uint4*)hi = *(const uint4*)h;
    *(uint4*)lo = *(const uint4*)l;
}

__device__ __forceinline__ void gridbar()
{
    __syncthreads();
    if (threadIdx.x == 0) {
        __threadfence();
        unsigned g = g_bar_gen;
        if (atomicAdd(&g_bar_cnt, 1u) == NBLK - 1) {
            g_bar_cnt = 0;
            __threadfence();
            g_bar_gen = g + 1;
        } else {
            while (g_bar_gen == g) { __nanosleep(32); }
        }
        __threadfence();
    }
    __syncthreads();
}

// ---------------- split all weights (Whh gate-permuted) ---------------------
// Whh dest: block bid owns rows [bid*48, bid*48+48) = gates {r,z,n} x 16 units
// dest row = (u>>4)*48 + gate*16 + (u&15)   for source row = gate*HM + u
__global__ __launch_bounds__(256) void split_all(
    const float* __restrict__ W2, const float* __restrict__ Wih,
    const float* __restrict__ Whh, const float* __restrict__ W3r)
{
    const size_t n1 = (size_t)H2 * H1 / 8, n2 = (size_t)G3 * H2 / 8;
    const size_t n3 = (size_t)G3 * HM / 8, n4 = (size_t)PEN * HM / 8;
    size_t c = (size_t)blockIdx.x * 256 + threadIdx.x;
    if (c < n1) split8(W2 + c * 8, g_W2hi + c * 8, g_W2lo + c * 8);
    else if (c < n1 + n2) { size_t j = c - n1; split8(Wih + j * 8, g_Wihhi + j * 8, g_Wihlo + j * 8); }
    else if (c < n1 + n2 + n3) {
        size_t j = c - n1 - n2;
        const size_t rpc = HM / 8;
        size_t row = j / rpc, wi = j % rpc;
        int gate = (int)(row >> 11);
        int u    = (int)(row & 2047);
        size_t drow = (size_t)(u >> 4) * 48 + (size_t)gate * 16 + (u & 15);
        size_t d = drow * rpc + wi;
        split8(Whh + j * 8, g_Whhhi + d * 8, g_Whhlo + d * 8);
    }
    else if (c < n1 + n2 + n3 + n4) { size_t j = c - n1 - n2 - n3; split8(W3r + j * 8, g_W3hi + j * 8, g_W3lo + j * 8); }
}

// ---------------- act1 FFMA (K=24) -> bf16 hi/lo ----------------------------
__global__ __launch_bounds__(256) void gemm_ffma_split(
    const float* __restrict__ A, const float* __restrict__ Bm,
    const float* __restrict__ bias)
{
    __shared__ float As[8][128], Bs[8][128];
    const int tid = threadIdx.x, tx = tid & 15, ty = tid >> 4;
    const int arow = tid >> 1, acol = (tid & 1) << 2;
    const float* Ap = A  + (size_t)(blockIdx.y * 128 + arow) * INF + acol;
    const float* Bp = Bm + (size_t)(blockIdx.x * 128 + arow) * INF + acol;
    float acc[8][8];
#pragma unroll
    for (int i = 0; i < 8; i++)
#pragma unroll
        for (int j = 0; j < 8; j++) acc[i][j] = 0.0f;
    for (int k0 = 0; k0 < INF; k0 += 8) {
        float4 a = *(const float4*)(Ap + k0);
        float4 b = *(const float4*)(Bp + k0);
        __syncthreads();
        As[acol][arow] = a.x; As[acol + 1][arow] = a.y; As[acol + 2][arow] = a.z; As[acol + 3][arow] = a.w;
        Bs[acol][arow] = b.x; Bs[acol + 1][arow] = b.y; Bs[acol + 2][arow] = b.z; Bs[acol + 3][arow] = b.w;
        __syncthreads();
#pragma unroll
        for (int k = 0; k < 8; k++) {
            float av[8], bv[8];
            *(float4*)av       = *(const float4*)&As[k][ty * 8];
            *(float4*)(av + 4) = *(const float4*)&As[k][ty * 8 + 4];
            *(float4*)bv       = *(const float4*)&Bs[k][tx * 8];
            *(float4*)(bv + 4) = *(const float4*)&Bs[k][tx * 8 + 4];
#pragma unroll
            for (int i = 0; i < 8; i++)
#pragma unroll
                for (int j = 0; j < 8; j++) acc[i][j] += av[i] * bv[j];
        }
    }
    const int crow = blockIdx.y * 128 + ty * 8, ccol = blockIdx.x * 128 + tx * 8;
#pragma unroll
    for (int i = 0; i < 8; i++) {
        __align__(16) unsigned short h8[8], l8[8];
#pragma unroll
        for (int j = 0; j < 8; j++)
            split1(fmaxf(acc[i][j] + bias[ccol + j], 0.0f), h8[j], l8[j]);
        *(uint4*)(g_a1hi + (size_t)(crow + i) * H1 + ccol) = *(const uint4*)h8;
        *(uint4*)(g_a1lo + (size_t)(crow + i) * H1 + ccol) = *(const uint4*)l8;
    }
}

// ---------------- bf16-split NT GEMM (128x128, K-tile 64, 3-stage) ----------
#define RB   144
#define ASZ  18432
#define STG  73728
template<int OUTM, int RELU>
__global__ __launch_bounds__(256, 1) void gemm_tc(
    const bf16* __restrict__ Ahi, const bf16* __restrict__ Alo,
    const bf16* __restrict__ Bhi, const bf16* __restrict__ Blo,
    const float* __restrict__ bias,
    float* __restrict__ Cf, bf16* __restrict__ Chi, bf16* __restrict__ Clo,
    int N, int K)
{
    extern __shared__ char smraw[];
    const uint32_t sb = su32(smraw);
    const int tid = threadIdx.x, warp = tid >> 5, lane = tid & 31;
    const int wm = warp >> 2, wn = warp & 3, g = lane >> 2, tg = lane & 3;
    const int mBase = blockIdx.y * 128, nBase = blockIdx.x * 128;
    const int NT = K / 64;
    const int arow = (lane & 7) + ((lane >> 3) & 1) * 8, ach = lane >> 4;
    const int brow = (lane & 7) + ((lane >> 4) & 1) * 8, bch = (lane >> 3) & 1;

    float acc[4][4][4];
#pragma unroll
    for (int i = 0; i < 4; i++)
#pragma unroll
        for (int j = 0; j < 4; j++)
#pragma unroll
            for (int q = 0; q < 4; q++) acc[i][j][q] = 0.0f;

    auto load_stage = [&](int st, int k0) {
        uint32_t d0 = sb + st * STG;
#pragma unroll
        for (int q = 0; q < 4; q++) {
            int c = q * 256 + tid, row = c >> 3, ch = c & 7;
            size_t ka = (size_t)(mBase + row) * K + k0 + ch * 8;
            size_t kb = (size_t)(nBase + row) * K + k0 + ch * 8;
            uint32_t o = row * RB + ch * 16;
            cpa16(d0 + o,           Ahi + ka);
            cpa16(d0 + ASZ + o,     Alo + ka);
            cpa16(d0 + 2 * ASZ + o, Bhi + kb);
            cpa16(d0 + 3 * ASZ + o, Blo + kb);
        }
        cp_commit();
    };

    load_stage(0, 0);
    load_stage(1, 64);
    for (int kt = 0; kt < NT; kt++) {
        if (kt < NT - 1) cp_wait1(); else cp_wait0();
        __syncthreads();
        if (kt + 2 < NT) load_stage((kt + 2) % 3, (kt + 2) * 64);
        const uint32_t s0 = sb + (kt % 3) * STG;
#pragma unroll
        for (int kk = 0; kk < 4; kk++) {
            uint32_t ah[4][4], al[4][4];
#pragma unroll
            for (int i = 0; i < 4; i++) {
                uint32_t ad = s0 + (wm * 64 + i * 16 + arow) * RB + (kk * 2 + ach) * 16;
                ldsm4(ah[i], ad);
                ldsm4(al[i], ad + ASZ);
            }
#pragma unroll
            for (int j = 0; j < 2; j++) {
                uint32_t bh[4], bl[4];
                uint32_t bd = s0 + 2 * ASZ + (wn * 32 + j * 16 + brow) * RB + (kk * 2 + bch) * 16;
                ldsm4(bh, bd);
                ldsm4(bl, bd + ASZ);
#pragma unroll
                for (int i = 0; i < 4; i++) {
                    mma16816(acc[i][2 * j],     ah[i], bh);
                    mma16816(acc[i][2 * j],     ah[i], bl);
                    mma16816(acc[i][2 * j],     al[i], bh);
                    mma16816(acc[i][2 * j + 1], ah[i], bh + 2);
                    mma16816(acc[i][2 * j + 1], ah[i], bl + 2);
                    mma16816(acc[i][2 * j + 1], al[i], bh + 2);
                }
            }
        }
    }

#pragma unroll
    for (int i = 0; i < 4; i++) {
        const int row = mBase + wm * 64 + i * 16 + g;
#pragma unroll
        for (int j = 0; j < 4; j++) {
            const int col = nBase + wn * 32 + j * 8 + 2 * tg;
            const float b0 = bias[col], b1 = bias[col + 1];
            float v00 = acc[i][j][0] + b0, v01 = acc[i][j][1] + b1;
            float v10 = acc[i][j][2] + b0, v11 = acc[i][j][3] + b1;
            if (RELU) { v00 = fmaxf(v00, 0.f); v01 = fmaxf(v01, 0.f);
                        v10 = fmaxf(v10, 0.f); v11 = fmaxf(v11, 0.f); }
            if (OUTM == 0) {
                *(float2*)(Cf + (size_t)row * N + col)       = make_float2(v00, v01);
                *(float2*)(Cf + (size_t)(row + 8) * N + col) = make_float2(v10, v11);
            } else {
                unsigned short h0, l0, h1, l1;
                split1(v00, h0, l0); split1(v01, h1, l1);
                *(uint32_t*)(Chi + (size_t)row * N + col) = (uint32_t)h0 | ((uint32_t)h1 << 16);
                *(uint32_t*)(Clo + (size_t)row * N + col) = (uint32_t)l0 | ((uint32_t)l1 << 16);
                split1(v10, h0, l0); split1(v11, h1, l1);
                *(uint32_t*)(Chi + (size_t)(row + 8) * N + col) = (uint32_t)h0 | ((uint32_t)h1 << 16);
                *(uint32_t*)(Clo + (size_t)(row + 8) * N + col) = (uint32_t)l0 | ((uint32_t)l1 << 16);
            }
        }
    }
}

// ---------------- persistent GRU (fused gates, 1 gridbar/step) --------------
// 128 blocks x 192 thr; block bid owns hidden units [bid*16, bid*16+16),
// its 48 W-rows (gate-permuted) give r/z/n for those units.
#define GA   9216
#define GBO  18432
#define GBLO 25344
#define GSTG 32256
#define ACCP 52
__global__ __launch_bounds__(192, 1) void gru_persist(
    const float* __restrict__ b_hh, const int* __restrict__ labraw)
{
    extern __shared__ char smraw[];
    const uint32_t sb = su32(smraw);
    float* smacc = (float*)(smraw + 3 * GSTG);   // 64 x 52 floats = 13312 B
    const int tid = threadIdx.x, bid = blockIdx.x, warp = tid >> 5, lane = tid & 31;
    const int wm = warp / 3, wn = warp % 3, g = lane >> 2, tg = lane & 3;
    const int arow = (lane & 7) + ((lane >> 3) & 1) * 8, ach = lane >> 4;
    const int brow = (lane & 7) + ((lane >> 4) & 1) * 8, bch = (lane >> 3) & 1;
    const int gsz = NBLK * 192, gtid = bid * 192 + tid;
    const int u0 = bid * 16;

    for (int i = gtid; i < BB * HM; i += gsz) {
        g_hshi[i] = __float2bfloat16(0.0f);
        g_hslo[i] = __float2bfloat16(0.0f);
    }
    if (bid == 0 && warp == 0) {
        unsigned oddmask = __ballot_sync(0xffffffff, labraw[2 * lane + 1] != 0);
        if (oddmask == 0) { g_labels[lane] = labraw[2 * lane]; g_labels[lane + 32] = labraw[2 * (lane + 32)]; }
        else              { g_labels[lane] = labraw[lane];     g_labels[lane + 32] = labraw[lane + 32]; }
    }
    gridbar();

    const int NT = HM / 64;
    for (int t = 0; t < TT; t++) {
        const bf16* Ah_t = g_hshi + (size_t)t * BB * HM;
        const bf16* Al_t = g_hslo + (size_t)t * BB * HM;

        // 12 independent accumulator chains per warp (hh/hl/lh x 2 x 2)
        float ahh[2][2][4], ahl[2][2][4], alh[2][2][4];
#pragma unroll
        for (int i = 0; i < 2; i++)
#pragma unroll
            for (int j = 0; j < 2; j++)
#pragma unroll
                for (int q = 0; q < 4; q++) { ahh[i][j][q] = 0.f; ahl[i][j][q] = 0.f; alh[i][j][q] = 0.f; }

        auto load_stage = [&](int st, int k0) {
            uint32_t d0 = sb + st * GSTG;
            for (int c = tid; c < 1792; c += 192) {
                if (c < 1024) {
                    const bool hi = c < 512;
                    const int cc = c & 511, row = cc >> 3, ch = cc & 7;
                    size_t ka = (size_t)row * HM + k0 + ch * 8;
                    cpa16(d0 + (hi ? 0 : GA) + row * RB + ch * 16,
                          (hi ? Ah_t : Al_t) + ka);
                } else {
                    const bool hi = c < 1408;
                    const int cc = c - (hi ? 1024 : 1408), row = cc >> 3, ch = cc & 7;
                    size_t kb = (size_t)(bid * 48 + row) * HM + k0 + ch * 8;
                    cpa16(d0 + (hi ? GBO : GBLO) + row * RB + ch * 16,
                          (hi ? g_Whhhi : g_Whhlo) + kb);
                }
            }
            cp_commit();
        };

        load_stage(0, 0);
        load_stage(1, 64);
        for (int kt = 0; kt < NT; kt++) {
            if (kt < NT - 1) cp_wait1(); else cp_wait0();
            __syncthreads();
            if (kt + 2 < NT) load_stage((kt + 2) % 3, (kt + 2) * 64);
            const uint32_t s0 = sb + (kt % 3) * GSTG;
#pragma unroll
            for (int kk = 0; kk < 4; kk++) {
                uint32_t ah[2][4], al[2][4];
#pragma unroll
                for (int i = 0; i < 2; i++) {
                    uint32_t ad = s0 + (wm * 32 + i * 16 + arow) * RB + (kk * 2 + ach) * 16;
                    ldsm4(ah[i], ad);
                    ldsm4(al[i], ad + GA);
                }
                uint32_t bh[4], bl[4];
                uint32_t bd = s0 + GBO + (wn * 16 + brow) * RB + (kk * 2 + bch) * 16;
                ldsm4(bh, bd);
                ldsm4(bl, bd + (GBLO - GBO));
#pragma unroll
                for (int i = 0; i < 2; i++) {
                    mma16816(ahh[i][0], ah[i], bh);
                    mma16816(ahl[i][0], ah[i], bl);
                    mma16816(alh[i][0], al[i], bh);
                    mma16816(ahh[i][1], ah[i], bh + 2);
                    mma16816(ahl[i][1], ah[i], bl + 2);
                    mma16816(alh[i][1], al[i], bh + 2);
                }
            }
        }

        // merge chains and stash tile in smem
#pragma unroll
        for (int i = 0; i < 2; i++) {
            const int row = wm * 32 + i * 16 + g;
#pragma unroll
            for (int j = 0; j < 2; j++) {
                const int col = wn * 16 + j * 8 + 2 * tg;
                float s0v = ahh[i][j][0] + ahl[i][j][0] + alh[i][j][0];
                float s1v = ahh[i][j][1] + ahl[i][j][1] + alh[i][j][1];
                float s2v = ahh[i][j][2] + ahl[i][j][2] + alh[i][j][2];
                float s3v = ahh[i][j][3] + ahl[i][j][3] + alh[i][j][3];
                smacc[row * ACCP + col]           = s0v;
                smacc[row * ACCP + col + 1]       = s1v;
                smacc[(row + 8) * ACCP + col]     = s2v;
                smacc[(row + 8) * ACCP + col + 1] = s3v;
            }
        }
        __syncthreads();

        // fused gates for this block's 16 hidden units x 64 batches
        {
            bf16* hhn = g_hshi + (size_t)(t + 1) * BB * HM;
            bf16* hln = g_hslo + (size_t)(t + 1) * BB * HM;
            for (int idx = tid; idx < BB * 16; idx += 192) {
                const int b = idx >> 4, ul = idx & 15;
                const int u = u0 + ul;
                const float ar = smacc[b * ACCP + ul]      + b_hh[u];
                const float az = smacc[b * ACCP + 16 + ul] + b_hh[HM + u];
                const float an = smacc[b * ACCP + 32 + ul] + b_hh[2 * HM + u];
                const float* xrow = g_xg + (size_t)(b * TT + t) * G3;
                const float r  = 1.0f / (1.0f + expf(-(xrow[u] + ar)));
                const float z  = 1.0f / (1.0f + expf(-(xrow[HM + u] + az)));
                const float nn = tanhf(xrow[2 * HM + u] + r * an);
                const float hp = __bfloat162float(Ah_t[(size_t)b * HM + u])
                               + __bfloat162float(Al_t[(size_t)b * HM + u]);
                const float h  = (1.0f - z) * nn + z * hp;
                unsigned short hh, hl;
                split1(h, hh, hl);
                hhn[(size_t)b * HM + u] = *reinterpret_cast<bf16*>(&hh);
                hln[(size_t)b * HM + u] = *reinterpret_cast<bf16*>(&hl);
            }
        }
        gridbar();
    }
}

// ---------------- heads + zero ----------------------------------------------
__global__ __launch_bounds__(128) void heads_kernel(
    const float* __restrict__ W4, const float* __restrict__ b4,
    const float* __restrict__ W5, const float* __restrict__ b5,
    const float* __restrict__ W6, const float* __restrict__ b6,
    float* __restrict__ out)
{
    const int r = blockIdx.x, t = r >> 6, b = r & 63;
    const int lab = g_labels[b];
    const float* s  = g_outs + (size_t)r * PEN;
    const float* w4 = W4 + (size_t)lab * PEN;
    const float* w5 = W5 + (size_t)lab * PEN;
    const float* w6 = W6 + (size_t)lab * PEN;
    float a4 = 0.f, a5 = 0.f, a6 = 0.f;
    for (int p = threadIdx.x; p < PEN; p += 128) {
        const float v = s[p];
        a4 += v * w4[p]; a5 += v * w5[p]; a6 += v * w6[p];
    }
    __shared__ float red[3][128];
    red[0][threadIdx.x] = a4; red[1][threadIdx.x] = a5; red[2][threadIdx.x] = a6;
    __syncthreads();
    for (int s2 = 64; s2 > 0; s2 >>= 1) {
        if (threadIdx.x < s2) {
            red[0][threadIdx.x] += red[0][threadIdx.x + s2];
            red[1][threadIdx.x] += red[1][threadIdx.x + s2];
            red[2][threadIdx.x] += red[2][threadIdx.x + s2];
        }
        __syncthreads();
    }
    if (threadIdx.x == 0) {
        const int o = b * TT + t;
        out[o]          = red[0][0] + b4[lab];
        out[BT + o]     = red[1][0] + b5[lab];
        out[2 * BT + o] = red[2][0] + b6[lab];
    }
}

__global__ void zero_kernel(float* p, int n)
{
    int i = blockIdx.x * blockDim.x + threadIdx.x;
    if (i < n) p[i] = 0.0f;
}

// ---------------- launch ----------------------------------------------------
extern "C" void kernel_launch(void* const* d_in, const int* in_sizes, int n_in,
                              void* d_out, int out_size)
{
    const float* x    = (const float*)d_in[0];
    const int*   labr = (const int*)d_in[1];
    const float* W1   = (const float*)d_in[2];
    const float* b1   = (const float*)d_in[3];
    const float* W2   = (const float*)d_in[4];
    const float* b2   = (const float*)d_in[5];
    const float* W_ih = (const float*)d_in[6];
    const float* W_hh = (const float*)d_in[7];
    const float* b_ih = (const float*)d_in[8];
    const float* b_hh = (const float*)d_in[9];
    const float* W3   = (const float*)d_in[10];
    const float* b3   = (const float*)d_in[11];
    const float* W4   = (const float*)d_in[12];
    const float* b4   = (const float*)d_in[13];
    const float* W5   = (const float*)d_in[14];
    const float* b5   = (const float*)d_in[15];
    const float* W6   = (const float*)d_in[16];
    const float* b6   = (const float*)d_in[17];
    float* out = (float*)d_out;

    bf16 *a1hi, *a1lo, *a2hi, *a2lo, *hshi, *hslo, *w2hi, *w2lo, *wihhi, *wihlo, *w3hi, *w3lo;
    float *xg, *outs;
    cudaGetSymbolAddress((void**)&a1hi, g_a1hi);
    cudaGetSymbolAddress((void**)&a1lo, g_a1lo);
    cudaGetSymbolAddress((void**)&a2hi, g_a2hi);
    cudaGetSymbolAddress((void**)&a2lo, g_a2lo);
    cudaGetSymbolAddress((void**)&hshi, g_hshi);
    cudaGetSymbolAddress((void**)&hslo, g_hslo);
    cudaGetSymbolAddress((void**)&w2hi, g_W2hi);
    cudaGetSymbolAddress((void**)&w2lo, g_W2lo);
    cudaGetSymbolAddress((void**)&wihhi, g_Wihhi);
    cudaGetSymbolAddress((void**)&wihlo, g_Wihlo);
    cudaGetSymbolAddress((void**)&w3hi, g_W3hi);
    cudaGetSymbolAddress((void**)&w3lo, g_W3lo);
    cudaGetSymbolAddress((void**)&xg, g_xg);
    cudaGetSymbolAddress((void**)&outs, g_outs);

    const int GEMM_SMEM = 3 * STG;                 // 221184
    const int GRU_SMEM  = 3 * GSTG + 64 * ACCP * 4; // 110080
    cudaFuncSetAttribute(gemm_tc<0, 0>, cudaFuncAttributeMaxDynamicSharedMemorySize, GEMM_SMEM);
    cudaFuncSetAttribute(gemm_tc<0, 1>, cudaFuncAttributeMaxDynamicSharedMemorySize, GEMM_SMEM);
    cudaFuncSetAttribute(gemm_tc<1, 1>, cudaFuncAttributeMaxDynamicSharedMemorySize, GEMM_SMEM);
    cudaFuncSetAttribute(gru_persist, cudaFuncAttributeMaxDynamicSharedMemorySize, GRU_SMEM);

    // 0) zero output tail
    const int tail = out_size - 3 * BT;
    zero_kernel<<<(((tail > 0 ? tail : 1) + 255) / 256), 256>>>(out + 3 * BT, tail > 0 ? tail : 0);
    // 1) act1
    {
        dim3 g(H1 / 128, BT / 128);
        gemm_ffma_split<<<g, 256>>>(x, W1, b1);
    }
    // 2) split all weights (Whh gate-permuted)
    {
        size_t chunks = (size_t)H2 * H1 / 8 + (size_t)G3 * H2 / 8 + (size_t)G3 * HM / 8 + (size_t)PEN * HM / 8;
        split_all<<<(unsigned)((chunks + 255) / 256), 256>>>(W2, W_ih, W_hh, W3);
    }
    // 3) act2 -> bf16 hi/lo
    {
        dim3 g(H2 / 128, BT / 128);
        gemm_tc<1, 1><<<g, 256, GEMM_SMEM>>>(a1hi, a1lo, w2hi, w2lo, b2,
                                             nullptr, a2hi, a2lo, H2, H1);
    }
    // 4) xg -> f32
    {
        dim3 g(G3 / 128, BT / 128);
        gemm_tc<0, 0><<<g, 256, GEMM_SMEM>>>(a2hi, a2lo, wihhi, wihlo, b_ih,
                                             xg, nullptr, nullptr, G3, H2);
    }
    // 5) persistent GRU (profiled)
    gru_persist<<<NBLK, 192, GRU_SMEM>>>(b_hh, labr);
    // 6) out_s = relu(h @ W3^T + b3)
    {
        dim3 g(PEN / 128, BT / 128);
        gemm_tc<0, 1><<<g, 256, GEMM_SMEM>>>(hshi + (size_t)BB * HM, hslo + (size_t)BB * HM,
                                             w3hi, w3lo, b3, outs, nullptr, nullptr, PEN, HM);
    }
    // 7) heads
    heads_kernel<<<BT, 128>>>(W4, b4, W5, b5, W6, b6, out);
}

// round 12
// speedup vs baseline: 2.2474x; 1.1060x over previous
#include <cuda_runtime.h>
#include <cuda_bf16.h>
#include <cuda_fp16.h>
#include <math.h>
#include <stdint.h>

#define BB 64
#define TT 366
#define INF 24
#define H1 1024
#define H2 2048
#define HM 2048
#define PEN 1024
#define BT 23424
#define G3 6144
#define NBLK 128
typedef __nv_bfloat16 bf16;
typedef __half h16;

// ---------------- scratch ---------------------------------------------------
__device__ bf16  g_a1hi[(size_t)BT * H1];
__device__ bf16  g_a1lo[(size_t)BT * H1];
__device__ bf16  g_a2hi[(size_t)BT * H2];
__device__ bf16  g_a2lo[(size_t)BT * H2];
__device__ float g_xg  [(size_t)BT * G3];
__device__ bf16  g_hshi[(size_t)(TT + 1) * BB * HM];   // bf16 h (for W3 GEMM)
__device__ bf16  g_hslo[(size_t)(TT + 1) * BB * HM];
__device__ h16   g_hfhi[(size_t)(TT + 1) * BB * HM];   // fp16 h (GRU A operand)
__device__ h16   g_hflo[(size_t)(TT + 1) * BB * HM];
__device__ float g_outs[(size_t)BT * PEN];
__device__ bf16  g_W2hi [(size_t)H2 * H1];
__device__ bf16  g_W2lo [(size_t)H2 * H1];
__device__ bf16  g_Wihhi[(size_t)G3 * H2];
__device__ bf16  g_Wihlo[(size_t)G3 * H2];
__device__ h16   g_Whhf [(size_t)G3 * HM];             // fp16, gate-permuted rows
__device__ bf16  g_W3hi [(size_t)PEN * HM];
__device__ bf16  g_W3lo [(size_t)PEN * HM];
__device__ int      g_labels[BB];
__device__ unsigned g_bar_cnt = 0;
__device__ volatile unsigned g_bar_gen = 0;

// ---------------- asm helpers ----------------------------------------------
__device__ __forceinline__ uint32_t su32(const void* p) {
    uint32_t a;
    asm("{ .reg .u64 t; cvta.to.shared.u64 t, %1; cvt.u32.u64 %0, t; }" : "=r"(a) : "l"(p));
    return a;
}
__device__ __forceinline__ void mma16816(float* d, const uint32_t* a, const uint32_t* b) {
    asm volatile(
        "mma.sync.aligned.m16n8k16.row.col.f32.bf16.bf16.f32 "
        "{%0,%1,%2,%3},{%4,%5,%6,%7},{%8,%9},{%0,%1,%2,%3};"
        : "+f"(d[0]), "+f"(d[1]), "+f"(d[2]), "+f"(d[3])
        : "r"(a[0]), "r"(a[1]), "r"(a[2]), "r"(a[3]), "r"(b[0]), "r"(b[1]));
}
__device__ __forceinline__ void mmaf16(float* d, const uint32_t* a, const uint32_t* b) {
    asm volatile(
        "mma.sync.aligned.m16n8k16.row.col.f32.f16.f16.f32 "
        "{%0,%1,%2,%3},{%4,%5,%6,%7},{%8,%9},{%0,%1,%2,%3};"
        : "+f"(d[0]), "+f"(d[1]), "+f"(d[2]), "+f"(d[3])
        : "r"(a[0]), "r"(a[1]), "r"(a[2]), "r"(a[3]), "r"(b[0]), "r"(b[1]));
}
__device__ __forceinline__ void ldsm4(uint32_t* r, uint32_t a) {
    asm volatile("ldmatrix.sync.aligned.m8n8.x4.shared.b16 {%0,%1,%2,%3},[%4];"
                 : "=r"(r[0]), "=r"(r[1]), "=r"(r[2]), "=r"(r[3]) : "r"(a));
}
__device__ __forceinline__ void cpa16(uint32_t d, const void* s) {
    asm volatile("cp.async.cg.shared.global [%0],[%1],16;" :: "r"(d), "l"(s));
}
__device__ __forceinline__ void cp_commit() { asm volatile("cp.async.commit_group;"); }
__device__ __forceinline__ void cp_wait1()  { asm volatile("cp.async.wait_group 1;"); }
__device__ __forceinline__ void cp_wait0()  { asm volatile("cp.async.wait_group 0;"); }

__device__ __forceinline__ void split1(float v, unsigned short& h, unsigned short& l) {
    bf16 hb = __float2bfloat16(v);
    h = *reinterpret_cast<unsigned short*>(&hb);
    bf16 lb = __float2bfloat16(v - __bfloat162float(hb));
    l = *reinterpret_cast<unsigned short*>(&lb);
}
__device__ __forceinline__ void splitH(float v, unsigned short& h, unsigned short& l) {
    h16 hb = __float2half_rn(v);
    h = *reinterpret_cast<unsigned short*>(&hb);
    h16 lb = __float2half_rn(v - __half2float(hb));
    l = *reinterpret_cast<unsigned short*>(&lb);
}
__device__ __forceinline__ void split8(const float* s, bf16* hi, bf16* lo) {
    float4 a = *(const float4*)s, b = *(const float4*)(s + 4);
    float v[8] = {a.x, a.y, a.z, a.w, b.x, b.y, b.z, b.w};
    __align__(16) unsigned short h[8], l[8];
#pragma unroll
    for (int i = 0; i < 8; i++) split1(v[i], h[i], l[i]);
    *(uint4*)hi = *(const uint4*)h;
    *(uint4*)lo = *(const uint4*)l;
}
__device__ __forceinline__ void cvt8H(const float* s, h16* w) {
    float4 a = *(const float4*)s, b = *(const float4*)(s + 4);
    float v[8] = {a.x, a.y, a.z, a.w, b.x, b.y, b.z, b.w};
    __align__(16) unsigned short o[8];
#pragma unroll
    for (int i = 0; i < 8; i++) {
        h16 hb = __float2half_rn(v[i]);
        o[i] = *reinterpret_cast<unsigned short*>(&hb);
    }
    *(uint4*)w = *(const uint4*)o;
}

__device__ __forceinline__ void gridbar()
{
    __syncthreads();
    if (threadIdx.x == 0) {
        __threadfence();
        unsigned g = g_bar_gen;
        if (atomicAdd(&g_bar_cnt, 1u) == NBLK - 1) {
            g_bar_cnt = 0;
            __threadfence();
            g_bar_gen = g + 1;
        } else {
            while (g_bar_gen == g) { __nanosleep(32); }
        }
        __threadfence();
    }
    __syncthreads();
}

// ---------------- split/convert all weights ---------------------------------
// Whh -> fp16 gate-permuted: dest row = (u>>4)*48 + gate*16 + (u&15)
__global__ __launch_bounds__(256) void split_all(
    const float* __restrict__ W2, const float* __restrict__ Wih,
    const float* __restrict__ Whh, const float* __restrict__ W3r)
{
    const size_t n1 = (size_t)H2 * H1 / 8, n2 = (size_t)G3 * H2 / 8;
    const size_t n3 = (size_t)G3 * HM / 8, n4 = (size_t)PEN * HM / 8;
    size_t c = (size_t)blockIdx.x * 256 + threadIdx.x;
    if (c < n1) split8(W2 + c * 8, g_W2hi + c * 8, g_W2lo + c * 8);
    else if (c < n1 + n2) { size_t j = c - n1; split8(Wih + j * 8, g_Wihhi + j * 8, g_Wihlo + j * 8); }
    else if (c < n1 + n2 + n3) {
        size_t j = c - n1 - n2;
        const size_t rpc = HM / 8;
        size_t row = j / rpc, wi = j % rpc;
        int gate = (int)(row >> 11), u = (int)(row & 2047);
        size_t drow = (size_t)(u >> 4) * 48 + (size_t)gate * 16 + (u & 15);
        cvt8H(Whh + j * 8, g_Whhf + (drow * rpc + wi) * 8);
    }
    else if (c < n1 + n2 + n3 + n4) { size_t j = c - n1 - n2 - n3; split8(W3r + j * 8, g_W3hi + j * 8, g_W3lo + j * 8); }
}

// ---------------- act1 FFMA (K=24) -> bf16 hi/lo ----------------------------
__global__ __launch_bounds__(256) void gemm_ffma_split(
    const float* __restrict__ A, const float* __restrict__ Bm,
    const float* __restrict__ bias)
{
    __shared__ float As[8][128], Bs[8][128];
    const int tid = threadIdx.x, tx = tid & 15, ty = tid >> 4;
    const int arow = tid >> 1, acol = (tid & 1) << 2;
    const float* Ap = A  + (size_t)(blockIdx.y * 128 + arow) * INF + acol;
    const float* Bp = Bm + (size_t)(blockIdx.x * 128 + arow) * INF + acol;
    float acc[8][8];
#pragma unroll
    for (int i = 0; i < 8; i++)
#pragma unroll
        for (int j = 0; j < 8; j++) acc[i][j] = 0.0f;
    for (int k0 = 0; k0 < INF; k0 += 8) {
        float4 a = *(const float4*)(Ap + k0);
        float4 b = *(const float4*)(Bp + k0);
        __syncthreads();
        As[acol][arow] = a.x; As[acol + 1][arow] = a.y; As[acol + 2][arow] = a.z; As[acol + 3][arow] = a.w;
        Bs[acol][arow] = b.x; Bs[acol + 1][arow] = b.y; Bs[acol + 2][arow] = b.z; Bs[acol + 3][arow] = b.w;
        __syncthreads();
#pragma unroll
        for (int k = 0; k < 8; k++) {
            float av[8], bv[8];
            *(float4*)av       = *(const float4*)&As[k][ty * 8];
            *(float4*)(av + 4) = *(const float4*)&As[k][ty * 8 + 4];
            *(float4*)bv       = *(const float4*)&Bs[k][tx * 8];
            *(float4*)(bv + 4) = *(const float4*)&Bs[k][tx * 8 + 4];
#pragma unroll
            for (int i = 0; i < 8; i++)
#pragma unroll
                for (int j = 0; j < 8; j++) acc[i][j] += av[i] * bv[j];
        }
    }
    const int crow = blockIdx.y * 128 + ty * 8, ccol = blockIdx.x * 128 + tx * 8;
#pragma unroll
    for (int i = 0; i < 8; i++) {
        __align__(16) unsigned short h8[8], l8[8];
#pragma unroll
        for (int j = 0; j < 8; j++)
            split1(fmaxf(acc[i][j] + bias[ccol + j], 0.0f), h8[j], l8[j]);
        *(uint4*)(g_a1hi + (size_t)(crow + i) * H1 + ccol) = *(const uint4*)h8;
        *(uint4*)(g_a1lo + (size_t)(crow + i) * H1 + ccol) = *(const uint4*)l8;
    }
}

// ---------------- bf16-split NT GEMM (R10, proven) --------------------------
#define RB   144
#define ASZ  18432
#define STG  73728
template<int OUTM, int RELU>
__global__ __launch_bounds__(256, 1) void gemm_tc(
    const bf16* __restrict__ Ahi, const bf16* __restrict__ Alo,
    const bf16* __restrict__ Bhi, const bf16* __restrict__ Blo,
    const float* __restrict__ bias,
    float* __restrict__ Cf, bf16* __restrict__ Chi, bf16* __restrict__ Clo,
    int N, int K)
{
    extern __shared__ char smraw[];
    const uint32_t sb = su32(smraw);
    const int tid = threadIdx.x, warp = tid >> 5, lane = tid & 31;
    const int wm = warp >> 2, wn = warp & 3, g = lane >> 2, tg = lane & 3;
    const int mBase = blockIdx.y * 128, nBase = blockIdx.x * 128;
    const int NT = K / 64;
    const int arow = (lane & 7) + ((lane >> 3) & 1) * 8, ach = lane >> 4;
    const int brow = (lane & 7) + ((lane >> 4) & 1) * 8, bch = (lane >> 3) & 1;

    float acc[4][4][4];
#pragma unroll
    for (int i = 0; i < 4; i++)
#pragma unroll
        for (int j = 0; j < 4; j++)
#pragma unroll
            for (int q = 0; q < 4; q++) acc[i][j][q] = 0.0f;

    auto load_stage = [&](int st, int k0) {
        uint32_t d0 = sb + st * STG;
#pragma unroll
        for (int q = 0; q < 4; q++) {
            int c = q * 256 + tid, row = c >> 3, ch = c & 7;
            size_t ka = (size_t)(mBase + row) * K + k0 + ch * 8;
            size_t kb = (size_t)(nBase + row) * K + k0 + ch * 8;
            uint32_t o = row * RB + ch * 16;
            cpa16(d0 + o,           Ahi + ka);
            cpa16(d0 + ASZ + o,     Alo + ka);
            cpa16(d0 + 2 * ASZ + o, Bhi + kb);
            cpa16(d0 + 3 * ASZ + o, Blo + kb);
        }
        cp_commit();
    };

    load_stage(0, 0);
    load_stage(1, 64);
    for (int kt = 0; kt < NT; kt++) {
        if (kt < NT - 1) cp_wait1(); else cp_wait0();
        __syncthreads();
        if (kt + 2 < NT) load_stage((kt + 2) % 3, (kt + 2) * 64);
        const uint32_t s0 = sb + (kt % 3) * STG;
#pragma unroll
        for (int kk = 0; kk < 4; kk++) {
            uint32_t ah[4][4], al[4][4];
#pragma unroll
            for (int i = 0; i < 4; i++) {
                uint32_t ad = s0 + (wm * 64 + i * 16 + arow) * RB + (kk * 2 + ach) * 16;
                ldsm4(ah[i], ad);
                ldsm4(al[i], ad + ASZ);
            }
#pragma unroll
            for (int j = 0; j < 2; j++) {
                uint32_t bh[4], bl[4];
                uint32_t bd = s0 + 2 * ASZ + (wn * 32 + j * 16 + brow) * RB + (kk * 2 + bch) * 16;
                ldsm4(bh, bd);
                ldsm4(bl, bd + ASZ);
#pragma unroll
                for (int i = 0; i < 4; i++) {
                    mma16816(acc[i][2 * j],     ah[i], bh);
                    mma16816(acc[i][2 * j],     ah[i], bl);
                    mma16816(acc[i][2 * j],     al[i], bh);
                    mma16816(acc[i][2 * j + 1], ah[i], bh + 2);
                    mma16816(acc[i][2 * j + 1], ah[i], bl + 2);
                    mma16816(acc[i][2 * j + 1], al[i], bh + 2);
                }
            }
        }
    }

#pragma unroll
    for (int i = 0; i < 4; i++) {
        const int row = mBase + wm * 64 + i * 16 + g;
#pragma unroll
        for (int j = 0; j < 4; j++) {
            const int col = nBase + wn * 32 + j * 8 + 2 * tg;
            const float b0 = bias[col], b1 = bias[col + 1];
            float v00 = acc[i][j][0] + b0, v01 = acc[i][j][1] + b1;
            float v10 = acc[i][j][2] + b0, v11 = acc[i][j][3] + b1;
            if (RELU) { v00 = fmaxf(v00, 0.f); v01 = fmaxf(v01, 0.f);
                        v10 = fmaxf(v10, 0.f); v11 = fmaxf(v11, 0.f); }
            if (OUTM == 0) {
                *(float2*)(Cf + (size_t)row * N + col)       = make_float2(v00, v01);
                *(float2*)(Cf + (size_t)(row + 8) * N + col) = make_float2(v10, v11);
            } else {
                unsigned short h0, l0, h1, l1;
                split1(v00, h0, l0); split1(v01, h1, l1);
                *(uint32_t*)(Chi + (size_t)row * N + col) = (uint32_t)h0 | ((uint32_t)h1 << 16);
                *(uint32_t*)(Clo + (size_t)row * N + col) = (uint32_t)l0 | ((uint32_t)l1 << 16);
                split1(v10, h0, l0); split1(v11, h1, l1);
                *(uint32_t*)(Chi + (size_t)(row + 8) * N + col) = (uint32_t)h0 | ((uint32_t)h1 << 16);
                *(uint32_t*)(Clo + (size_t)(row + 8) * N + col) = (uint32_t)l0 | ((uint32_t)l1 << 16);
            }
        }
    }
}

// ---------------- persistent GRU: fp16 W resident in smem -------------------
// 128 blk x 192 thr; W slice 48x2048 fp16 resident; A K-tile 32, 3 stages.
#define WRB   4112
#define WBYT  (48 * WRB)            // 197376
#define GAR   80
#define GAH   (64 * GAR)            // 5120
#define GSTG  (2 * GAH)             // 10240
#define ACCP  52
__global__ __launch_bounds__(192, 1) void gru_persist(
    const float* __restrict__ b_hh, const int* __restrict__ labraw)
{
    extern __shared__ char smraw[];
    const uint32_t sb = su32(smraw);
    const uint32_t aBase = sb + WBYT;
    float* smacc = (float*)(smraw + WBYT);   // aliases A stages after K-loop
    const int tid = threadIdx.x, bid = blockIdx.x, warp = tid >> 5, lane = tid & 31;
    const int wm = warp / 3, wn = warp % 3, g = lane >> 2, tg = lane & 3;
    const int arow = (lane & 7) + ((lane >> 3) & 1) * 8, ach = lane >> 4;
    const int brow = (lane & 7) + ((lane >> 4) & 1) * 8, bch = (lane >> 3) & 1;
    const int gsz = NBLK * 192, gtid = bid * 192 + tid;
    const int u0 = bid * 16;

    // load resident W slice once (48 rows x 2048 fp16, 256 16B-chunks/row)
    for (int c = tid; c < 48 * 256; c += 192) {
        int row = c >> 8, ch = c & 255;
        *(uint4*)(smraw + row * WRB + ch * 16) =
            *(const uint4*)(g_Whhf + (size_t)(bid * 48 + row) * HM + ch * 8);
    }
    for (int i = gtid; i < BB * HM; i += gsz) {
        g_hshi[i] = __float2bfloat16(0.0f);
        g_hslo[i] = __float2bfloat16(0.0f);
        g_hfhi[i] = __float2half(0.0f);
        g_hflo[i] = __float2half(0.0f);
    }
    if (bid == 0 && warp == 0) {
        unsigned oddmask = __ballot_sync(0xffffffff, labraw[2 * lane + 1] != 0);
        if (oddmask == 0) { g_labels[lane] = labraw[2 * lane]; g_labels[lane + 32] = labraw[2 * (lane + 32)]; }
        else              { g_labels[lane] = labraw[lane];     g_labels[lane + 32] = labraw[lane + 32]; }
    }
    gridbar();

    const int NT = HM / 32;   // 64 K-tiles of 32
    for (int t = 0; t < TT; t++) {
        const h16* Ah_t = g_hfhi + (size_t)t * BB * HM;
        const h16* Al_t = g_hflo + (size_t)t * BB * HM;

        float aH[2][2][4], aL[2][2][4];
#pragma unroll
        for (int i = 0; i < 2; i++)
#pragma unroll
            for (int j = 0; j < 2; j++)
#pragma unroll
                for (int q = 0; q < 4; q++) { aH[i][j][q] = 0.f; aL[i][j][q] = 0.f; }

        auto load_stage = [&](int st, int k0) {
            uint32_t d0 = aBase + st * GSTG;
            for (int c = tid; c < 512; c += 192) {
                const bool hi = c < 256;
                const int cc = c & 255, row = cc >> 2, ch = cc & 3;
                size_t ka = (size_t)row * HM + k0 + ch * 8;
                cpa16(d0 + (hi ? 0 : GAH) + row * GAR + ch * 16,
                      (hi ? Ah_t : Al_t) + ka);
            }
            cp_commit();
        };

        load_stage(0, 0);
        load_stage(1, 32);
        for (int kt = 0; kt < NT; kt++) {
            if (kt < NT - 1) cp_wait1(); else cp_wait0();
            __syncthreads();
            if (kt + 2 < NT) load_stage((kt + 2) % 3, (kt + 2) * 32);
            const uint32_t s0 = aBase + (kt % 3) * GSTG;
#pragma unroll
            for (int kk = 0; kk < 2; kk++) {
                uint32_t ah[2][4], al[2][4];
#pragma unroll
                for (int i = 0; i < 2; i++) {
                    uint32_t ad = s0 + (wm * 32 + i * 16 + arow) * GAR + (kk * 2 + ach) * 16;
                    ldsm4(ah[i], ad);
                    ldsm4(al[i], ad + GAH);
                }
                uint32_t bw[4];
                ldsm4(bw, sb + (wn * 16 + brow) * WRB + kt * 64 + kk * 32 + bch * 16);
#pragma unroll
                for (int i = 0; i < 2; i++) {
                    mmaf16(aH[i][0], ah[i], bw);
                    mmaf16(aL[i][0], al[i], bw);
                    mmaf16(aH[i][1], ah[i], bw + 2);
                    mmaf16(aL[i][1], al[i], bw + 2);
                }
            }
        }
        __syncthreads();   // A stages drained; safe to alias smacc

        // merge chains -> smacc
#pragma unroll
        for (int i = 0; i < 2; i++) {
            const int row = wm * 32 + i * 16 + g;
#pragma unroll
            for (int j = 0; j < 2; j++) {
                const int col = wn * 16 + j * 8 + 2 * tg;
                smacc[row * ACCP + col]           = aH[i][j][0] + aL[i][j][0];
                smacc[row * ACCP + col + 1]       = aH[i][j][1] + aL[i][j][1];
                smacc[(row + 8) * ACCP + col]     = aH[i][j][2] + aL[i][j][2];
                smacc[(row + 8) * ACCP + col + 1] = aH[i][j][3] + aL[i][j][3];
            }
        }
        __syncthreads();

        // fused gates: 16 hidden units x 64 batches
        {
            bf16* hbh = g_hshi + (size_t)(t + 1) * BB * HM;
            bf16* hbl = g_hslo + (size_t)(t + 1) * BB * HM;
            h16*  hfh = g_hfhi + (size_t)(t + 1) * BB * HM;
            h16*  hfl = g_hflo + (size_t)(t + 1) * BB * HM;
            for (int idx = tid; idx < BB * 16; idx += 192) {
                const int b = idx >> 4, ul = idx & 15;
                const int u = u0 + ul;
                const float ar = smacc[b * ACCP + ul]      + b_hh[u];
                const float az = smacc[b * ACCP + 16 + ul] + b_hh[HM + u];
                const float an = smacc[b * ACCP + 32 + ul] + b_hh[2 * HM + u];
                const float* xrow = g_xg + (size_t)(b * TT + t) * G3;
                const float r  = 1.0f / (1.0f + expf(-(xrow[u] + ar)));
                const float z  = 1.0f / (1.0f + expf(-(xrow[HM + u] + az)));
                const float nn = tanhf(xrow[2 * HM + u] + r * an);
                const float hp = __half2float(Ah_t[(size_t)b * HM + u])
                               + __half2float(Al_t[(size_t)b * HM + u]);
                const float h  = (1.0f - z) * nn + z * hp;
                unsigned short s0w, s1w;
                split1(h, s0w, s1w);
                hbh[(size_t)b * HM + u] = *reinterpret_cast<bf16*>(&s0w);
                hbl[(size_t)b * HM + u] = *reinterpret_cast<bf16*>(&s1w);
                splitH(h, s0w, s1w);
                hfh[(size_t)b * HM + u] = *reinterpret_cast<h16*>(&s0w);
                hfl[(size_t)b * HM + u] = *reinterpret_cast<h16*>(&s1w);
            }
        }
        gridbar();
    }
}

// ---------------- heads + zero ----------------------------------------------
__global__ __launch_bounds__(128) void heads_kernel(
    const float* __restrict__ W4, const float* __restrict__ b4,
    const float* __restrict__ W5, const float* __restrict__ b5,
    const float* __restrict__ W6, const float* __restrict__ b6,
    float* __restrict__ out)
{
    const int r = blockIdx.x, t = r >> 6, b = r & 63;
    const int lab = g_labels[b];
    const float* s  = g_outs + (size_t)r * PEN;
    const float* w4 = W4 + (size_t)lab * PEN;
    const float* w5 = W5 + (size_t)lab * PEN;
    const float* w6 = W6 + (size_t)lab * PEN;
    float a4 = 0.f, a5 = 0.f, a6 = 0.f;
    for (int p = threadIdx.x; p < PEN; p += 128) {
        const float v = s[p];
        a4 += v * w4[p]; a5 += v * w5[p]; a6 += v * w6[p];
    }
    __shared__ float red[3][128];
    red[0][threadIdx.x] = a4; red[1][threadIdx.x] = a5; red[2][threadIdx.x] = a6;
    __syncthreads();
    for (int s2 = 64; s2 > 0; s2 >>= 1) {
        if (threadIdx.x < s2) {
            red[0][threadIdx.x] += red[0][threadIdx.x + s2];
            red[1][threadIdx.x] += red[1][threadIdx.x + s2];
            red[2][threadIdx.x] += red[2][threadIdx.x + s2];
        }
        __syncthreads();
    }
    if (threadIdx.x == 0) {
        const int o = b * TT + t;
        out[o]          = red[0][0] + b4[lab];
        out[BT + o]     = red[1][0] + b5[lab];
        out[2 * BT + o] = red[2][0] + b6[lab];
    }
}

__global__ void zero_kernel(float* p, int n)
{
    int i = blockIdx.x * blockDim.x + threadIdx.x;
    if (i < n) p[i] = 0.0f;
}

// ---------------- launch ----------------------------------------------------
extern "C" void kernel_launch(void* const* d_in, const int* in_sizes, int n_in,
                              void* d_out, int out_size)
{
    const float* x    = (const float*)d_in[0];
    const int*   labr = (const int*)d_in[1];
    const float* W1   = (const float*)d_in[2];
    const float* b1   = (const float*)d_in[3];
    const float* W2   = (const float*)d_in[4];
    const float* b2   = (const float*)d_in[5];
    const float* W_ih = (const float*)d_in[6];
    const float* W_hh = (const float*)d_in[7];
    const float* b_ih = (const float*)d_in[8];
    const float* b_hh = (const float*)d_in[9];
    const float* W3   = (const float*)d_in[10];
    const float* b3   = (const float*)d_in[11];
    const float* W4   = (const float*)d_in[12];
    const float* b4   = (const float*)d_in[13];
    const float* W5   = (const float*)d_in[14];
    const float* b5   = (const float*)d_in[15];
    const float* W6   = (const float*)d_in[16];
    const float* b6   = (const float*)d_in[17];
    float* out = (float*)d_out;

    bf16 *a1hi, *a1lo, *a2hi, *a2lo, *hshi, *hslo, *w2hi, *w2lo, *wihhi, *wihlo, *w3hi, *w3lo;
    float *xg, *outs;
    cudaGetSymbolAddress((void**)&a1hi, g_a1hi);
    cudaGetSymbolAddress((void**)&a1lo, g_a1lo);
    cudaGetSymbolAddress((void**)&a2hi, g_a2hi);
    cudaGetSymbolAddress((void**)&a2lo, g_a2lo);
    cudaGetSymbolAddress((void**)&hshi, g_hshi);
    cudaGetSymbolAddress((void**)&hslo, g_hslo);
    cudaGetSymbolAddress((void**)&w2hi, g_W2hi);
    cudaGetSymbolAddress((void**)&w2lo, g_W2lo);
    cudaGetSymbolAddress((void**)&wihhi, g_Wihhi);
    cudaGetSymbolAddress((void**)&wihlo, g_Wihlo);
    cudaGetSymbolAddress((void**)&w3hi, g_W3hi);
    cudaGetSymbolAddress((void**)&w3lo, g_W3lo);
    cudaGetSymbolAddress((void**)&xg,   g_xg);
    cudaGetSymbolAddress((void**)&outs, g_outs);

    const int GEMM_SMEM = 3 * STG;              // 221184
    const int GRU_SMEM  = WBYT + 3 * GSTG;      // 228096
    cudaFuncSetAttribute(gemm_tc<0, 0>, cudaFuncAttributeMaxDynamicSharedMemorySize, GEMM_SMEM);
    cudaFuncSetAttribute(gemm_tc<0, 1>, cudaFuncAttributeMaxDynamicSharedMemorySize, GEMM_SMEM);
    cudaFuncSetAttribute(gemm_tc<1, 1>, cudaFuncAttributeMaxDynamicSharedMemorySize, GEMM_SMEM);
    cudaFuncSetAttribute(gru_persist, cudaFuncAttributeMaxDynamicSharedMemorySize, GRU_SMEM);

    // 0) zero output tail
    const int tail = out_size - 3 * BT;
    zero_kernel<<<(((tail > 0 ? tail : 1) + 255) / 256), 256>>>(out + 3 * BT, tail > 0 ? tail : 0);
    // 1) act1 -> bf16 hi/lo
    {
        dim3 g(H1 / 128, BT / 128);
        gemm_ffma_split<<<g, 256>>>(x, W1, b1);
    }
    // 2) split/convert weights (Whh -> fp16 gate-permuted)
    {
        size_t chunks = (size_t)H2 * H1 / 8 + (size_t)G3 * H2 / 8 + (size_t)G3 * HM / 8 + (size_t)PEN * HM / 8;
        split_all<<<(unsigned)((chunks + 255) / 256), 256>>>(W2, W_ih, W_hh, W3);
    }
    // 3) act2 -> bf16 hi/lo
    {
        dim3 g(H2 / 128, BT / 128);
        gemm_tc<1, 1><<<g, 256, GEMM_SMEM>>>(a1hi, a1lo, w2hi, w2lo, b2,
                                             nullptr, a2hi, a2lo, H2, H1);
    }
    // 4) xg -> f32
    {
        dim3 g(G3 / 128, BT / 128);
        gemm_tc<0, 0><<<g, 256, GEMM_SMEM>>>(a2hi, a2lo, wihhi, wihlo, b_ih,
                                             xg, nullptr, nullptr, G3, H2);
    }
    // 5) persistent GRU (profiled)
    gru_persist<<<NBLK, 192, GRU_SMEM>>>(b_hh, labr);
    // 6) out_s = relu(h @ W3^T + b3)
    {
        dim3 g(PEN / 128, BT / 128);
        gemm_tc<0, 1><<<g, 256, GEMM_SMEM>>>(hshi + (size_t)BB * HM, hslo + (size_t)BB * HM,
                                             w3hi, w3lo, b3, outs, nullptr, nullptr, PEN, HM);
    }
    // 7) heads
    heads_kernel<<<BT, 128>>>(W4, b4, W5, b5, W6, b6, out);
}

// round 13
// speedup vs baseline: 2.8970x; 1.2890x over previous
#include <cuda_runtime.h>
#include <cuda_bf16.h>
#include <cuda_fp16.h>
#include <math.h>
#include <stdint.h>

#define BB 64
#define TT 366
#define INF 24
#define H1 1024
#define H2 2048
#define HM 2048
#define PEN 1024
#define BT 23424
#define G3 6144
#define NBLK 128
typedef __nv_bfloat16 bf16;
typedef __half h16;

// ---------------- scratch ---------------------------------------------------
__device__ bf16  g_a1hi[(size_t)BT * H1];
__device__ bf16  g_a1lo[(size_t)BT * H1];
__device__ bf16  g_a2hi[(size_t)BT * H2];
__device__ bf16  g_a2lo[(size_t)BT * H2];
__device__ float g_xg  [(size_t)BT * G3];
__device__ bf16  g_hshi[(size_t)(TT + 1) * BB * HM];   // bf16 h hi (W3 GEMM + carry)
__device__ bf16  g_hslo[(size_t)(TT + 1) * BB * HM];   // bf16 h lo
__device__ h16   g_hf  [(size_t)(TT + 1) * BB * HM];   // fp16 h (GRU A operand)
__device__ float g_outs[(size_t)BT * PEN];
__device__ bf16  g_W2hi [(size_t)H2 * H1];
__device__ bf16  g_W2lo [(size_t)H2 * H1];
__device__ bf16  g_Wihhi[(size_t)G3 * H2];
__device__ bf16  g_Wihlo[(size_t)G3 * H2];
__device__ h16   g_Whhf [(size_t)G3 * HM];             // fp16, gate-permuted rows
__device__ bf16  g_W3hi [(size_t)PEN * HM];
__device__ bf16  g_W3lo [(size_t)PEN * HM];
__device__ int      g_labels[BB];
__device__ unsigned g_bar_cnt = 0;
__device__ volatile unsigned g_bar_gen = 0;

// ---------------- asm helpers ----------------------------------------------
__device__ __forceinline__ uint32_t su32(const void* p) {
    uint32_t a;
    asm("{ .reg .u64 t; cvta.to.shared.u64 t, %1; cvt.u32.u64 %0, t; }" : "=r"(a) : "l"(p));
    return a;
}
__device__ __forceinline__ void mma16816(float* d, const uint32_t* a, const uint32_t* b) {
    asm volatile(
        "mma.sync.aligned.m16n8k16.row.col.f32.bf16.bf16.f32 "
        "{%0,%1,%2,%3},{%4,%5,%6,%7},{%8,%9},{%0,%1,%2,%3};"
        : "+f"(d[0]), "+f"(d[1]), "+f"(d[2]), "+f"(d[3])
        : "r"(a[0]), "r"(a[1]), "r"(a[2]), "r"(a[3]), "r"(b[0]), "r"(b[1]));
}
__device__ __forceinline__ void mmaf16(float* d, const uint32_t* a, const uint32_t* b) {
    asm volatile(
        "mma.sync.aligned.m16n8k16.row.col.f32.f16.f16.f32 "
        "{%0,%1,%2,%3},{%4,%5,%6,%7},{%8,%9},{%0,%1,%2,%3};"
        : "+f"(d[0]), "+f"(d[1]), "+f"(d[2]), "+f"(d[3])
        : "r"(a[0]), "r"(a[1]), "r"(a[2]), "r"(a[3]), "r"(b[0]), "r"(b[1]));
}
__device__ __forceinline__ void ldsm4(uint32_t* r, uint32_t a) {
    asm volatile("ldmatrix.sync.aligned.m8n8.x4.shared.b16 {%0,%1,%2,%3},[%4];"
                 : "=r"(r[0]), "=r"(r[1]), "=r"(r[2]), "=r"(r[3]) : "r"(a));
}
__device__ __forceinline__ void cpa16(uint32_t d, const void* s) {
    asm volatile("cp.async.cg.shared.global [%0],[%1],16;" :: "r"(d), "l"(s));
}
__device__ __forceinline__ void cp_commit() { asm volatile("cp.async.commit_group;"); }
__device__ __forceinline__ void cp_wait1()  { asm volatile("cp.async.wait_group 1;"); }
__device__ __forceinline__ void cp_wait0()  { asm volatile("cp.async.wait_group 0;"); }

__device__ __forceinline__ void split1(float v, unsigned short& h, unsigned short& l) {
    bf16 hb = __float2bfloat16(v);
    h = *reinterpret_cast<unsigned short*>(&hb);
    bf16 lb = __float2bfloat16(v - __bfloat162float(hb));
    l = *reinterpret_cast<unsigned short*>(&lb);
}
__device__ __forceinline__ void split8(const float* s, bf16* hi, bf16* lo) {
    float4 a = *(const float4*)s, b = *(const float4*)(s + 4);
    float v[8] = {a.x, a.y, a.z, a.w, b.x, b.y, b.z, b.w};
    __align__(16) unsigned short h[8], l[8];
#pragma unroll
    for (int i = 0; i < 8; i++) split1(v[i], h[i], l[i]);
    *(uint4*)hi = *(const uint4*)h;
    *(uint4*)lo = *(const uint4*)l;
}
__device__ __forceinline__ void cvt8H(const float* s, h16* w) {
    float4 a = *(const float4*)s, b = *(const float4*)(s + 4);
    float v[8] = {a.x, a.y, a.z, a.w, b.x, b.y, b.z, b.w};
    __align__(16) unsigned short o[8];
#pragma unroll
    for (int i = 0; i < 8; i++) {
        h16 hb = __float2half_rn(v[i]);
        o[i] = *reinterpret_cast<unsigned short*>(&hb);
    }
    *(uint4*)w = *(const uint4*)o;
}

__device__ __forceinline__ void gridbar()
{
    __syncthreads();
    if (threadIdx.x == 0) {
        __threadfence();
        unsigned g = g_bar_gen;
        if (atomicAdd(&g_bar_cnt, 1u) == NBLK - 1) {
            g_bar_cnt = 0;
            __threadfence();
            g_bar_gen = g + 1;
        } else {
            while (g_bar_gen == g) { __nanosleep(32); }
        }
        __threadfence();
    }
    __syncthreads();
}

// ---------------- split/convert all weights ---------------------------------
__global__ __launch_bounds__(256) void split_all(
    const float* __restrict__ W2, const float* __restrict__ Wih,
    const float* __restrict__ Whh, const float* __restrict__ W3r)
{
    const size_t n1 = (size_t)H2 * H1 / 8, n2 = (size_t)G3 * H2 / 8;
    const size_t n3 = (size_t)G3 * HM / 8, n4 = (size_t)PEN * HM / 8;
    size_t c = (size_t)blockIdx.x * 256 + threadIdx.x;
    if (c < n1) split8(W2 + c * 8, g_W2hi + c * 8, g_W2lo + c * 8);
    else if (c < n1 + n2) { size_t j = c - n1; split8(Wih + j * 8, g_Wihhi + j * 8, g_Wihlo + j * 8); }
    else if (c < n1 + n2 + n3) {
        size_t j = c - n1 - n2;
        const size_t rpc = HM / 8;
        size_t row = j / rpc, wi = j % rpc;
        int gate = (int)(row >> 11), u = (int)(row & 2047);
        size_t drow = (size_t)(u >> 4) * 48 + (size_t)gate * 16 + (u & 15);
        cvt8H(Whh + j * 8, g_Whhf + (drow * rpc + wi) * 8);
    }
    else if (c < n1 + n2 + n3 + n4) { size_t j = c - n1 - n2 - n3; split8(W3r + j * 8, g_W3hi + j * 8, g_W3lo + j * 8); }
}

// ---------------- act1 FFMA (K=24) -> bf16 hi/lo ----------------------------
__global__ __launch_bounds__(256) void gemm_ffma_split(
    const float* __restrict__ A, const float* __restrict__ Bm,
    const float* __restrict__ bias)
{
    __shared__ float As[8][128], Bs[8][128];
    const int tid = threadIdx.x, tx = tid & 15, ty = tid >> 4;
    const int arow = tid >> 1, acol = (tid & 1) << 2;
    const float* Ap = A  + (size_t)(blockIdx.y * 128 + arow) * INF + acol;
    const float* Bp = Bm + (size_t)(blockIdx.x * 128 + arow) * INF + acol;
    float acc[8][8];
#pragma unroll
    for (int i = 0; i < 8; i++)
#pragma unroll
        for (int j = 0; j < 8; j++) acc[i][j] = 0.0f;
    for (int k0 = 0; k0 < INF; k0 += 8) {
        float4 a = *(const float4*)(Ap + k0);
        float4 b = *(const float4*)(Bp + k0);
        __syncthreads();
        As[acol][arow] = a.x; As[acol + 1][arow] = a.y; As[acol + 2][arow] = a.z; As[acol + 3][arow] = a.w;
        Bs[acol][arow] = b.x; Bs[acol + 1][arow] = b.y; Bs[acol + 2][arow] = b.z; Bs[acol + 3][arow] = b.w;
        __syncthreads();
#pragma unroll
        for (int k = 0; k < 8; k++) {
            float av[8], bv[8];
            *(float4*)av       = *(const float4*)&As[k][ty * 8];
            *(float4*)(av + 4) = *(const float4*)&As[k][ty * 8 + 4];
            *(float4*)bv       = *(const float4*)&Bs[k][tx * 8];
            *(float4*)(bv + 4) = *(const float4*)&Bs[k][tx * 8 + 4];
#pragma unroll
            for (int i = 0; i < 8; i++)
#pragma unroll
                for (int j = 0; j < 8; j++) acc[i][j] += av[i] * bv[j];
        }
    }
    const int crow = blockIdx.y * 128 + ty * 8, ccol = blockIdx.x * 128 + tx * 8;
#pragma unroll
    for (int i = 0; i < 8; i++) {
        __align__(16) unsigned short h8[8], l8[8];
#pragma unroll
        for (int j = 0; j < 8; j++)
            split1(fmaxf(acc[i][j] + bias[ccol + j], 0.0f), h8[j], l8[j]);
        *(uint4*)(g_a1hi + (size_t)(crow + i) * H1 + ccol) = *(const uint4*)h8;
        *(uint4*)(g_a1lo + (size_t)(crow + i) * H1 + ccol) = *(const uint4*)l8;
    }
}

// ---------------- bf16-split NT GEMM (proven) -------------------------------
#define RB   144
#define ASZ  18432
#define STG  73728
template<int OUTM, int RELU>
__global__ __launch_bounds__(256, 1) void gemm_tc(
    const bf16* __restrict__ Ahi, const bf16* __restrict__ Alo,
    const bf16* __restrict__ Bhi, const bf16* __restrict__ Blo,
    const float* __restrict__ bias,
    float* __restrict__ Cf, bf16* __restrict__ Chi, bf16* __restrict__ Clo,
    int N, int K)
{
    extern __shared__ char smraw[];
    const uint32_t sb = su32(smraw);
    const int tid = threadIdx.x, warp = tid >> 5, lane = tid & 31;
    const int wm = warp >> 2, wn = warp & 3, g = lane >> 2, tg = lane & 3;
    const int mBase = blockIdx.y * 128, nBase = blockIdx.x * 128;
    const int NT = K / 64;
    const int arow = (lane & 7) + ((lane >> 3) & 1) * 8, ach = lane >> 4;
    const int brow = (lane & 7) + ((lane >> 4) & 1) * 8, bch = (lane >> 3) & 1;

    float acc[4][4][4];
#pragma unroll
    for (int i = 0; i < 4; i++)
#pragma unroll
        for (int j = 0; j < 4; j++)
#pragma unroll
            for (int q = 0; q < 4; q++) acc[i][j][q] = 0.0f;

    auto load_stage = [&](int st, int k0) {
        uint32_t d0 = sb + st * STG;
#pragma unroll
        for (int q = 0; q < 4; q++) {
            int c = q * 256 + tid, row = c >> 3, ch = c & 7;
            size_t ka = (size_t)(mBase + row) * K + k0 + ch * 8;
            size_t kb = (size_t)(nBase + row) * K + k0 + ch * 8;
            uint32_t o = row * RB + ch * 16;
            cpa16(d0 + o,           Ahi + ka);
            cpa16(d0 + ASZ + o,     Alo + ka);
            cpa16(d0 + 2 * ASZ + o, Bhi + kb);
            cpa16(d0 + 3 * ASZ + o, Blo + kb);
        }
        cp_commit();
    };

    load_stage(0, 0);
    load_stage(1, 64);
    for (int kt = 0; kt < NT; kt++) {
        if (kt < NT - 1) cp_wait1(); else cp_wait0();
        __syncthreads();
        if (kt + 2 < NT) load_stage((kt + 2) % 3, (kt + 2) * 64);
        const uint32_t s0 = sb + (kt % 3) * STG;
#pragma unroll
        for (int kk = 0; kk < 4; kk++) {
            uint32_t ah[4][4], al[4][4];
#pragma unroll
            for (int i = 0; i < 4; i++) {
                uint32_t ad = s0 + (wm * 64 + i * 16 + arow) * RB + (kk * 2 + ach) * 16;
                ldsm4(ah[i], ad);
                ldsm4(al[i], ad + ASZ);
            }
#pragma unroll
            for (int j = 0; j < 2; j++) {
                uint32_t bh[4], bl[4];
                uint32_t bd = s0 + 2 * ASZ + (wn * 32 + j * 16 + brow) * RB + (kk * 2 + bch) * 16;
                ldsm4(bh, bd);
                ldsm4(bl, bd + ASZ);
#pragma unroll
                for (int i = 0; i < 4; i++) {
                    mma16816(acc[i][2 * j],     ah[i], bh);
                    mma16816(acc[i][2 * j],     ah[i], bl);
                    mma16816(acc[i][2 * j],     al[i], bh);
                    mma16816(acc[i][2 * j + 1], ah[i], bh + 2);
                    mma16816(acc[i][2 * j + 1], ah[i], bl + 2);
                    mma16816(acc[i][2 * j + 1], al[i], bh + 2);
                }
            }
        }
    }

#pragma unroll
    for (int i = 0; i < 4; i++) {
        const int row = mBase + wm * 64 + i * 16 + g;
#pragma unroll
        for (int j = 0; j < 4; j++) {
            const int col = nBase + wn * 32 + j * 8 + 2 * tg;
            const float b0 = bias[col], b1 = bias[col + 1];
            float v00 = acc[i][j][0] + b0, v01 = acc[i][j][1] + b1;
            float v10 = acc[i][j][2] + b0, v11 = acc[i][j][3] + b1;
            if (RELU) { v00 = fmaxf(v00, 0.f); v01 = fmaxf(v01, 0.f);
                        v10 = fmaxf(v10, 0.f); v11 = fmaxf(v11, 0.f); }
            if (OUTM == 0) {
                *(float2*)(Cf + (size_t)row * N + col)       = make_float2(v00, v01);
                *(float2*)(Cf + (size_t)(row + 8) * N + col) = make_float2(v10, v11);
            } else {
                unsigned short h0, l0, h1, l1;
                split1(v00, h0, l0); split1(v01, h1, l1);
                *(uint32_t*)(Chi + (size_t)row * N + col) = (uint32_t)h0 | ((uint32_t)h1 << 16);
                *(uint32_t*)(Clo + (size_t)row * N + col) = (uint32_t)l0 | ((uint32_t)l1 << 16);
                split1(v10, h0, l0); split1(v11, h1, l1);
                *(uint32_t*)(Chi + (size_t)(row + 8) * N + col) = (uint32_t)h0 | ((uint32_t)h1 << 16);
                *(uint32_t*)(Clo + (size_t)(row + 8) * N + col) = (uint32_t)l0 | ((uint32_t)l1 << 16);
            }
        }
    }
}

// ---------------- persistent GRU: fp16 W resident, fp16 single h ------------
// 128 blk x 192 thr; W 48x2048 fp16 resident; A (h fp16) K-tile 64, 3 stages.
#define WRB   4112
#define WBYT  (48 * WRB)            // 197376
#define GAR   144
#define GSTG  (64 * GAR)            // 9216
#define ACCP  52
__global__ __launch_bounds__(192, 1) void gru_persist(
    const float* __restrict__ b_hh, const int* __restrict__ labraw)
{
    extern __shared__ char smraw[];
    const uint32_t sb = su32(smraw);
    const uint32_t aBase = sb + WBYT;
    float* smacc = (float*)(smraw + WBYT);   // aliases A stages after K-loop
    const int tid = threadIdx.x, bid = blockIdx.x, warp = tid >> 5, lane = tid & 31;
    const int wm = warp / 3, wn = warp % 3, g = lane >> 2, tg = lane & 3;
    const int arow = (lane & 7) + ((lane >> 3) & 1) * 8, ach = lane >> 4;
    const int brow = (lane & 7) + ((lane >> 4) & 1) * 8, bch = (lane >> 3) & 1;
    const int gsz = NBLK * 192, gtid = bid * 192 + tid;
    const int u0 = bid * 16;

    // load resident W slice once (48 rows x 2048 fp16 = 256 16B-chunks/row)
    for (int c = tid; c < 48 * 256; c += 192) {
        int row = c >> 8, ch = c & 255;
        *(uint4*)(smraw + row * WRB + ch * 16) =
            *(const uint4*)(g_Whhf + (size_t)(bid * 48 + row) * HM + ch * 8);
    }
    for (int i = gtid; i < BB * HM; i += gsz) {
        g_hshi[i] = __float2bfloat16(0.0f);
        g_hslo[i] = __float2bfloat16(0.0f);
        g_hf[i]   = __float2half(0.0f);
    }
    if (bid == 0 && warp == 0) {
        unsigned oddmask = __ballot_sync(0xffffffff, labraw[2 * lane + 1] != 0);
        if (oddmask == 0) { g_labels[lane] = labraw[2 * lane]; g_labels[lane + 32] = labraw[2 * (lane + 32)]; }
        else              { g_labels[lane] = labraw[lane];     g_labels[lane + 32] = labraw[lane + 32]; }
    }
    gridbar();

    const int NT = HM / 64;   // 32 K-tiles of 64
    for (int t = 0; t < TT; t++) {
        const h16*  Ah_t = g_hf   + (size_t)t * BB * HM;
        const bf16* Hbh  = g_hshi + (size_t)t * BB * HM;
        const bf16* Hbl  = g_hslo + (size_t)t * BB * HM;

        float aH[2][2][4];
#pragma unroll
        for (int i = 0; i < 2; i++)
#pragma unroll
            for (int j = 0; j < 2; j++)
#pragma unroll
                for (int q = 0; q < 4; q++) aH[i][j][q] = 0.f;

        auto load_stage = [&](int st, int k0) {
            uint32_t d0 = aBase + st * GSTG;
            for (int c = tid; c < 512; c += 192) {
                int row = c >> 3, ch = c & 7;
                cpa16(d0 + row * GAR + ch * 16,
                      Ah_t + (size_t)row * HM + k0 + ch * 8);
            }
            cp_commit();
        };

        load_stage(0, 0);
        load_stage(1, 64);
        for (int kt = 0; kt < NT; kt++) {
            if (kt < NT - 1) cp_wait1(); else cp_wait0();
            __syncthreads();
            if (kt + 2 < NT) load_stage((kt + 2) % 3, (kt + 2) * 64);
            const uint32_t s0 = aBase + (kt % 3) * GSTG;
#pragma unroll
            for (int kk = 0; kk < 4; kk++) {
                uint32_t ah[2][4];
#pragma unroll
                for (int i = 0; i < 2; i++)
                    ldsm4(ah[i], s0 + (wm * 32 + i * 16 + arow) * GAR + (kk * 2 + ach) * 16);
                uint32_t bw[4];
                ldsm4(bw, sb + (wn * 16 + brow) * WRB + kt * 128 + kk * 32 + bch * 16);
#pragma unroll
                for (int i = 0; i < 2; i++) {
                    mmaf16(aH[i][0], ah[i], bw);
                    mmaf16(aH[i][1], ah[i], bw + 2);
                }
            }
        }
        __syncthreads();   // A stages drained; safe to alias smacc

        // acc -> smacc
#pragma unroll
        for (int i = 0; i < 2; i++) {
            const int row = wm * 32 + i * 16 + g;
#pragma unroll
            for (int j = 0; j < 2; j++) {
                const int col = wn * 16 + j * 8 + 2 * tg;
                smacc[row * ACCP + col]           = aH[i][j][0];
                smacc[row * ACCP + col + 1]       = aH[i][j][1];
                smacc[(row + 8) * ACCP + col]     = aH[i][j][2];
                smacc[(row + 8) * ACCP + col + 1] = aH[i][j][3];
            }
        }
        __syncthreads();

        // fused gates: 16 hidden units x 64 batches (hp from bf16 pair)
        {
            bf16* hbh = g_hshi + (size_t)(t + 1) * BB * HM;
            bf16* hbl = g_hslo + (size_t)(t + 1) * BB * HM;
            h16*  hfn = g_hf   + (size_t)(t + 1) * BB * HM;
            for (int idx = tid; idx < BB * 16; idx += 192) {
                const int b = idx >> 4, ul = idx & 15;
                const int u = u0 + ul;
                const float ar = smacc[b * ACCP + ul]      + b_hh[u];
                const float az = smacc[b * ACCP + 16 + ul] + b_hh[HM + u];
                const float an = smacc[b * ACCP + 32 + ul] + b_hh[2 * HM + u];
                const float* xrow = g_xg + (size_t)(b * TT + t) * G3;
                const float r  = 1.0f / (1.0f + expf(-(xrow[u] + ar)));
                const float z  = 1.0f / (1.0f + expf(-(xrow[HM + u] + az)));
                const float nn = tanhf(xrow[2 * HM + u] + r * an);
                const float hp = __bfloat162float(Hbh[(size_t)b * HM + u])
                               + __bfloat162float(Hbl[(size_t)b * HM + u]);
                const float h  = (1.0f - z) * nn + z * hp;
                unsigned short s0w, s1w;
                split1(h, s0w, s1w);
                hbh[(size_t)b * HM + u] = *reinterpret_cast<bf16*>(&s0w);
                hbl[(size_t)b * HM + u] = *reinterpret_cast<bf16*>(&s1w);
                hfn[(size_t)b * HM + u] = __float2half_rn(h);
            }
        }
        gridbar();
    }
}

// ---------------- heads + zero ----------------------------------------------
__global__ __launch_bounds__(128) void heads_kernel(
    const float* __restrict__ W4, const float* __restrict__ b4,
    const float* __restrict__ W5, const float* __restrict__ b5,
    const float* __restrict__ W6, const float* __restrict__ b6,
    float* __restrict__ out)
{
    const int r = blockIdx.x, t = r >> 6, b = r & 63;
    const int lab = g_labels[b];
    const float* s  = g_outs + (size_t)r * PEN;
    const float* w4 = W4 + (size_t)lab * PEN;
    const float* w5 = W5 + (size_t)lab * PEN;
    const float* w6 = W6 + (size_t)lab * PEN;
    float a4 = 0.f, a5 = 0.f, a6 = 0.f;
    for (int p = threadIdx.x; p < PEN; p += 128) {
        const float v = s[p];
        a4 += v * w4[p]; a5 += v * w5[p]; a6 += v * w6[p];
    }
    __shared__ float red[3][128];
    red[0][threadIdx.x] = a4; red[1][threadIdx.x] = a5; red[2][threadIdx.x] = a6;
    __syncthreads();
    for (int s2 = 64; s2 > 0; s2 >>= 1) {
        if (threadIdx.x < s2) {
            red[0][threadIdx.x] += red[0][threadIdx.x + s2];
            red[1][threadIdx.x] += red[1][threadIdx.x + s2];
            red[2][threadIdx.x] += red[2][threadIdx.x + s2];
        }
        __syncthreads();
    }
    if (threadIdx.x == 0) {
        const int o = b * TT + t;
        out[o]          = red[0][0] + b4[lab];
        out[BT + o]     = red[1][0] + b5[lab];
        out[2 * BT + o] = red[2][0] + b6[lab];
    }
}

__global__ void zero_kernel(float* p, int n)
{
    int i = blockIdx.x * blockDim.x + threadIdx.x;
    if (i < n) p[i] = 0.0f;
}

// ---------------- launch ----------------------------------------------------
extern "C" void kernel_launch(void* const* d_in, const int* in_sizes, int n_in,
                              void* d_out, int out_size)
{
    const float* x    = (const float*)d_in[0];
    const int*   labr = (const int*)d_in[1];
    const float* W1   = (const float*)d_in[2];
    const float* b1   = (const float*)d_in[3];
    const float* W2   = (const float*)d_in[4];
    const float* b2   = (const float*)d_in[5];
    const float* W_ih = (const float*)d_in[6];
    const float* W_hh = (const float*)d_in[7];
    const float* b_ih = (const float*)d_in[8];
    const float* b_hh = (const float*)d_in[9];
    const float* W3   = (const float*)d_in[10];
    const float* b3   = (const float*)d_in[11];
    const float* W4   = (const float*)d_in[12];
    const float* b4   = (const float*)d_in[13];
    const float* W5   = (const float*)d_in[14];
    const float* b5   = (const float*)d_in[15];
    const float* W6   = (const float*)d_in[16];
    const float* b6   = (const float*)d_in[17];
    float* out = (float*)d_out;

    bf16 *a1hi, *a1lo, *a2hi, *a2lo, *hshi, *hslo, *w2hi, *w2lo, *wihhi, *wihlo, *w3hi, *w3lo;
    float *xg, *outs;
    cudaGetSymbolAddress((void**)&a1hi, g_a1hi);
    cudaGetSymbolAddress((void**)&a1lo, g_a1lo);
    cudaGetSymbolAddress((void**)&a2hi, g_a2hi);
    cudaGetSymbolAddress((void**)&a2lo, g_a2lo);
    cudaGetSymbolAddress((void**)&hshi, g_hshi);
    cudaGetSymbolAddress((void**)&hslo, g_hslo);
    cudaGetSymbolAddress((void**)&w2hi, g_W2hi);
    cudaGetSymbolAddress((void**)&w2lo, g_W2lo);
    cudaGetSymbolAddress((void**)&wihhi, g_Wihhi);
    cudaGetSymbolAddress((void**)&wihlo, g_Wihlo);
    cudaGetSymbolAddress((void**)&w3hi, g_W3hi);
    cudaGetSymbolAddress((void**)&w3lo, g_W3lo);
    cudaGetSymbolAddress((void**)&xg,   g_xg);
    cudaGetSymbolAddress((void**)&outs, g_outs);

    const int GEMM_SMEM = 3 * STG;              // 221184
    const int GRU_SMEM  = WBYT + 3 * GSTG;      // 225024
    cudaFuncSetAttribute(gemm_tc<0, 0>, cudaFuncAttributeMaxDynamicSharedMemorySize, GEMM_SMEM);
    cudaFuncSetAttribute(gemm_tc<0, 1>, cudaFuncAttributeMaxDynamicSharedMemorySize, GEMM_SMEM);
    cudaFuncSetAttribute(gemm_tc<1, 1>, cudaFuncAttributeMaxDynamicSharedMemorySize, GEMM_SMEM);
    cudaFuncSetAttribute(gru_persist, cudaFuncAttributeMaxDynamicSharedMemorySize, GRU_SMEM);

    // 0) zero output tail
    const int tail = out_size - 3 * BT;
    zero_kernel<<<(((tail > 0 ? tail : 1) + 255) / 256), 256>>>(out + 3 * BT, tail > 0 ? tail : 0);
    // 1) act1 -> bf16 hi/lo
    {
        dim3 g(H1 / 128, BT / 128);
        gemm_ffma_split<<<g, 256>>>(x, W1, b1);
    }
    // 2) split/convert weights (Whh -> fp16 gate-permuted)
    {
        size_t chunks = (size_t)H2 * H1 / 8 + (size_t)G3 * H2 / 8 + (size_t)G3 * HM / 8 + (size_t)PEN * HM / 8;
        split_all<<<(unsigned)((chunks + 255) / 256), 256>>>(W2, W_ih, W_hh, W3);
    }
    // 3) act2 -> bf16 hi/lo
    {
        dim3 g(H2 / 128, BT / 128);
        gemm_tc<1, 1><<<g, 256, GEMM_SMEM>>>(a1hi, a1lo, w2hi, w2lo, b2,
                                             nullptr, a2hi, a2lo, H2, H1);
    }
    // 4) xg -> f32
    {
        dim3 g(G3 / 128, BT / 128);
        gemm_tc<0, 0><<<g, 256, GEMM_SMEM>>>(a2hi, a2lo, wihhi, wihlo, b_ih,
                                             xg, nullptr, nullptr, G3, H2);
    }
    // 5) persistent GRU (profiled)
    gru_persist<<<NBLK, 192, GRU_SMEM>>>(b_hh, labr);
    // 6) out_s = relu(h @ W3^T + b3)
    {
        dim3 g(PEN / 128, BT / 128);
        gemm_tc<0, 1><<<g, 256, GEMM_SMEM>>>(hshi + (size_t)BB * HM, hslo + (size_t)BB * HM,
                                             w3hi, w3lo, b3, outs, nullptr, nullptr, PEN, HM);
    }
    // 7) heads
    heads_kernel<<<BT, 128>>>(W4, b4, W5, b5, W6, b6, out);
}

// round 15
// speedup vs baseline: 4.1618x; 1.4366x over previous
#include <cuda_runtime.h>
#include <cuda_fp16.h>
#include <math.h>
#include <stdint.h>

#define BB 64
#define TT 366
#define INF 24
#define H1 1024
#define H2 2048
#define HM 2048
#define PEN 1024
#define BT 23424
#define G3 6144
#define NBLK 128
typedef __half h16;

// ---------------- scratch ---------------------------------------------------
__device__ h16   g_a1hi[(size_t)BT * H1];
__device__ h16   g_a1lo[(size_t)BT * H1];
__device__ h16   g_a2hi[(size_t)BT * H2];
__device__ h16   g_a2lo[(size_t)BT * H2];
__device__ float g_xg  [(size_t)BT * G3];
__device__ h16   g_hfhi[(size_t)(TT + 1) * BB * HM];   // fp16 h hi (GRU A + W3 GEMM)
__device__ h16   g_hflo[(size_t)(TT + 1) * BB * HM];   // fp16 h lo (carry + W3 GEMM)
__device__ float g_outs[(size_t)BT * PEN];
__device__ h16   g_W2f [(size_t)H2 * H1];
__device__ h16   g_Wihf[(size_t)G3 * H2];
__device__ h16   g_Whhf[(size_t)G3 * HM];              // fp16, gate-permuted rows
__device__ h16   g_W3f [(size_t)PEN * HM];
__device__ int      g_labels[BB];
__device__ unsigned g_bar_cnt = 0;
__device__ volatile unsigned g_bar_gen = 0;

// ---------------- asm helpers ----------------------------------------------
__device__ __forceinline__ uint32_t su32(const void* p) {
    uint32_t a;
    asm("{ .reg .u64 t; cvta.to.shared.u64 t, %1; cvt.u32.u64 %0, t; }" : "=r"(a) : "l"(p));
    return a;
}
__device__ __forceinline__ void mmaf16(float* d, const uint32_t* a, const uint32_t* b) {
    asm volatile(
        "mma.sync.aligned.m16n8k16.row.col.f32.f16.f16.f32 "
        "{%0,%1,%2,%3},{%4,%5,%6,%7},{%8,%9},{%0,%1,%2,%3};"
        : "+f"(d[0]), "+f"(d[1]), "+f"(d[2]), "+f"(d[3])
        : "r"(a[0]), "r"(a[1]), "r"(a[2]), "r"(a[3]), "r"(b[0]), "r"(b[1]));
}
__device__ __forceinline__ void ldsm4(uint32_t* r, uint32_t a) {
    asm volatile("ldmatrix.sync.aligned.m8n8.x4.shared.b16 {%0,%1,%2,%3},[%4];"
                 : "=r"(r[0]), "=r"(r[1]), "=r"(r[2]), "=r"(r[3]) : "r"(a));
}
__device__ __forceinline__ void cpa16(uint32_t d, const void* s) {
    asm volatile("cp.async.cg.shared.global [%0],[%1],16;" :: "r"(d), "l"(s));
}
__device__ __forceinline__ void cp_commit() { asm volatile("cp.async.commit_group;"); }
__device__ __forceinline__ void cp_wait1()  { asm volatile("cp.async.wait_group 1;"); }
__device__ __forceinline__ void cp_wait0()  { asm volatile("cp.async.wait_group 0;"); }

__device__ __forceinline__ void splitH(float v, unsigned short& h, unsigned short& l) {
    h16 hb = __float2half_rn(v);
    h = *reinterpret_cast<unsigned short*>(&hb);
    h16 lb = __float2half_rn(v - __half2float(hb));
    l = *reinterpret_cast<unsigned short*>(&lb);
}
__device__ __forceinline__ void cvt8H(const float* s, h16* w) {
    float4 a = *(const float4*)s, b = *(const float4*)(s + 4);
    float v[8] = {a.x, a.y, a.z, a.w, b.x, b.y, b.z, b.w};
    __align__(16) unsigned short o[8];
#pragma unroll
    for (int i = 0; i < 8; i++) {
        h16 hb = __float2half_rn(v[i]);
        o[i] = *reinterpret_cast<unsigned short*>(&hb);
    }
    *(uint4*)w = *(const uint4*)o;
}

__device__ __forceinline__ void gridbar()
{
    __syncthreads();
    if (threadIdx.x == 0) {
        __threadfence();
        unsigned g = g_bar_gen;
        if (atomicAdd(&g_bar_cnt, 1u) == NBLK - 1) {
            g_bar_cnt = 0;
            __threadfence();
            g_bar_gen = g + 1;
        } else {
            while (g_bar_gen == g) { __nanosleep(32); }
        }
        __threadfence();
    }
    __syncthreads();
}

// ---------------- convert all weights to fp16 -------------------------------
__global__ __launch_bounds__(256) void split_all(
    const float* __restrict__ W2, const float* __restrict__ Wih,
    const float* __restrict__ Whh, const float* __restrict__ W3r)
{
    const size_t n1 = (size_t)H2 * H1 / 8, n2 = (size_t)G3 * H2 / 8;
    const size_t n3 = (size_t)G3 * HM / 8, n4 = (size_t)PEN * HM / 8;
    size_t c = (size_t)blockIdx.x * 256 + threadIdx.x;
    if (c < n1) cvt8H(W2 + c * 8, g_W2f + c * 8);
    else if (c < n1 + n2) { size_t j = c - n1; cvt8H(Wih + j * 8, g_Wihf + j * 8); }
    else if (c < n1 + n2 + n3) {
        size_t j = c - n1 - n2;
        const size_t rpc = HM / 8;
        size_t row = j / rpc, wi = j % rpc;
        int gate = (int)(row >> 11), u = (int)(row & 2047);
        size_t drow = (size_t)(u >> 4) * 48 + (size_t)gate * 16 + (u & 15);
        cvt8H(Whh + j * 8, g_Whhf + (drow * rpc + wi) * 8);
    }
    else if (c < n1 + n2 + n3 + n4) { size_t j = c - n1 - n2 - n3; cvt8H(W3r + j * 8, g_W3f + j * 8); }
}

// ---------------- act1 FFMA (K=24) -> fp16 hi/lo ----------------------------
__global__ __launch_bounds__(256) void gemm_ffma_split(
    const float* __restrict__ A, const float* __restrict__ Bm,
    const float* __restrict__ bias)
{
    __shared__ float As[8][128], Bs[8][128];
    const int tid = threadIdx.x, tx = tid & 15, ty = tid >> 4;
    const int arow = tid >> 1, acol = (tid & 1) << 2;
    const float* Ap = A  + (size_t)(blockIdx.y * 128 + arow) * INF + acol;
    const float* Bp = Bm + (size_t)(blockIdx.x * 128 + arow) * INF + acol;
    float acc[8][8];
#pragma unroll
    for (int i = 0; i < 8; i++)
#pragma unroll
        for (int j = 0; j < 8; j++) acc[i][j] = 0.0f;
    for (int k0 = 0; k0 < INF; k0 += 8) {
        float4 a = *(const float4*)(Ap + k0);
        float4 b = *(const float4*)(Bp + k0);
        __syncthreads();
        As[acol][arow] = a.x; As[acol + 1][arow] = a.y; As[acol + 2][arow] = a.z; As[acol + 3][arow] = a.w;
        Bs[acol][arow] = b.x; Bs[acol + 1][arow] = b.y; Bs[acol + 2][arow] = b.z; Bs[acol + 3][arow] = b.w;
        __syncthreads();
#pragma unroll
        for (int k = 0; k < 8; k++) {
            float av[8], bv[8];
            *(float4*)av       = *(const float4*)&As[k][ty * 8];
            *(float4*)(av + 4) = *(const float4*)&As[k][ty * 8 + 4];
            *(float4*)bv       = *(const float4*)&Bs[k][tx * 8];
            *(float4*)(bv + 4) = *(const float4*)&Bs[k][tx * 8 + 4];
#pragma unroll
            for (int i = 0; i < 8; i++)
#pragma unroll
                for (int j = 0; j < 8; j++) acc[i][j] += av[i] * bv[j];
        }
    }
    const int crow = blockIdx.y * 128 + ty * 8, ccol = blockIdx.x * 128 + tx * 8;
#pragma unroll
    for (int i = 0; i < 8; i++) {
        __align__(16) unsigned short h8[8], l8[8];
#pragma unroll
        for (int j = 0; j < 8; j++)
            splitH(fmaxf(acc[i][j] + bias[ccol + j], 0.0f), h8[j], l8[j]);
        *(uint4*)(g_a1hi + (size_t)(crow + i) * H1 + ccol) = *(const uint4*)h8;
        *(uint4*)(g_a1lo + (size_t)(crow + i) * H1 + ccol) = *(const uint4*)l8;
    }
}

// ---------------- fp16 2-term NT GEMM (128x128, K-tile 64, 3-stage) ---------
#define RB   144
#define ASZ  18432
#define STG  55296
template<int OUTM, int RELU>
__global__ __launch_bounds__(256, 1) void gemm_tc(
    const h16* __restrict__ Ahi, const h16* __restrict__ Alo,
    const h16* __restrict__ Bw, const float* __restrict__ bias,
    float* __restrict__ Cf, h16* __restrict__ Chi, h16* __restrict__ Clo,
    int N, int K)
{
    extern __shared__ char smraw[];
    const uint32_t sb = su32(smraw);
    const int tid = threadIdx.x, warp = tid >> 5, lane = tid & 31;
    const int wm = warp >> 2, wn = warp & 3, g = lane >> 2, tg = lane & 3;
    const int mBase = blockIdx.y * 128, nBase = blockIdx.x * 128;
    const int NT = K / 64;
    const int arow = (lane & 7) + ((lane >> 3) & 1) * 8, ach = lane >> 4;
    const int brow = (lane & 7) + ((lane >> 4) & 1) * 8, bch = (lane >> 3) & 1;

    float acc[4][4][4];
#pragma unroll
    for (int i = 0; i < 4; i++)
#pragma unroll
        for (int j = 0; j < 4; j++)
#pragma unroll
            for (int q = 0; q < 4; q++) acc[i][j][q] = 0.0f;

    auto load_stage = [&](int st, int k0) {
        uint32_t d0 = sb + st * STG;
#pragma unroll
        for (int q = 0; q < 4; q++) {
            int c = q * 256 + tid, row = c >> 3, ch = c & 7;   // 1024 chunks: all 128 rows
            size_t ka = (size_t)(mBase + row) * K + k0 + ch * 8;
            size_t kb = (size_t)(nBase + row) * K + k0 + ch * 8;
            uint32_t o = row * RB + ch * 16;
            cpa16(d0 + o,           Ahi + ka);
            cpa16(d0 + ASZ + o,     Alo + ka);
            cpa16(d0 + 2 * ASZ + o, Bw + kb);
        }
        cp_commit();
    };

    load_stage(0, 0);
    load_stage(1, 64);
    for (int kt = 0; kt < NT; kt++) {
        if (kt < NT - 1) cp_wait1(); else cp_wait0();
        __syncthreads();
        if (kt + 2 < NT) load_stage((kt + 2) % 3, (kt + 2) * 64);
        const uint32_t s0 = sb + (kt % 3) * STG;
#pragma unroll
        for (int kk = 0; kk < 4; kk++) {
            uint32_t ah[4][4], al[4][4];
#pragma unroll
            for (int i = 0; i < 4; i++) {
                uint32_t ad = s0 + (wm * 64 + i * 16 + arow) * RB + (kk * 2 + ach) * 16;
                ldsm4(ah[i], ad);
                ldsm4(al[i], ad + ASZ);
            }
#pragma unroll
            for (int j = 0; j < 2; j++) {
                uint32_t bw[4];
                ldsm4(bw, s0 + 2 * ASZ + (wn * 32 + j * 16 + brow) * RB + (kk * 2 + bch) * 16);
#pragma unroll
                for (int i = 0; i < 4; i++) {
                    mmaf16(acc[i][2 * j],     ah[i], bw);
                    mmaf16(acc[i][2 * j],     al[i], bw);
                    mmaf16(acc[i][2 * j + 1], ah[i], bw + 2);
                    mmaf16(acc[i][2 * j + 1], al[i], bw + 2);
                }
            }
        }
    }

#pragma unroll
    for (int i = 0; i < 4; i++) {
        const int row = mBase + wm * 64 + i * 16 + g;
#pragma unroll
        for (int j = 0; j < 4; j++) {
            const int col = nBase + wn * 32 + j * 8 + 2 * tg;
            const float b0 = bias[col], b1 = bias[col + 1];
            float v00 = acc[i][j][0] + b0, v01 = acc[i][j][1] + b1;
            float v10 = acc[i][j][2] + b0, v11 = acc[i][j][3] + b1;
            if (RELU) { v00 = fmaxf(v00, 0.f); v01 = fmaxf(v01, 0.f);
                        v10 = fmaxf(v10, 0.f); v11 = fmaxf(v11, 0.f); }
            if (OUTM == 0) {
                *(float2*)(Cf + (size_t)row * N + col)       = make_float2(v00, v01);
                *(float2*)(Cf + (size_t)(row + 8) * N + col) = make_float2(v10, v11);
            } else {
                unsigned short h0, l0, h1, l1;
                splitH(v00, h0, l0); splitH(v01, h1, l1);
                *(uint32_t*)(Chi + (size_t)row * N + col) = (uint32_t)h0 | ((uint32_t)h1 << 16);
                *(uint32_t*)(Clo + (size_t)row * N + col) = (uint32_t)l0 | ((uint32_t)l1 << 16);
                splitH(v10, h0, l0); splitH(v11, h1, l1);
                *(uint32_t*)(Chi + (size_t)(row + 8) * N + col) = (uint32_t)h0 | ((uint32_t)h1 << 16);
                *(uint32_t*)(Clo + (size_t)(row + 8) * N + col) = (uint32_t)l0 | ((uint32_t)l1 << 16);
            }
        }
    }
}

// ---------------- persistent GRU: W resident, 3-stage A, reg x-prefetch -----
#define WRB   4112
#define WBYT  (48 * WRB)            // 197376
#define GAR   144
#define GSTG  (64 * GAR)            // 9216
#define ACCP  52
__global__ __launch_bounds__(192, 1) void gru_persist(
    const float* __restrict__ b_hh, const int* __restrict__ labraw)
{
    extern __shared__ char smraw[];
    const uint32_t sb = su32(smraw);
    const uint32_t aBase = sb + WBYT;
    float* smacc = (float*)(smraw + WBYT);   // aliases A stages after K-loop
    const int tid = threadIdx.x, bid = blockIdx.x, warp = tid >> 5, lane = tid & 31;
    const int wm = warp / 3, wn = warp % 3, g = lane >> 2, tg = lane & 3;
    const int arow = (lane & 7) + ((lane >> 3) & 1) * 8, ach = lane >> 4;
    const int brow = (lane & 7) + ((lane >> 4) & 1) * 8, bch = (lane >> 3) & 1;
    const int gsz = NBLK * 192, gtid = bid * 192 + tid;
    const int u0 = bid * 16;

    // load resident W slice once
    for (int c = tid; c < 48 * 256; c += 192) {
        int row = c >> 8, ch = c & 255;
        *(uint4*)(smraw + row * WRB + ch * 16) =
            *(const uint4*)(g_Whhf + (size_t)(bid * 48 + row) * HM + ch * 8);
    }
    for (int i = gtid; i < BB * HM; i += gsz) {
        g_hfhi[i] = __float2half(0.0f);
        g_hflo[i] = __float2half(0.0f);
    }
    if (bid == 0 && warp == 0) {
        unsigned oddmask = __ballot_sync(0xffffffff, labraw[2 * lane + 1] != 0);
        if (oddmask == 0) { g_labels[lane] = labraw[2 * lane]; g_labels[lane + 32] = labraw[2 * (lane + 32)]; }
        else              { g_labels[lane] = labraw[lane];     g_labels[lane + 32] = labraw[lane + 32]; }
    }
    gridbar();

    const int NT = HM / 64;   // 32 K-tiles of 64
    for (int t = 0; t < TT; t++) {
        const h16* Ah_t = g_hfhi + (size_t)t * BB * HM;
        const h16* Al_t = g_hflo + (size_t)t * BB * HM;

        // register prefetch of gate-x for this step (hidden under K-loop)
        float xr_r[6], xz_r[6], xn_r[6];
#pragma unroll
        for (int q = 0; q < 6; q++) {
            const int idx = tid + q * 192;
            if (idx < BB * 16) {
                const int b = idx >> 4, u = u0 + (idx & 15);
                const float* xrow = g_xg + (size_t)(b * TT + t) * G3;
                xr_r[q] = __ldg(xrow + u);
                xz_r[q] = __ldg(xrow + HM + u);
                xn_r[q] = __ldg(xrow + 2 * HM + u);
            } else { xr_r[q] = xz_r[q] = xn_r[q] = 0.f; }
        }

        float aH[2][2][4];
#pragma unroll
        for (int i = 0; i < 2; i++)
#pragma unroll
            for (int j = 0; j < 2; j++)
#pragma unroll
                for (int q = 0; q < 4; q++) aH[i][j][q] = 0.f;

        auto load_stage = [&](int st, int k0) {
            uint32_t d0 = aBase + st * GSTG;
            for (int c = tid; c < 512; c += 192) {
                int row = c >> 3, ch = c & 7;
                cpa16(d0 + row * GAR + ch * 16,
                      Ah_t + (size_t)row * HM + k0 + ch * 8);
            }
            cp_commit();
        };

        load_stage(0, 0);
        load_stage(1, 64);
        for (int kt = 0; kt < NT; kt++) {
            if (kt < NT - 1) cp_wait1(); else cp_wait0();
            __syncthreads();
            if (kt + 2 < NT) load_stage((kt + 2) % 3, (kt + 2) * 64);
            const uint32_t s0 = aBase + (kt % 3) * GSTG;
#pragma unroll
            for (int kk = 0; kk < 4; kk++) {
                uint32_t ah[2][4];
#pragma unroll
                for (int i = 0; i < 2; i++)
                    ldsm4(ah[i], s0 + (wm * 32 + i * 16 + arow) * GAR + (kk * 2 + ach) * 16);
                uint32_t bw[4];
                ldsm4(bw, sb + (wn * 16 + brow) * WRB + kt * 128 + kk * 32 + bch * 16);
#pragma unroll
                for (int i = 0; i < 2; i++) {
                    mmaf16(aH[i][0], ah[i], bw);
                    mmaf16(aH[i][1], ah[i], bw + 2);
                }
            }
        }
        __syncthreads();   // A stages drained; safe to alias smacc

        // acc -> smacc
#pragma unroll
        for (int i = 0; i < 2; i++) {
            const int row = wm * 32 + i * 16 + g;
#pragma unroll
            for (int j = 0; j < 2; j++) {
                const int col = wn * 16 + j * 8 + 2 * tg;
                smacc[row * ACCP + col]           = aH[i][j][0];
                smacc[row * ACCP + col + 1]       = aH[i][j][1];
                smacc[(row + 8) * ACCP + col]     = aH[i][j][2];
                smacc[(row + 8) * ACCP + col + 1] = aH[i][j][3];
            }
        }
        __syncthreads();

        // fused gates (x from registers; hp from fp16 pair)
        {
            h16* hhn = g_hfhi + (size_t)(t + 1) * BB * HM;
            h16* hln = g_hflo + (size_t)(t + 1) * BB * HM;
#pragma unroll
            for (int q = 0; q < 6; q++) {
                const int idx = tid + q * 192;
                if (idx < BB * 16) {
                    const int b = idx >> 4, ul = idx & 15;
                    const int u = u0 + ul;
                    const float ar = smacc[b * ACCP + ul]      + b_hh[u];
                    const float az = smacc[b * ACCP + 16 + ul] + b_hh[HM + u];
                    const float an = smacc[b * ACCP + 32 + ul] + b_hh[2 * HM + u];
                    const float r  = 1.0f / (1.0f + expf(-(xr_r[q] + ar)));
                    const float z  = 1.0f / (1.0f + expf(-(xz_r[q] + az)));
                    const float nn = tanhf(xn_r[q] + r * an);
                    const float hp = __half2float(Ah_t[(size_t)b * HM + u])
                                   + __half2float(Al_t[(size_t)b * HM + u]);
                    const float h  = (1.0f - z) * nn + z * hp;
                    unsigned short s0w, s1w;
                    splitH(h, s0w, s1w);
                    hhn[(size_t)b * HM + u] = *reinterpret_cast<h16*>(&s0w);
                    hln[(size_t)b * HM + u] = *reinterpret_cast<h16*>(&s1w);
                }
            }
        }
        gridbar();
    }
}

// ---------------- heads + zero ----------------------------------------------
__global__ __launch_bounds__(128) void heads_kernel(
    const float* __restrict__ W4, const float* __restrict__ b4,
    const float* __restrict__ W5, const float* __restrict__ b5,
    const float* __restrict__ W6, const float* __restrict__ b6,
    float* __restrict__ out)
{
    const int r = blockIdx.x, t = r >> 6, b = r & 63;
    const int lab = g_labels[b];
    const float* s  = g_outs + (size_t)r * PEN;
    const float* w4 = W4 + (size_t)lab * PEN;
    const float* w5 = W5 + (size_t)lab * PEN;
    const float* w6 = W6 + (size_t)lab * PEN;
    float a4 = 0.f, a5 = 0.f, a6 = 0.f;
    for (int p = threadIdx.x; p < PEN; p += 128) {
        const float v = s[p];
        a4 += v * w4[p]; a5 += v * w5[p]; a6 += v * w6[p];
    }
    __shared__ float red[3][128];
    red[0][threadIdx.x] = a4; red[1][threadIdx.x] = a5; red[2][threadIdx.x] = a6;
    __syncthreads();
    for (int s2 = 64; s2 > 0; s2 >>= 1) {
        if (threadIdx.x < s2) {
            red[0][threadIdx.x] += red[0][threadIdx.x + s2];
            red[1][threadIdx.x] += red[1][threadIdx.x + s2];
            red[2][threadIdx.x] += red[2][threadIdx.x + s2];
        }
        __syncthreads();
    }
    if (threadIdx.x == 0) {
        const int o = b * TT + t;
        out[o]          = red[0][0] + b4[lab];
        out[BT + o]     = red[1][0] + b5[lab];
        out[2 * BT + o] = red[2][0] + b6[lab];
    }
}

__global__ void zero_kernel(float* p, int n)
{
    int i = blockIdx.x * blockDim.x + threadIdx.x;
    if (i < n) p[i] = 0.0f;
}

// ---------------- launch ----------------------------------------------------
extern "C" void kernel_launch(void* const* d_in, const int* in_sizes, int n_in,
                              void* d_out, int out_size)
{
    const float* x    = (const float*)d_in[0];
    const int*   labr = (const int*)d_in[1];
    const float* W1   = (const float*)d_in[2];
    const float* b1   = (const float*)d_in[3];
    const float* W2   = (const float*)d_in[4];
    const float* b2   = (const float*)d_in[5];
    const float* W_ih = (const float*)d_in[6];
    const float* W_hh = (const float*)d_in[7];
    const float* b_ih = (const float*)d_in[8];
    const float* b_hh = (const float*)d_in[9];
    const float* W3   = (const float*)d_in[10];
    const float* b3   = (const float*)d_in[11];
    const float* W4   = (const float*)d_in[12];
    const float* b4   = (const float*)d_in[13];
    const float* W5   = (const float*)d_in[14];
    const float* b5   = (const float*)d_in[15];
    const float* W6   = (const float*)d_in[16];
    const float* b6   = (const float*)d_in[17];
    float* out = (float*)d_out;

    h16 *a1hi, *a1lo, *a2hi, *a2lo, *hfhi, *hflo, *w2f, *wihf, *w3f;
    float *xg, *outs;
    cudaGetSymbolAddress((void**)&a1hi, g_a1hi);
    cudaGetSymbolAddress((void**)&a1lo, g_a1lo);
    cudaGetSymbolAddress((void**)&a2hi, g_a2hi);
    cudaGetSymbolAddress((void**)&a2lo, g_a2lo);
    cudaGetSymbolAddress((void**)&hfhi, g_hfhi);
    cudaGetSymbolAddress((void**)&hflo, g_hflo);
    cudaGetSymbolAddress((void**)&w2f,  g_W2f);
    cudaGetSymbolAddress((void**)&wihf, g_Wihf);
    cudaGetSymbolAddress((void**)&w3f,  g_W3f);
    cudaGetSymbolAddress((void**)&xg,   g_xg);
    cudaGetSymbolAddress((void**)&outs, g_outs);

    const int GEMM_SMEM = 3 * STG;              // 165888
    const int GRU_SMEM  = WBYT + 3 * GSTG;      // 225024
    cudaFuncSetAttribute(gemm_tc<0, 0>, cudaFuncAttributeMaxDynamicSharedMemorySize, GEMM_SMEM);
    cudaFuncSetAttribute(gemm_tc<0, 1>, cudaFuncAttributeMaxDynamicSharedMemorySize, GEMM_SMEM);
    cudaFuncSetAttribute(gemm_tc<1, 1>, cudaFuncAttributeMaxDynamicSharedMemorySize, GEMM_SMEM);
    cudaFuncSetAttribute(gru_persist, cudaFuncAttributeMaxDynamicSharedMemorySize, GRU_SMEM);

    // 0) zero output tail
    const int tail = out_size - 3 * BT;
    zero_kernel<<<(((tail > 0 ? tail : 1) + 255) / 256), 256>>>(out + 3 * BT, tail > 0 ? tail : 0);
    // 1) act1 -> fp16 hi/lo
    {
        dim3 g(H1 / 128, BT / 128);
        gemm_ffma_split<<<g, 256>>>(x, W1, b1);
    }
    // 2) convert weights to fp16 (Whh gate-permuted)
    {
        size_t chunks = (size_t)H2 * H1 / 8 + (size_t)G3 * H2 / 8 + (size_t)G3 * HM / 8 + (size_t)PEN * HM / 8;
        split_all<<<(unsigned)((chunks + 255) / 256), 256>>>(W2, W_ih, W_hh, W3);
    }
    // 3) act2 -> fp16 hi/lo
    {
        dim3 g(H2 / 128, BT / 128);
        gemm_tc<1, 1><<<g, 256, GEMM_SMEM>>>(a1hi, a1lo, w2f, b2,
                                             nullptr, a2hi, a2lo, H2, H1);
    }
    // 4) xg -> f32
    {
        dim3 g(G3 / 128, BT / 128);
        gemm_tc<0, 0><<<g, 256, GEMM_SMEM>>>(a2hi, a2lo, wihf, b_ih,
                                             xg, nullptr, nullptr, G3, H2);
    }
    // 5) persistent GRU (profiled)
    gru_persist<<<NBLK, 192, GRU_SMEM>>>(b_hh, labr);
    // 6) out_s = relu(h @ W3^T + b3)
    {
        dim3 g(PEN / 128, BT / 128);
        gemm_tc<0, 1><<<g, 256, GEMM_SMEM>>>(hfhi + (size_t)BB * HM, hflo + (size_t)BB * HM,
                                             w3f, b3, outs, nullptr, nullptr, PEN, HM);
    }
    // 7) heads
    heads_kernel<<<BT, 128>>>(W4, b4, W5, b5, W6, b6, out);
}

// round 16
// speedup vs baseline: 4.9779x; 1.1961x over previous
#include <cuda_runtime.h>
#include <cuda_fp16.h>
#include <math.h>
#include <stdint.h>

#define BB 64
#define TT 366
#define INF 24
#define H1 1024
#define H2 2048
#define HM 2048
#define PEN 1024
#define BT 23424
#define G3 6144
#define NBLK 128
typedef __half h16;

// ---------------- scratch ---------------------------------------------------
__device__ h16   g_a1hi[(size_t)BT * H1];
__device__ h16   g_a1lo[(size_t)BT * H1];
__device__ h16   g_a2f [(size_t)BT * H2];              // fp16 single (xg input)
__device__ float g_xg  [(size_t)BT * G3];
__device__ h16   g_hfhi[(size_t)(TT + 1) * BB * HM];   // fp16 h hi (GRU A + W3 GEMM)
__device__ h16   g_hflo[(size_t)(TT + 1) * BB * HM];   // fp16 h lo (carry + W3 GEMM)
__device__ float g_outs[(size_t)BT * PEN];
__device__ h16   g_W2f [(size_t)H2 * H1];
__device__ h16   g_Wihf[(size_t)G3 * H2];
__device__ h16   g_Whhf[(size_t)G3 * HM];              // fp16, gate-permuted rows
__device__ h16   g_W3f [(size_t)PEN * HM];
__device__ int      g_labels[BB];
__device__ unsigned g_bar_cnt = 0;
__device__ volatile unsigned g_bar_gen = 0;

// ---------------- asm helpers ----------------------------------------------
__device__ __forceinline__ uint32_t su32(const void* p) {
    uint32_t a;
    asm("{ .reg .u64 t; cvta.to.shared.u64 t, %1; cvt.u32.u64 %0, t; }" : "=r"(a) : "l"(p));
    return a;
}
__device__ __forceinline__ void mmaf16(float* d, const uint32_t* a, const uint32_t* b) {
    asm volatile(
        "mma.sync.aligned.m16n8k16.row.col.f32.f16.f16.f32 "
        "{%0,%1,%2,%3},{%4,%5,%6,%7},{%8,%9},{%0,%1,%2,%3};"
        : "+f"(d[0]), "+f"(d[1]), "+f"(d[2]), "+f"(d[3])
        : "r"(a[0]), "r"(a[1]), "r"(a[2]), "r"(a[3]), "r"(b[0]), "r"(b[1]));
}
__device__ __forceinline__ void ldsm4(uint32_t* r, uint32_t a) {
    asm volatile("ldmatrix.sync.aligned.m8n8.x4.shared.b16 {%0,%1,%2,%3},[%4];"
                 : "=r"(r[0]), "=r"(r[1]), "=r"(r[2]), "=r"(r[3]) : "r"(a));
}
__device__ __forceinline__ void cpa16(uint32_t d, const void* s) {
    asm volatile("cp.async.cg.shared.global [%0],[%1],16;" :: "r"(d), "l"(s));
}
__device__ __forceinline__ void cp_commit() { asm volatile("cp.async.commit_group;"); }
__device__ __forceinline__ void cp_wait1()  { asm volatile("cp.async.wait_group 1;"); }
__device__ __forceinline__ void cp_wait0()  { asm volatile("cp.async.wait_group 0;"); }

__device__ __forceinline__ void splitH(float v, unsigned short& h, unsigned short& l) {
    h16 hb = __float2half_rn(v);
    h = *reinterpret_cast<unsigned short*>(&hb);
    h16 lb = __float2half_rn(v - __half2float(hb));
    l = *reinterpret_cast<unsigned short*>(&lb);
}
__device__ __forceinline__ void cvt8H(const float* s, h16* w) {
    float4 a = *(const float4*)s, b = *(const float4*)(s + 4);
    float v[8] = {a.x, a.y, a.z, a.w, b.x, b.y, b.z, b.w};
    __align__(16) unsigned short o[8];
#pragma unroll
    for (int i = 0; i < 8; i++) {
        h16 hb = __float2half_rn(v[i]);
        o[i] = *reinterpret_cast<unsigned short*>(&hb);
    }
    *(uint4*)w = *(const uint4*)o;
}

__device__ __forceinline__ void gridbar()
{
    __syncthreads();
    if (threadIdx.x == 0) {
        __threadfence();
        unsigned g = g_bar_gen;
        if (atomicAdd(&g_bar_cnt, 1u) == NBLK - 1) {
            g_bar_cnt = 0;
            __threadfence();
            g_bar_gen = g + 1;
        } else {
            while (g_bar_gen == g) { __nanosleep(32); }
        }
        __threadfence();
    }
    __syncthreads();
}

// ---------------- convert all weights to fp16 -------------------------------
__global__ __launch_bounds__(256) void split_all(
    const float* __restrict__ W2, const float* __restrict__ Wih,
    const float* __restrict__ Whh, const float* __restrict__ W3r)
{
    const size_t n1 = (size_t)H2 * H1 / 8, n2 = (size_t)G3 * H2 / 8;
    const size_t n3 = (size_t)G3 * HM / 8, n4 = (size_t)PEN * HM / 8;
    size_t c = (size_t)blockIdx.x * 256 + threadIdx.x;
    if (c < n1) cvt8H(W2 + c * 8, g_W2f + c * 8);
    else if (c < n1 + n2) { size_t j = c - n1; cvt8H(Wih + j * 8, g_Wihf + j * 8); }
    else if (c < n1 + n2 + n3) {
        size_t j = c - n1 - n2;
        const size_t rpc = HM / 8;
        size_t row = j / rpc, wi = j % rpc;
        int gate = (int)(row >> 11), u = (int)(row & 2047);
        size_t drow = (size_t)(u >> 4) * 48 + (size_t)gate * 16 + (u & 15);
        cvt8H(Whh + j * 8, g_Whhf + (drow * rpc + wi) * 8);
    }
    else if (c < n1 + n2 + n3 + n4) { size_t j = c - n1 - n2 - n3; cvt8H(W3r + j * 8, g_W3f + j * 8); }
}

// ---------------- act1 FFMA (K=24) -> fp16 hi/lo ----------------------------
__global__ __launch_bounds__(256) void gemm_ffma_split(
    const float* __restrict__ A, const float* __restrict__ Bm,
    const float* __restrict__ bias)
{
    __shared__ float As[8][128], Bs[8][128];
    const int tid = threadIdx.x, tx = tid & 15, ty = tid >> 4;
    const int arow = tid >> 1, acol = (tid & 1) << 2;
    const float* Ap = A  + (size_t)(blockIdx.y * 128 + arow) * INF + acol;
    const float* Bp = Bm + (size_t)(blockIdx.x * 128 + arow) * INF + acol;
    float acc[8][8];
#pragma unroll
    for (int i = 0; i < 8; i++)
#pragma unroll
        for (int j = 0; j < 8; j++) acc[i][j] = 0.0f;
    for (int k0 = 0; k0 < INF; k0 += 8) {
        float4 a = *(const float4*)(Ap + k0);
        float4 b = *(const float4*)(Bp + k0);
        __syncthreads();
        As[acol][arow] = a.x; As[acol + 1][arow] = a.y; As[acol + 2][arow] = a.z; As[acol + 3][arow] = a.w;
        Bs[acol][arow] = b.x; Bs[acol + 1][arow] = b.y; Bs[acol + 2][arow] = b.z; Bs[acol + 3][arow] = b.w;
        __syncthreads();
#pragma unroll
        for (int k = 0; k < 8; k++) {
            float av[8], bv[8];
            *(float4*)av       = *(const float4*)&As[k][ty * 8];
            *(float4*)(av + 4) = *(const float4*)&As[k][ty * 8 + 4];
            *(float4*)bv       = *(const float4*)&Bs[k][tx * 8];
            *(float4*)(bv + 4) = *(const float4*)&Bs[k][tx * 8 + 4];
#pragma unroll
            for (int i = 0; i < 8; i++)
#pragma unroll
                for (int j = 0; j < 8; j++) acc[i][j] += av[i] * bv[j];
        }
    }
    const int crow = blockIdx.y * 128 + ty * 8, ccol = blockIdx.x * 128 + tx * 8;
#pragma unroll
    for (int i = 0; i < 8; i++) {
        __align__(16) unsigned short h8[8], l8[8];
#pragma unroll
        for (int j = 0; j < 8; j++)
            splitH(fmaxf(acc[i][j] + bias[ccol + j], 0.0f), h8[j], l8[j]);
        *(uint4*)(g_a1hi + (size_t)(crow + i) * H1 + ccol) = *(const uint4*)h8;
        *(uint4*)(g_a1lo + (size_t)(crow + i) * H1 + ccol) = *(const uint4*)l8;
    }
}

// ---------------- fp16 2-term NT GEMM (128x128, K-tile 64, 3-stage) ---------
// OUTM: 0 = f32, 2 = fp16 single
#define RB   144
#define ASZ  18432
#define STG2 55296
template<int OUTM, int RELU>
__global__ __launch_bounds__(256, 1) void gemm_tc2(
    const h16* __restrict__ Ahi, const h16* __restrict__ Alo,
    const h16* __restrict__ Bw, const float* __restrict__ bias,
    float* __restrict__ Cf, h16* __restrict__ Ch,
    int N, int K)
{
    extern __shared__ char smraw[];
    const uint32_t sb = su32(smraw);
    const int tid = threadIdx.x, warp = tid >> 5, lane = tid & 31;
    const int wm = warp >> 2, wn = warp & 3, g = lane >> 2, tg = lane & 3;
    const int mBase = blockIdx.y * 128, nBase = blockIdx.x * 128;
    const int NT = K / 64;
    const int arow = (lane & 7) + ((lane >> 3) & 1) * 8, ach = lane >> 4;
    const int brow = (lane & 7) + ((lane >> 4) & 1) * 8, bch = (lane >> 3) & 1;

    float acc[4][4][4];
#pragma unroll
    for (int i = 0; i < 4; i++)
#pragma unroll
        for (int j = 0; j < 4; j++)
#pragma unroll
            for (int q = 0; q < 4; q++) acc[i][j][q] = 0.0f;

    auto load_stage = [&](int st, int k0) {
        uint32_t d0 = sb + st * STG2;
#pragma unroll
        for (int q = 0; q < 4; q++) {
            int c = q * 256 + tid, row = c >> 3, ch = c & 7;
            size_t ka = (size_t)(mBase + row) * K + k0 + ch * 8;
            size_t kb = (size_t)(nBase + row) * K + k0 + ch * 8;
            uint32_t o = row * RB + ch * 16;
            cpa16(d0 + o,           Ahi + ka);
            cpa16(d0 + ASZ + o,     Alo + ka);
            cpa16(d0 + 2 * ASZ + o, Bw + kb);
        }
        cp_commit();
    };

    load_stage(0, 0);
    load_stage(1, 64);
    for (int kt = 0; kt < NT; kt++) {
        if (kt < NT - 1) cp_wait1(); else cp_wait0();
        __syncthreads();
        if (kt + 2 < NT) load_stage((kt + 2) % 3, (kt + 2) * 64);
        const uint32_t s0 = sb + (kt % 3) * STG2;
#pragma unroll
        for (int kk = 0; kk < 4; kk++) {
            uint32_t ah[4][4], al[4][4];
#pragma unroll
            for (int i = 0; i < 4; i++) {
                uint32_t ad = s0 + (wm * 64 + i * 16 + arow) * RB + (kk * 2 + ach) * 16;
                ldsm4(ah[i], ad);
                ldsm4(al[i], ad + ASZ);
            }
#pragma unroll
            for (int j = 0; j < 2; j++) {
                uint32_t bw[4];
                ldsm4(bw, s0 + 2 * ASZ + (wn * 32 + j * 16 + brow) * RB + (kk * 2 + bch) * 16);
#pragma unroll
                for (int i = 0; i < 4; i++) {
                    mmaf16(acc[i][2 * j],     ah[i], bw);
                    mmaf16(acc[i][2 * j],     al[i], bw);
                    mmaf16(acc[i][2 * j + 1], ah[i], bw + 2);
                    mmaf16(acc[i][2 * j + 1], al[i], bw + 2);
                }
            }
        }
    }

#pragma unroll
    for (int i = 0; i < 4; i++) {
        const int row = mBase + wm * 64 + i * 16 + g;
#pragma unroll
        for (int j = 0; j < 4; j++) {
            const int col = nBase + wn * 32 + j * 8 + 2 * tg;
            const float b0 = bias[col], b1 = bias[col + 1];
            float v00 = acc[i][j][0] + b0, v01 = acc[i][j][1] + b1;
            float v10 = acc[i][j][2] + b0, v11 = acc[i][j][3] + b1;
            if (RELU) { v00 = fmaxf(v00, 0.f); v01 = fmaxf(v01, 0.f);
                        v10 = fmaxf(v10, 0.f); v11 = fmaxf(v11, 0.f); }
            if (OUTM == 0) {
                *(float2*)(Cf + (size_t)row * N + col)       = make_float2(v00, v01);
                *(float2*)(Cf + (size_t)(row + 8) * N + col) = make_float2(v10, v11);
            } else {
                h16 p0 = __float2half_rn(v00), p1 = __float2half_rn(v01);
                h16 p2 = __float2half_rn(v10), p3 = __float2half_rn(v11);
                *(uint32_t*)(Ch + (size_t)row * N + col) =
                    (uint32_t)*reinterpret_cast<unsigned short*>(&p0) |
                    ((uint32_t)*reinterpret_cast<unsigned short*>(&p1) << 16);
                *(uint32_t*)(Ch + (size_t)(row + 8) * N + col) =
                    (uint32_t)*reinterpret_cast<unsigned short*>(&p2) |
                    ((uint32_t)*reinterpret_cast<unsigned short*>(&p3) << 16);
            }
        }
    }
}

// ---------------- fp16 1-term NT GEMM (xg): 2 CTAs/SM -----------------------
#define STG1 36864
__global__ __launch_bounds__(256, 2) void gemm_tc1(
    const h16* __restrict__ Aw, const h16* __restrict__ Bw,
    const float* __restrict__ bias, float* __restrict__ Cf,
    int N, int K)
{
    extern __shared__ char smraw[];
    const uint32_t sb = su32(smraw);
    const int tid = threadIdx.x, warp = tid >> 5, lane = tid & 31;
    const int wm = warp >> 2, wn = warp & 3, g = lane >> 2, tg = lane & 3;
    const int mBase = blockIdx.y * 128, nBase = blockIdx.x * 128;
    const int NT = K / 64;
    const int arow = (lane & 7) + ((lane >> 3) & 1) * 8, ach = lane >> 4;
    const int brow = (lane & 7) + ((lane >> 4) & 1) * 8, bch = (lane >> 3) & 1;

    float acc[4][4][4];
#pragma unroll
    for (int i = 0; i < 4; i++)
#pragma unroll
        for (int j = 0; j < 4; j++)
#pragma unroll
            for (int q = 0; q < 4; q++) acc[i][j][q] = 0.0f;

    auto load_stage = [&](int st, int k0) {
        uint32_t d0 = sb + st * STG1;
#pragma unroll
        for (int q = 0; q < 4; q++) {
            int c = q * 256 + tid, row = c >> 3, ch = c & 7;
            size_t ka = (size_t)(mBase + row) * K + k0 + ch * 8;
            size_t kb = (size_t)(nBase + row) * K + k0 + ch * 8;
            uint32_t o = row * RB + ch * 16;
            cpa16(d0 + o,       Aw + ka);
            cpa16(d0 + ASZ + o, Bw + kb);
        }
        cp_commit();
    };

    load_stage(0, 0);
    load_stage(1, 64);
    for (int kt = 0; kt < NT; kt++) {
        if (kt < NT - 1) cp_wait1(); else cp_wait0();
        __syncthreads();
        if (kt + 2 < NT) load_stage((kt + 2) % 3, (kt + 2) * 64);
        const uint32_t s0 = sb + (kt % 3) * STG1;
#pragma unroll
        for (int kk = 0; kk < 4; kk++) {
            uint32_t ah[4][4];
#pragma unroll
            for (int i = 0; i < 4; i++)
                ldsm4(ah[i], s0 + (wm * 64 + i * 16 + arow) * RB + (kk * 2 + ach) * 16);
#pragma unroll
            for (int j = 0; j < 2; j++) {
                uint32_t bw[4];
                ldsm4(bw, s0 + ASZ + (wn * 32 + j * 16 + brow) * RB + (kk * 2 + bch) * 16);
#pragma unroll
                for (int i = 0; i < 4; i++) {
                    mmaf16(acc[i][2 * j],     ah[i], bw);
                    mmaf16(acc[i][2 * j + 1], ah[i], bw + 2);
                }
            }
        }
    }

#pragma unroll
    for (int i = 0; i < 4; i++) {
        const int row = mBase + wm * 64 + i * 16 + g;
#pragma unroll
        for (int j = 0; j < 4; j++) {
            const int col = nBase + wn * 32 + j * 8 + 2 * tg;
            *(float2*)(Cf + (size_t)row * N + col) =
                make_float2(acc[i][j][0] + bias[col], acc[i][j][1] + bias[col + 1]);
            *(float2*)(Cf + (size_t)(row + 8) * N + col) =
                make_float2(acc[i][j][2] + bias[col], acc[i][j][3] + bias[col + 1]);
        }
    }
}

// ---------------- persistent GRU: W resident, 3-stage A, reg x-prefetch -----
#define WRB   4112
#define WBYT  (48 * WRB)            // 197376
#define GAR   144
#define GSTG  (64 * GAR)            // 9216
#define ACCP  52
__global__ __launch_bounds__(192, 1) void gru_persist(
    const float* __restrict__ b_hh, const int* __restrict__ labraw)
{
    extern __shared__ char smraw[];
    const uint32_t sb = su32(smraw);
    const uint32_t aBase = sb + WBYT;
    float* smacc = (float*)(smraw + WBYT);   // aliases A stages after K-loop
    const int tid = threadIdx.x, bid = blockIdx.x, warp = tid >> 5, lane = tid & 31;
    const int wm = warp / 3, wn = warp % 3, g = lane >> 2, tg = lane & 3;
    const int arow = (lane & 7) + ((lane >> 3) & 1) * 8, ach = lane >> 4;
    const int brow = (lane & 7) + ((lane >> 4) & 1) * 8, bch = (lane >> 3) & 1;
    const int gsz = NBLK * 192, gtid = bid * 192 + tid;
    const int u0 = bid * 16;

    for (int c = tid; c < 48 * 256; c += 192) {
        int row = c >> 8, ch = c & 255;
        *(uint4*)(smraw + row * WRB + ch * 16) =
            *(const uint4*)(g_Whhf + (size_t)(bid * 48 + row) * HM + ch * 8);
    }
    for (int i = gtid; i < BB * HM; i += gsz) {
        g_hfhi[i] = __float2half(0.0f);
        g_hflo[i] = __float2half(0.0f);
    }
    if (bid == 0 && warp == 0) {
        unsigned oddmask = __ballot_sync(0xffffffff, labraw[2 * lane + 1] != 0);
        if (oddmask == 0) { g_labels[lane] = labraw[2 * lane]; g_labels[lane + 32] = labraw[2 * (lane + 32)]; }
        else              { g_labels[lane] = labraw[lane];     g_labels[lane + 32] = labraw[lane + 32]; }
    }
    gridbar();

    const int NT = HM / 64;
    for (int t = 0; t < TT; t++) {
        const h16* Ah_t = g_hfhi + (size_t)t * BB * HM;
        const h16* Al_t = g_hflo + (size_t)t * BB * HM;

        float xr_r[6], xz_r[6], xn_r[6];
#pragma unroll
        for (int q = 0; q < 6; q++) {
            const int idx = tid + q * 192;
            if (idx < BB * 16) {
                const int b = idx >> 4, u = u0 + (idx & 15);
                const float* xrow = g_xg + (size_t)(b * TT + t) * G3;
                xr_r[q] = __ldg(xrow + u);
                xz_r[q] = __ldg(xrow + HM + u);
                xn_r[q] = __ldg(xrow + 2 * HM + u);
            } else { xr_r[q] = xz_r[q] = xn_r[q] = 0.f; }
        }

        float aH[2][2][4];
#pragma unroll
        for (int i = 0; i < 2; i++)
#pragma unroll
            for (int j = 0; j < 2; j++)
#pragma unroll
                for (int q = 0; q < 4; q++) aH[i][j][q] = 0.f;

        auto load_stage = [&](int st, int k0) {
            uint32_t d0 = aBase + st * GSTG;
            for (int c = tid; c < 512; c += 192) {
                int row = c >> 3, ch = c & 7;
                cpa16(d0 + row * GAR + ch * 16,
                      Ah_t + (size_t)row * HM + k0 + ch * 8);
            }
            cp_commit();
        };

        load_stage(0, 0);
        load_stage(1, 64);
        for (int kt = 0; kt < NT; kt++) {
            if (kt < NT - 1) cp_wait1(); else cp_wait0();
            __syncthreads();
            if (kt + 2 < NT) load_stage((kt + 2) % 3, (kt + 2) * 64);
            const uint32_t s0 = aBase + (kt % 3) * GSTG;
#pragma unroll
            for (int kk = 0; kk < 4; kk++) {
                uint32_t ah[2][4];
#pragma unroll
                for (int i = 0; i < 2; i++)
                    ldsm4(ah[i], s0 + (wm * 32 + i * 16 + arow) * GAR + (kk * 2 + ach) * 16);
                uint32_t bw[4];
                ldsm4(bw, sb + (wn * 16 + brow) * WRB + kt * 128 + kk * 32 + bch * 16);
#pragma unroll
                for (int i = 0; i < 2; i++) {
                    mmaf16(aH[i][0], ah[i], bw);
                    mmaf16(aH[i][1], ah[i], bw + 2);
                }
            }
        }
        __syncthreads();

#pragma unroll
        for (int i = 0; i < 2; i++) {
            const int row = wm * 32 + i * 16 + g;
#pragma unroll
            for (int j = 0; j < 2; j++) {
                const int col = wn * 16 + j * 8 + 2 * tg;
                smacc[row * ACCP + col]           = aH[i][j][0];
                smacc[row * ACCP + col + 1]       = aH[i][j][1];
                smacc[(row + 8) * ACCP + col]     = aH[i][j][2];
                smacc[(row + 8) * ACCP + col + 1] = aH[i][j][3];
            }
        }
        __syncthreads();

        {
            h16* hhn = g_hfhi + (size_t)(t + 1) * BB * HM;
            h16* hln = g_hflo + (size_t)(t + 1) * BB * HM;
#pragma unroll
            for (int q = 0; q < 6; q++) {
                const int idx = tid + q * 192;
                if (idx < BB * 16) {
                    const int b = idx >> 4, ul = idx & 15;
                    const int u = u0 + ul;
                    const float ar = smacc[b * ACCP + ul]      + b_hh[u];
                    const float az = smacc[b * ACCP + 16 + ul] + b_hh[HM + u];
                    const float an = smacc[b * ACCP + 32 + ul] + b_hh[2 * HM + u];
                    const float r  = 1.0f / (1.0f + expf(-(xr_r[q] + ar)));
                    const float z  = 1.0f / (1.0f + expf(-(xz_r[q] + az)));
                    const float nn = tanhf(xn_r[q] + r * an);
                    const float hp = __half2float(Ah_t[(size_t)b * HM + u])
                                   + __half2float(Al_t[(size_t)b * HM + u]);
                    const float h  = (1.0f - z) * nn + z * hp;
                    unsigned short s0w, s1w;
                    splitH(h, s0w, s1w);
                    hhn[(size_t)b * HM + u] = *reinterpret_cast<h16*>(&s0w);
                    hln[(size_t)b * HM + u] = *reinterpret_cast<h16*>(&s1w);
                }
            }
        }
        gridbar();
    }
}

// ---------------- heads + zero ----------------------------------------------
__global__ __launch_bounds__(128) void heads_kernel(
    const float* __restrict__ W4, const float* __restrict__ b4,
    const float* __restrict__ W5, const float* __restrict__ b5,
    const float* __restrict__ W6, const float* __restrict__ b6,
    float* __restrict__ out)
{
    const int r = blockIdx.x, t = r >> 6, b = r & 63;
    const int lab = g_labels[b];
    const float* s  = g_outs + (size_t)r * PEN;
    const float* w4 = W4 + (size_t)lab * PEN;
    const float* w5 = W5 + (size_t)lab * PEN;
    const float* w6 = W6 + (size_t)lab * PEN;
    float a4 = 0.f, a5 = 0.f, a6 = 0.f;
    for (int p = threadIdx.x; p < PEN; p += 128) {
        const float v = s[p];
        a4 += v * w4[p]; a5 += v * w5[p]; a6 += v * w6[p];
    }
    __shared__ float red[3][128];
    red[0][threadIdx.x] = a4; red[1][threadIdx.x] = a5; red[2][threadIdx.x] = a6;
    __syncthreads();
    for (int s2 = 64; s2 > 0; s2 >>= 1) {
        if (threadIdx.x < s2) {
            red[0][threadIdx.x] += red[0][threadIdx.x + s2];
            red[1][threadIdx.x] += red[1][threadIdx.x + s2];
            red[2][threadIdx.x] += red[2][threadIdx.x + s2];
        }
        __syncthreads();
    }
    if (threadIdx.x == 0) {
        const int o = b * TT + t;
        out[o]          = red[0][0] + b4[lab];
        out[BT + o]     = red[1][0] + b5[lab];
        out[2 * BT + o] = red[2][0] + b6[lab];
    }
}

__global__ void zero_kernel(float* p, int n)
{
    int i = blockIdx.x * blockDim.x + threadIdx.x;
    if (i < n) p[i] = 0.0f;
}

// ---------------- launch ----------------------------------------------------
extern "C" void kernel_launch(void* const* d_in, const int* in_sizes, int n_in,
                              void* d_out, int out_size)
{
    const float* x    = (const float*)d_in[0];
    const int*   labr = (const int*)d_in[1];
    const float* W1   = (const float*)d_in[2];
    const float* b1   = (const float*)d_in[3];
    const float* W2   = (const float*)d_in[4];
    const float* b2   = (const float*)d_in[5];
    const float* W_ih = (const float*)d_in[6];
    const float* W_hh = (const float*)d_in[7];
    const float* b_ih = (const float*)d_in[8];
    const float* b_hh = (const float*)d_in[9];
    const float* W3   = (const float*)d_in[10];
    const float* b3   = (const float*)d_in[11];
    const float* W4   = (const float*)d_in[12];
    const float* b4   = (const float*)d_in[13];
    const float* W5   = (const float*)d_in[14];
    const float* b5   = (const float*)d_in[15];
    const float* W6   = (const float*)d_in[16];
    const float* b6   = (const float*)d_in[17];
    float* out = (float*)d_out;

    h16 *a1hi, *a1lo, *a2f, *hfhi, *hflo, *w2f, *wihf, *w3f;
    float *xg, *outs;
    cudaGetSymbolAddress((void**)&a1hi, g_a1hi);
    cudaGetSymbolAddress((void**)&a1lo, g_a1lo);
    cudaGetSymbolAddress((void**)&a2f,  g_a2f);
    cudaGetSymbolAddress((void**)&hfhi, g_hfhi);
    cudaGetSymbolAddress((void**)&hflo, g_hflo);
    cudaGetSymbolAddress((void**)&w2f,  g_W2f);
    cudaGetSymbolAddress((void**)&wihf, g_Wihf);
    cudaGetSymbolAddress((void**)&w3f,  g_W3f);
    cudaGetSymbolAddress((void**)&xg,   g_xg);
    cudaGetSymbolAddress((void**)&outs, g_outs);

    const int GEMM2_SMEM = 3 * STG2;            // 165888
    const int GEMM1_SMEM = 3 * STG1;            // 110592 (2 CTAs/SM)
    const int GRU_SMEM   = WBYT + 3 * GSTG;     // 225024
    cudaFuncSetAttribute(gemm_tc2<0, 1>, cudaFuncAttributeMaxDynamicSharedMemorySize, GEMM2_SMEM);
    cudaFuncSetAttribute(gemm_tc2<2, 1>, cudaFuncAttributeMaxDynamicSharedMemorySize, GEMM2_SMEM);
    cudaFuncSetAttribute(gemm_tc1, cudaFuncAttributeMaxDynamicSharedMemorySize, GEMM1_SMEM);
    cudaFuncSetAttribute(gru_persist, cudaFuncAttributeMaxDynamicSharedMemorySize, GRU_SMEM);

    // 0) zero output tail
    const int tail = out_size - 3 * BT;
    zero_kernel<<<(((tail > 0 ? tail : 1) + 255) / 256), 256>>>(out + 3 * BT, tail > 0 ? tail : 0);
    // 1) act1 -> fp16 hi/lo
    {
        dim3 g(H1 / 128, BT / 128);
        gemm_ffma_split<<<g, 256>>>(x, W1, b1);
    }
    // 2) convert weights to fp16 (Whh gate-permuted)
    {
        size_t chunks = (size_t)H2 * H1 / 8 + (size_t)G3 * H2 / 8 + (size_t)G3 * HM / 8 + (size_t)PEN * HM / 8;
        split_all<<<(unsigned)((chunks + 255) / 256), 256>>>(W2, W_ih, W_hh, W3);
    }
    // 3) act2 -> fp16 single (2-term input)
    {
        dim3 g(H2 / 128, BT / 128);
        gemm_tc2<2, 1><<<g, 256, GEMM2_SMEM>>>(a1hi, a1lo, w2f, b2,
                                               nullptr, a2f, H2, H1);
    }
    // 4) xg -> f32 (1-term, 2 CTAs/SM)
    {
        dim3 g(G3 / 128, BT / 128);
        gemm_tc1<<<g, 256, GEMM1_SMEM>>>(a2f, wihf, b_ih, xg, G3, H2);
    }
    // 5) persistent GRU (profiled)
    gru_persist<<<NBLK, 192, GRU_SMEM>>>(b_hh, labr);
    // 6) out_s = relu(h @ W3^T + b3)  (2-term: h hi/lo)
    {
        dim3 g(PEN / 128, BT / 128);
        gemm_tc2<0, 1><<<g, 256, GEMM2_SMEM>>>(hfhi + (size_t)BB * HM, hflo + (size_t)BB * HM,
                                               w3f, b3, outs, nullptr, PEN, HM);
    }
    // 7) heads
    heads_kernel<<<BT, 128>>>(W4, b4, W5, b5, W6, b6, out);
}

// round 17
// speedup vs baseline: 5.3166x; 1.0680x over previous
#include <cuda_runtime.h>
#include <cuda_fp16.h>
#include <math.h>
#include <stdint.h>

#define BB 64
#define TT 366
#define INF 24
#define H1 1024
#define H2 2048
#define HM 2048
#define PEN 1024
#define BT 23424
#define G3 6144
#define NBLK 128
typedef __half h16;

// ---------------- scratch ---------------------------------------------------
__device__ h16   g_a1hi[(size_t)BT * H1];
__device__ h16   g_a1lo[(size_t)BT * H1];
__device__ h16   g_a2f [(size_t)BT * H2];              // fp16 single (xg input)
__device__ float g_xg  [(size_t)BT * G3];
__device__ h16   g_hf  [(size_t)(TT + 1) * BB * HM];   // fp16 h (GRU A + W3 GEMM)
__device__ float g_outs[(size_t)BT * PEN];
__device__ h16   g_W2f [(size_t)H2 * H1];
__device__ h16   g_Wihf[(size_t)G3 * H2];
__device__ h16   g_Whhf[(size_t)G3 * HM];              // fp16, gate-permuted rows
__device__ h16   g_W3f [(size_t)PEN * HM];
__device__ int      g_labels[BB];
__device__ unsigned g_bar_cnt = 0;
__device__ volatile unsigned g_bar_gen = 0;

// ---------------- asm helpers ----------------------------------------------
__device__ __forceinline__ uint32_t su32(const void* p) {
    uint32_t a;
    asm("{ .reg .u64 t; cvta.to.shared.u64 t, %1; cvt.u32.u64 %0, t; }" : "=r"(a) : "l"(p));
    return a;
}
__device__ __forceinline__ void mmaf16(float* d, const uint32_t* a, const uint32_t* b) {
    asm volatile(
        "mma.sync.aligned.m16n8k16.row.col.f32.f16.f16.f32 "
        "{%0,%1,%2,%3},{%4,%5,%6,%7},{%8,%9},{%0,%1,%2,%3};"
        : "+f"(d[0]), "+f"(d[1]), "+f"(d[2]), "+f"(d[3])
        : "r"(a[0]), "r"(a[1]), "r"(a[2]), "r"(a[3]), "r"(b[0]), "r"(b[1]));
}
__device__ __forceinline__ void ldsm4(uint32_t* r, uint32_t a) {
    asm volatile("ldmatrix.sync.aligned.m8n8.x4.shared.b16 {%0,%1,%2,%3},[%4];"
                 : "=r"(r[0]), "=r"(r[1]), "=r"(r[2]), "=r"(r[3]) : "r"(a));
}
__device__ __forceinline__ void cpa16(uint32_t d, const void* s) {
    asm volatile("cp.async.cg.shared.global [%0],[%1],16;" :: "r"(d), "l"(s));
}
__device__ __forceinline__ void cp_commit() { asm volatile("cp.async.commit_group;"); }
__device__ __forceinline__ void cp_wait2()  { asm volatile("cp.async.wait_group 2;"); }
__device__ __forceinline__ void cp_wait1()  { asm volatile("cp.async.wait_group 1;"); }
__device__ __forceinline__ void cp_wait0()  { asm volatile("cp.async.wait_group 0;"); }

__device__ __forceinline__ void splitH(float v, unsigned short& h, unsigned short& l) {
    h16 hb = __float2half_rn(v);
    h = *reinterpret_cast<unsigned short*>(&hb);
    h16 lb = __float2half_rn(v - __half2float(hb));
    l = *reinterpret_cast<unsigned short*>(&lb);
}
__device__ __forceinline__ void cvt8H(const float* s, h16* w) {
    float4 a = *(const float4*)s, b = *(const float4*)(s + 4);
    float v[8] = {a.x, a.y, a.z, a.w, b.x, b.y, b.z, b.w};
    __align__(16) unsigned short o[8];
#pragma unroll
    for (int i = 0; i < 8; i++) {
        h16 hb = __float2half_rn(v[i]);
        o[i] = *reinterpret_cast<unsigned short*>(&hb);
    }
    *(uint4*)w = *(const uint4*)o;
}

__device__ __forceinline__ void gridbar()
{
    __syncthreads();
    if (threadIdx.x == 0) {
        __threadfence();
        unsigned g = g_bar_gen;
        if (atomicAdd(&g_bar_cnt, 1u) == NBLK - 1) {
            g_bar_cnt = 0;
            __threadfence();
            g_bar_gen = g + 1;
        } else {
            while (g_bar_gen == g) { __nanosleep(32); }
        }
        __threadfence();
    }
    __syncthreads();
}

// ---------------- convert all weights to fp16 -------------------------------
__global__ __launch_bounds__(256) void split_all(
    const float* __restrict__ W2, const float* __restrict__ Wih,
    const float* __restrict__ Whh, const float* __restrict__ W3r)
{
    const size_t n1 = (size_t)H2 * H1 / 8, n2 = (size_t)G3 * H2 / 8;
    const size_t n3 = (size_t)G3 * HM / 8, n4 = (size_t)PEN * HM / 8;
    size_t c = (size_t)blockIdx.x * 256 + threadIdx.x;
    if (c < n1) cvt8H(W2 + c * 8, g_W2f + c * 8);
    else if (c < n1 + n2) { size_t j = c - n1; cvt8H(Wih + j * 8, g_Wihf + j * 8); }
    else if (c < n1 + n2 + n3) {
        size_t j = c - n1 - n2;
        const size_t rpc = HM / 8;
        size_t row = j / rpc, wi = j % rpc;
        int gate = (int)(row >> 11), u = (int)(row & 2047);
        size_t drow = (size_t)(u >> 4) * 48 + (size_t)gate * 16 + (u & 15);
        cvt8H(Whh + j * 8, g_Whhf + (drow * rpc + wi) * 8);
    }
    else if (c < n1 + n2 + n3 + n4) { size_t j = c - n1 - n2 - n3; cvt8H(W3r + j * 8, g_W3f + j * 8); }
}

// ---------------- act1 FFMA (K=24) -> fp16 hi/lo ----------------------------
__global__ __launch_bounds__(256) void gemm_ffma_split(
    const float* __restrict__ A, const float* __restrict__ Bm,
    const float* __restrict__ bias)
{
    __shared__ float As[8][128], Bs[8][128];
    const int tid = threadIdx.x, tx = tid & 15, ty = tid >> 4;
    const int arow = tid >> 1, acol = (tid & 1) << 2;
    const float* Ap = A  + (size_t)(blockIdx.y * 128 + arow) * INF + acol;
    const float* Bp = Bm + (size_t)(blockIdx.x * 128 + arow) * INF + acol;
    float acc[8][8];
#pragma unroll
    for (int i = 0; i < 8; i++)
#pragma unroll
        for (int j = 0; j < 8; j++) acc[i][j] = 0.0f;
    for (int k0 = 0; k0 < INF; k0 += 8) {
        float4 a = *(const float4*)(Ap + k0);
        float4 b = *(const float4*)(Bp + k0);
        __syncthreads();
        As[acol][arow] = a.x; As[acol + 1][arow] = a.y; As[acol + 2][arow] = a.z; As[acol + 3][arow] = a.w;
        Bs[acol][arow] = b.x; Bs[acol + 1][arow] = b.y; Bs[acol + 2][arow] = b.z; Bs[acol + 3][arow] = b.w;
        __syncthreads();
#pragma unroll
        for (int k = 0; k < 8; k++) {
            float av[8], bv[8];
            *(float4*)av       = *(const float4*)&As[k][ty * 8];
            *(float4*)(av + 4) = *(const float4*)&As[k][ty * 8 + 4];
            *(float4*)bv       = *(const float4*)&Bs[k][tx * 8];
            *(float4*)(bv + 4) = *(const float4*)&Bs[k][tx * 8 + 4];
#pragma unroll
            for (int i = 0; i < 8; i++)
#pragma unroll
                for (int j = 0; j < 8; j++) acc[i][j] += av[i] * bv[j];
        }
    }
    const int crow = blockIdx.y * 128 + ty * 8, ccol = blockIdx.x * 128 + tx * 8;
#pragma unroll
    for (int i = 0; i < 8; i++) {
        __align__(16) unsigned short h8[8], l8[8];
#pragma unroll
        for (int j = 0; j < 8; j++)
            splitH(fmaxf(acc[i][j] + bias[ccol + j], 0.0f), h8[j], l8[j]);
        *(uint4*)(g_a1hi + (size_t)(crow + i) * H1 + ccol) = *(const uint4*)h8;
        *(uint4*)(g_a1lo + (size_t)(crow + i) * H1 + ccol) = *(const uint4*)l8;
    }
}

// ---------------- fp16 2-term NT GEMM (act2): 4-stage -----------------------
// OUTM: 0 = f32, 2 = fp16 single
#define RB   144
#define ASZ  18432
#define STG2 55296
template<int OUTM, int RELU>
__global__ __launch_bounds__(256, 1) void gemm_tc2(
    const h16* __restrict__ Ahi, const h16* __restrict__ Alo,
    const h16* __restrict__ Bw, const float* __restrict__ bias,
    float* __restrict__ Cf, h16* __restrict__ Ch,
    int N, int K)
{
    extern __shared__ char smraw[];
    const uint32_t sb = su32(smraw);
    const int tid = threadIdx.x, warp = tid >> 5, lane = tid & 31;
    const int wm = warp >> 2, wn = warp & 3, g = lane >> 2, tg = lane & 3;
    const int mBase = blockIdx.y * 128, nBase = blockIdx.x * 128;
    const int NT = K / 64;
    const int arow = (lane & 7) + ((lane >> 3) & 1) * 8, ach = lane >> 4;
    const int brow = (lane & 7) + ((lane >> 4) & 1) * 8, bch = (lane >> 3) & 1;

    float acc[4][4][4];
#pragma unroll
    for (int i = 0; i < 4; i++)
#pragma unroll
        for (int j = 0; j < 4; j++)
#pragma unroll
            for (int q = 0; q < 4; q++) acc[i][j][q] = 0.0f;

    auto load_stage = [&](int st, int k0) {
        uint32_t d0 = sb + st * STG2;
#pragma unroll
        for (int q = 0; q < 4; q++) {
            int c = q * 256 + tid, row = c >> 3, ch = c & 7;
            size_t ka = (size_t)(mBase + row) * K + k0 + ch * 8;
            size_t kb = (size_t)(nBase + row) * K + k0 + ch * 8;
            uint32_t o = row * RB + ch * 16;
            cpa16(d0 + o,           Ahi + ka);
            cpa16(d0 + ASZ + o,     Alo + ka);
            cpa16(d0 + 2 * ASZ + o, Bw + kb);
        }
        cp_commit();
    };

    load_stage(0, 0);
    load_stage(1, 64);
    load_stage(2, 128);
    for (int kt = 0; kt < NT; kt++) {
        if (kt < NT - 2) cp_wait2();
        else if (kt == NT - 2) cp_wait1();
        else cp_wait0();
        __syncthreads();
        if (kt + 3 < NT) load_stage((kt + 3) & 3, (kt + 3) * 64);
        const uint32_t s0 = sb + (kt & 3) * STG2;
#pragma unroll
        for (int kk = 0; kk < 4; kk++) {
            uint32_t ah[4][4], al[4][4];
#pragma unroll
            for (int i = 0; i < 4; i++) {
                uint32_t ad = s0 + (wm * 64 + i * 16 + arow) * RB + (kk * 2 + ach) * 16;
                ldsm4(ah[i], ad);
                ldsm4(al[i], ad + ASZ);
            }
#pragma unroll
            for (int j = 0; j < 2; j++) {
                uint32_t bw[4];
                ldsm4(bw, s0 + 2 * ASZ + (wn * 32 + j * 16 + brow) * RB + (kk * 2 + bch) * 16);
#pragma unroll
                for (int i = 0; i < 4; i++) {
                    mmaf16(acc[i][2 * j],     ah[i], bw);
                    mmaf16(acc[i][2 * j],     al[i], bw);
                    mmaf16(acc[i][2 * j + 1], ah[i], bw + 2);
                    mmaf16(acc[i][2 * j + 1], al[i], bw + 2);
                }
            }
        }
    }

#pragma unroll
    for (int i = 0; i < 4; i++) {
        const int row = mBase + wm * 64 + i * 16 + g;
#pragma unroll
        for (int j = 0; j < 4; j++) {
            const int col = nBase + wn * 32 + j * 8 + 2 * tg;
            const float b0 = bias[col], b1 = bias[col + 1];
            float v00 = acc[i][j][0] + b0, v01 = acc[i][j][1] + b1;
            float v10 = acc[i][j][2] + b0, v11 = acc[i][j][3] + b1;
            if (RELU) { v00 = fmaxf(v00, 0.f); v01 = fmaxf(v01, 0.f);
                        v10 = fmaxf(v10, 0.f); v11 = fmaxf(v11, 0.f); }
            if (OUTM == 0) {
                *(float2*)(Cf + (size_t)row * N + col)       = make_float2(v00, v01);
                *(float2*)(Cf + (size_t)(row + 8) * N + col) = make_float2(v10, v11);
            } else {
                h16 p0 = __float2half_rn(v00), p1 = __float2half_rn(v01);
                h16 p2 = __float2half_rn(v10), p3 = __float2half_rn(v11);
                *(uint32_t*)(Ch + (size_t)row * N + col) =
                    (uint32_t)*reinterpret_cast<unsigned short*>(&p0) |
                    ((uint32_t)*reinterpret_cast<unsigned short*>(&p1) << 16);
                *(uint32_t*)(Ch + (size_t)(row + 8) * N + col) =
                    (uint32_t)*reinterpret_cast<unsigned short*>(&p2) |
                    ((uint32_t)*reinterpret_cast<unsigned short*>(&p3) << 16);
            }
        }
    }
}

// ---------------- fp16 1-term NT GEMM (xg, W3): 2 CTAs/SM -------------------
#define STG1 36864
template<int RELU>
__global__ __launch_bounds__(256, 2) void gemm_tc1(
    const h16* __restrict__ Aw, const h16* __restrict__ Bw,
    const float* __restrict__ bias, float* __restrict__ Cf,
    int N, int K)
{
    extern __shared__ char smraw[];
    const uint32_t sb = su32(smraw);
    const int tid = threadIdx.x, warp = tid >> 5, lane = tid & 31;
    const int wm = warp >> 2, wn = warp & 3, g = lane >> 2, tg = lane & 3;
    const int mBase = blockIdx.y * 128, nBase = blockIdx.x * 128;
    const int NT = K / 64;
    const int arow = (lane & 7) + ((lane >> 3) & 1) * 8, ach = lane >> 4;
    const int brow = (lane & 7) + ((lane >> 4) & 1) * 8, bch = (lane >> 3) & 1;

    float acc[4][4][4];
#pragma unroll
    for (int i = 0; i < 4; i++)
#pragma unroll
        for (int j = 0; j < 4; j++)
#pragma unroll
            for (int q = 0; q < 4; q++) acc[i][j][q] = 0.0f;

    auto load_stage = [&](int st, int k0) {
        uint32_t d0 = sb + st * STG1;
#pragma unroll
        for (int q = 0; q < 4; q++) {
            int c = q * 256 + tid, row = c >> 3, ch = c & 7;
            size_t ka = (size_t)(mBase + row) * K + k0 + ch * 8;
            size_t kb = (size_t)(nBase + row) * K + k0 + ch * 8;
            uint32_t o = row * RB + ch * 16;
            cpa16(d0 + o,       Aw + ka);
            cpa16(d0 + ASZ + o, Bw + kb);
        }
        cp_commit();
    };

    load_stage(0, 0);
    load_stage(1, 64);
    for (int kt = 0; kt < NT; kt++) {
        if (kt < NT - 1) cp_wait1(); else cp_wait0();
        __syncthreads();
        if (kt + 2 < NT) load_stage((kt + 2) % 3, (kt + 2) * 64);
        const uint32_t s0 = sb + (kt % 3) * STG1;
#pragma unroll
        for (int kk = 0; kk < 4; kk++) {
            uint32_t ah[4][4];
#pragma unroll
            for (int i = 0; i < 4; i++)
                ldsm4(ah[i], s0 + (wm * 64 + i * 16 + arow) * RB + (kk * 2 + ach) * 16);
#pragma unroll
            for (int j = 0; j < 2; j++) {
                uint32_t bw[4];
                ldsm4(bw, s0 + ASZ + (wn * 32 + j * 16 + brow) * RB + (kk * 2 + bch) * 16);
#pragma unroll
                for (int i = 0; i < 4; i++) {
                    mmaf16(acc[i][2 * j],     ah[i], bw);
                    mmaf16(acc[i][2 * j + 1], ah[i], bw + 2);
                }
            }
        }
    }

#pragma unroll
    for (int i = 0; i < 4; i++) {
        const int row = mBase + wm * 64 + i * 16 + g;
#pragma unroll
        for (int j = 0; j < 4; j++) {
            const int col = nBase + wn * 32 + j * 8 + 2 * tg;
            float v00 = acc[i][j][0] + bias[col], v01 = acc[i][j][1] + bias[col + 1];
            float v10 = acc[i][j][2] + bias[col], v11 = acc[i][j][3] + bias[col + 1];
            if (RELU) { v00 = fmaxf(v00, 0.f); v01 = fmaxf(v01, 0.f);
                        v10 = fmaxf(v10, 0.f); v11 = fmaxf(v11, 0.f); }
            *(float2*)(Cf + (size_t)row * N + col)       = make_float2(v00, v01);
            *(float2*)(Cf + (size_t)(row + 8) * N + col) = make_float2(v10, v11);
        }
    }
}

// ---------------- persistent GRU: W resident, reg carry ----------------------
#define WRB   4112
#define WBYT  (48 * WRB)            // 197376
#define GAR   144
#define GSTG  (64 * GAR)            // 9216
#define ACCP  52
__global__ __launch_bounds__(192, 1) void gru_persist(
    const float* __restrict__ b_hh, const int* __restrict__ labraw)
{
    extern __shared__ char smraw[];
    const uint32_t sb = su32(smraw);
    const uint32_t aBase = sb + WBYT;
    float* smacc = (float*)(smraw + WBYT);   // aliases A stages after K-loop
    const int tid = threadIdx.x, bid = blockIdx.x, warp = tid >> 5, lane = tid & 31;
    const int wm = warp / 3, wn = warp % 3, g = lane >> 2, tg = lane & 3;
    const int arow = (lane & 7) + ((lane >> 3) & 1) * 8, ach = lane >> 4;
    const int brow = (lane & 7) + ((lane >> 4) & 1) * 8, bch = (lane >> 3) & 1;
    const int gsz = NBLK * 192, gtid = bid * 192 + tid;
    const int u0 = bid * 16;

    for (int c = tid; c < 48 * 256; c += 192) {
        int row = c >> 8, ch = c & 255;
        *(uint4*)(smraw + row * WRB + ch * 16) =
            *(const uint4*)(g_Whhf + (size_t)(bid * 48 + row) * HM + ch * 8);
    }
    for (int i = gtid; i < BB * HM; i += gsz)
        g_hf[i] = __float2half(0.0f);
    if (bid == 0 && warp == 0) {
        unsigned oddmask = __ballot_sync(0xffffffff, labraw[2 * lane + 1] != 0);
        if (oddmask == 0) { g_labels[lane] = labraw[2 * lane]; g_labels[lane + 32] = labraw[2 * (lane + 32)]; }
        else              { g_labels[lane] = labraw[lane];     g_labels[lane + 32] = labraw[lane + 32]; }
    }
    gridbar();

    // fp32 carry in registers (static thread->cell map)
    float hp_r[6] = {0.f, 0.f, 0.f, 0.f, 0.f, 0.f};

    const int NT = HM / 64;
    for (int t = 0; t < TT; t++) {
        const h16* Ah_t = g_hf + (size_t)t * BB * HM;

        float xr_r[6], xz_r[6], xn_r[6];
#pragma unroll
        for (int q = 0; q < 6; q++) {
            const int idx = tid + q * 192;
            if (idx < BB * 16) {
                const int b = idx >> 4, u = u0 + (idx & 15);
                const float* xrow = g_xg + (size_t)(b * TT + t) * G3;
                xr_r[q] = __ldg(xrow + u);
                xz_r[q] = __ldg(xrow + HM + u);
                xn_r[q] = __ldg(xrow + 2 * HM + u);
            } else { xr_r[q] = xz_r[q] = xn_r[q] = 0.f; }
        }

        float aH[2][2][4];
#pragma unroll
        for (int i = 0; i < 2; i++)
#pragma unroll
            for (int j = 0; j < 2; j++)
#pragma unroll
                for (int q = 0; q < 4; q++) aH[i][j][q] = 0.f;

        auto load_stage = [&](int st, int k0) {
            uint32_t d0 = aBase + st * GSTG;
            for (int c = tid; c < 512; c += 192) {
                int row = c >> 3, ch = c & 7;
                cpa16(d0 + row * GAR + ch * 16,
                      Ah_t + (size_t)row * HM + k0 + ch * 8);
            }
            cp_commit();
        };

        load_stage(0, 0);
        load_stage(1, 64);
        for (int kt = 0; kt < NT; kt++) {
            if (kt < NT - 1) cp_wait1(); else cp_wait0();
            __syncthreads();
            if (kt + 2 < NT) load_stage((kt + 2) % 3, (kt + 2) * 64);
            const uint32_t s0 = aBase + (kt % 3) * GSTG;
#pragma unroll
            for (int kk = 0; kk < 4; kk++) {
                uint32_t ah[2][4];
#pragma unroll
                for (int i = 0; i < 2; i++)
                    ldsm4(ah[i], s0 + (wm * 32 + i * 16 + arow) * GAR + (kk * 2 + ach) * 16);
                uint32_t bw[4];
                ldsm4(bw, sb + (wn * 16 + brow) * WRB + kt * 128 + kk * 32 + bch * 16);
#pragma unroll
                for (int i = 0; i < 2; i++) {
                    mmaf16(aH[i][0], ah[i], bw);
                    mmaf16(aH[i][1], ah[i], bw + 2);
                }
            }
        }
        __syncthreads();

#pragma unroll
        for (int i = 0; i < 2; i++) {
            const int row = wm * 32 + i * 16 + g;
#pragma unroll
            for (int j = 0; j < 2; j++) {
                const int col = wn * 16 + j * 8 + 2 * tg;
                smacc[row * ACCP + col]           = aH[i][j][0];
                smacc[row * ACCP + col + 1]       = aH[i][j][1];
                smacc[(row + 8) * ACCP + col]     = aH[i][j][2];
                smacc[(row + 8) * ACCP + col + 1] = aH[i][j][3];
            }
        }
        __syncthreads();

        {
            h16* hhn = g_hf + (size_t)(t + 1) * BB * HM;
#pragma unroll
            for (int q = 0; q < 6; q++) {
                const int idx = tid + q * 192;
                if (idx < BB * 16) {
                    const int b = idx >> 4, ul = idx & 15;
                    const int u = u0 + ul;
                    const float ar = smacc[b * ACCP + ul]      + b_hh[u];
                    const float az = smacc[b * ACCP + 16 + ul] + b_hh[HM + u];
                    const float an = smacc[b * ACCP + 32 + ul] + b_hh[2 * HM + u];
                    const float r  = 1.0f / (1.0f + expf(-(xr_r[q] + ar)));
                    const float z  = 1.0f / (1.0f + expf(-(xz_r[q] + az)));
                    const float nn = tanhf(xn_r[q] + r * an);
                    const float h  = (1.0f - z) * nn + z * hp_r[q];
                    hp_r[q] = h;
                    hhn[(size_t)b * HM + u] = __float2half_rn(h);
                }
            }
        }
        gridbar();
    }
}

// ---------------- heads + zero ----------------------------------------------
__global__ __launch_bounds__(128) void heads_kernel(
    const float* __restrict__ W4, const float* __restrict__ b4,
    const float* __restrict__ W5, const float* __restrict__ b5,
    const float* __restrict__ W6, const float* __restrict__ b6,
    float* __restrict__ out)
{
    const int r = blockIdx.x, t = r >> 6, b = r & 63;
    const int lab = g_labels[b];
    const float* s  = g_outs + (size_t)r * PEN;
    const float* w4 = W4 + (size_t)lab * PEN;
    const float* w5 = W5 + (size_t)lab * PEN;
    const float* w6 = W6 + (size_t)lab * PEN;
    float a4 = 0.f, a5 = 0.f, a6 = 0.f;
    for (int p = threadIdx.x; p < PEN; p += 128) {
        const float v = s[p];
        a4 += v * w4[p]; a5 += v * w5[p]; a6 += v * w6[p];
    }
    __shared__ float red[3][128];
    red[0][threadIdx.x] = a4; red[1][threadIdx.x] = a5; red[2][threadIdx.x] = a6;
    __syncthreads();
    for (int s2 = 64; s2 > 0; s2 >>= 1) {
        if (threadIdx.x < s2) {
            red[0][threadIdx.x] += red[0][threadIdx.x + s2];
            red[1][threadIdx.x] += red[1][threadIdx.x + s2];
            red[2][threadIdx.x] += red[2][threadIdx.x + s2];
        }
        __syncthreads();
    }
    if (threadIdx.x == 0) {
        const int o = b * TT + t;
        out[o]          = red[0][0] + b4[lab];
        out[BT + o]     = red[1][0] + b5[lab];
        out[2 * BT + o] = red[2][0] + b6[lab];
    }
}

__global__ void zero_kernel(float* p, int n)
{
    int i = blockIdx.x * blockDim.x + threadIdx.x;
    if (i < n) p[i] = 0.0f;
}

// ---------------- launch ----------------------------------------------------
extern "C" void kernel_launch(void* const* d_in, const int* in_sizes, int n_in,
                              void* d_out, int out_size)
{
    const float* x    = (const float*)d_in[0];
    const int*   labr = (const int*)d_in[1];
    const float* W1   = (const float*)d_in[2];
    const float* b1   = (const float*)d_in[3];
    const float* W2   = (const float*)d_in[4];
    const float* b2   = (const float*)d_in[5];
    const float* W_ih = (const float*)d_in[6];
    const float* W_hh = (const float*)d_in[7];
    const float* b_ih = (const float*)d_in[8];
    const float* b_hh = (const float*)d_in[9];
    const float* W3   = (const float*)d_in[10];
    const float* b3   = (const float*)d_in[11];
    const float* W4   = (const float*)d_in[12];
    const float* b4   = (const float*)d_in[13];
    const float* W5   = (const float*)d_in[14];
    const float* b5   = (const float*)d_in[15];
    const float* W6   = (const float*)d_in[16];
    const float* b6   = (const float*)d_in[17];
    float* out = (float*)d_out;

    h16 *a1hi, *a1lo, *a2f, *hf, *w2f, *wihf, *w3f;
    float *xg, *outs;
    cudaGetSymbolAddress((void**)&a1hi, g_a1hi);
    cudaGetSymbolAddress((void**)&a1lo, g_a1lo);
    cudaGetSymbolAddress((void**)&a2f,  g_a2f);
    cudaGetSymbolAddress((void**)&hf,   g_hf);
    cudaGetSymbolAddress((void**)&w2f,  g_W2f);
    cudaGetSymbolAddress((void**)&wihf, g_Wihf);
    cudaGetSymbolAddress((void**)&w3f,  g_W3f);
    cudaGetSymbolAddress((void**)&xg,   g_xg);
    cudaGetSymbolAddress((void**)&outs, g_outs);

    const int GEMM2_SMEM = 4 * STG2;            // 221184
    const int GEMM1_SMEM = 3 * STG1;            // 110592 (2 CTAs/SM)
    const int GRU_SMEM   = WBYT + 3 * GSTG;     // 225024
    cudaFuncSetAttribute(gemm_tc2<2, 1>, cudaFuncAttributeMaxDynamicSharedMemorySize, GEMM2_SMEM);
    cudaFuncSetAttribute(gemm_tc1<0>, cudaFuncAttributeMaxDynamicSharedMemorySize, GEMM1_SMEM);
    cudaFuncSetAttribute(gemm_tc1<1>, cudaFuncAttributeMaxDynamicSharedMemorySize, GEMM1_SMEM);
    cudaFuncSetAttribute(gru_persist, cudaFuncAttributeMaxDynamicSharedMemorySize, GRU_SMEM);

    // 0) zero output tail
    const int tail = out_size - 3 * BT;
    zero_kernel<<<(((tail > 0 ? tail : 1) + 255) / 256), 256>>>(out + 3 * BT, tail > 0 ? tail : 0);
    // 1) act1 -> fp16 hi/lo
    {
        dim3 g(H1 / 128, BT / 128);
        gemm_ffma_split<<<g, 256>>>(x, W1, b1);
    }
    // 2) convert weights to fp16 (Whh gate-permuted)
    {
        size_t chunks = (size_t)H2 * H1 / 8 + (size_t)G3 * H2 / 8 + (size_t)G3 * HM / 8 + (size_t)PEN * HM / 8;
        split_all<<<(unsigned)((chunks + 255) / 256), 256>>>(W2, W_ih, W_hh, W3);
    }
    // 3) act2 -> fp16 single (2-term input, 4-stage)
    {
        dim3 g(H2 / 128, BT / 128);
        gemm_tc2<2, 1><<<g, 256, GEMM2_SMEM>>>(a1hi, a1lo, w2f, b2,
                                               nullptr, a2f, H2, H1);
    }
    // 4) xg -> f32 (1-term, 2 CTAs/SM)
    {
        dim3 g(G3 / 128, BT / 128);
        gemm_tc1<0><<<g, 256, GEMM1_SMEM>>>(a2f, wihf, b_ih, xg, G3, H2);
    }
    // 5) persistent GRU (profiled)
    gru_persist<<<NBLK, 192, GRU_SMEM>>>(b_hh, labr);
    // 6) out_s = relu(h @ W3^T + b3)  (1-term)
    {
        dim3 g(PEN / 128, BT / 128);
        gemm_tc1<1><<<g, 256, GEMM1_SMEM>>>(hf + (size_t)BB * HM, w3f, b3, outs, PEN, HM);
    }
    // 7) heads
    heads_kernel<<<BT, 128>>>(W4, b4, W5, b5, W6, b6, out);
}